// round 1
// baseline (speedup 1.0000x reference)
#include <cuda_runtime.h>

#define N_NODES 100000

// Scratch (allocation-free rule: __device__ globals)
__device__ float g_agg[N_NODES * 128];
__device__ float g_cnt[N_NODES];
__device__ float g_h0[N_NODES * 128];
__device__ float g_h1[N_NODES * 128];

// ---------------------------------------------------------------------------
__global__ void zero_kernel(float* __restrict__ p, int n) {
    int i = blockIdx.x * blockDim.x + threadIdx.x;
    if (i < n) p[i] = 0.0f;
}

__global__ void count_kernel(const int* __restrict__ dst, int E, float* __restrict__ cnt) {
    int e = blockIdx.x * blockDim.x + threadIdx.x;
    if (e < E) atomicAdd(&cnt[dst[e]], 1.0f);
}

template <int F>
__global__ void scatter_kernel(const float* __restrict__ feat,
                               const int* __restrict__ src,
                               const int* __restrict__ dst,
                               int E, float* __restrict__ agg) {
    int id = blockIdx.x * blockDim.x + threadIdx.x;
    if (id >= E * F) return;
    int e = id / F;
    int f = id - e * F;
    int s = __ldg(&src[e]);
    int d = __ldg(&dst[e]);
    atomicAdd(&agg[d * F + f], __ldg(&feat[s * F + f]));
}

// ---------------------------------------------------------------------------
// out[n,:] = (RELU?) ( bl + (agg[n,:]/max(cnt,1)) @ Wl + xin[n,:] @ Wr )
// K = per-matrix input dim (64 for layer0, 128 for layer1); output dim = 128.
// Block: 512 threads = 4 groups of 128; each group computes 4 nodes at a time
// with 8 register accumulators per thread (agg-part and x-part separated so
// the 1/cnt scale factors out of the k-loop).
template <int K, bool RELU>
__launch_bounds__(512, 1)
__global__ void sage_gemm_kernel(const float* __restrict__ agg,
                                 const float* __restrict__ cnt,
                                 const float* __restrict__ xin,
                                 const float* __restrict__ Wl,
                                 const float* __restrict__ bl,
                                 const float* __restrict__ Wr,
                                 float* __restrict__ outp) {
    extern __shared__ float sm[];
    float* Wls   = sm;                    // K*128
    float* Wrs   = Wls + K * 128;         // K*128
    float* bs    = Wrs + K * 128;         // 128
    float* stage = bs + 128;              // NQ * 4 * 2K   ([q][a(K) | x(K)])
    const int NQ = blockDim.x >> 7;
    float* rq    = stage + NQ * 8 * K;    // NQ * 4

    int tid = threadIdx.x;
    for (int i = tid; i < K * 128; i += blockDim.x) {
        Wls[i] = Wl[i];
        Wrs[i] = Wr[i];
    }
    if (tid < 128) bs[tid] = bl[tid];
    __syncthreads();

    int group = tid >> 7;
    int lt    = tid & 127;
    float* st = stage + group * (8 * K);

    int ntiles = (N_NODES + 3) >> 2;
    for (int base = blockIdx.x * NQ; base < ntiles; base += gridDim.x * NQ) {
        int tile   = base + group;
        bool active = (tile < ntiles);
        int n0 = tile * 4;
        if (active) {
            for (int idx = lt; idx < 4 * K; idx += 128) {
                int q = idx / K, k = idx - q * K;
                int node = n0 + q;
                float a = 0.0f, xv = 0.0f;
                if (node < N_NODES) {
                    a  = agg[node * K + k];
                    xv = xin[node * K + k];
                }
                st[q * 2 * K + k]     = a;
                st[q * 2 * K + K + k] = xv;
            }
            if (lt < 4) {
                int node = n0 + lt;
                float c = (node < N_NODES) ? cnt[node] : 1.0f;
                rq[group * 4 + lt] = 1.0f / fmaxf(c, 1.0f);
            }
        }
        __syncthreads();
        if (active) {
            int j = lt;
            float ga0 = 0, ga1 = 0, ga2 = 0, ga3 = 0;
            float gx0 = 0, gx1 = 0, gx2 = 0, gx3 = 0;
            const float4* A0 = (const float4*)(st + 0 * K);
            const float4* X0 = (const float4*)(st + 1 * K);
            const float4* A1 = (const float4*)(st + 2 * K);
            const float4* X1 = (const float4*)(st + 3 * K);
            const float4* A2 = (const float4*)(st + 4 * K);
            const float4* X2 = (const float4*)(st + 5 * K);
            const float4* A3 = (const float4*)(st + 6 * K);
            const float4* X3 = (const float4*)(st + 7 * K);
#pragma unroll 8
            for (int k4 = 0; k4 < K / 4; k4++) {
                float4 a0 = A0[k4], a1 = A1[k4], a2 = A2[k4], a3 = A3[k4];
                float4 x0 = X0[k4], x1 = X1[k4], x2 = X2[k4], x3 = X3[k4];
                int kb = k4 * 4;
                float wl, wr;
#define GEMM_STEP(U, C)                                              \
                wl = Wls[(kb + U) * 128 + j];                        \
                wr = Wrs[(kb + U) * 128 + j];                        \
                ga0 += a0.C * wl; ga1 += a1.C * wl;                  \
                ga2 += a2.C * wl; ga3 += a3.C * wl;                  \
                gx0 += x0.C * wr; gx1 += x1.C * wr;                  \
                gx2 += x2.C * wr; gx3 += x3.C * wr;
                GEMM_STEP(0, x)
                GEMM_STEP(1, y)
                GEMM_STEP(2, z)
                GEMM_STEP(3, w)
#undef GEMM_STEP
            }
            float r0 = rq[group * 4 + 0], r1 = rq[group * 4 + 1];
            float r2 = rq[group * 4 + 2], r3 = rq[group * 4 + 3];
            float b = bs[j];
            float o0 = b + ga0 * r0 + gx0;
            float o1 = b + ga1 * r1 + gx1;
            float o2 = b + ga2 * r2 + gx2;
            float o3 = b + ga3 * r3 + gx3;
            if (RELU) {
                o0 = fmaxf(o0, 0.0f); o1 = fmaxf(o1, 0.0f);
                o2 = fmaxf(o2, 0.0f); o3 = fmaxf(o3, 0.0f);
            }
            if (n0 + 0 < N_NODES) outp[(n0 + 0) * 128 + j] = o0;
            if (n0 + 1 < N_NODES) outp[(n0 + 1) * 128 + j] = o1;
            if (n0 + 2 < N_NODES) outp[(n0 + 2) * 128 + j] = o2;
            if (n0 + 3 < N_NODES) outp[(n0 + 3) * 128 + j] = o3;
        }
        __syncthreads();
    }
}

// ---------------------------------------------------------------------------
// out[e] = b2 + W2 . relu( [h1[src], h1[dst], eattr] @ W1 + b1 )
// W1 (288x128, 147 KB) resident in SMEM. 4 groups x 4-edge tiles.
__launch_bounds__(512, 1)
__global__ void classify_kernel(const float* __restrict__ h1,
                                const int* __restrict__ fsrc,
                                const int* __restrict__ fdst,
                                const float* __restrict__ eattr,
                                const float* __restrict__ W1,
                                const float* __restrict__ b1,
                                const float* __restrict__ W2,
                                const float* __restrict__ b2,
                                float* __restrict__ outp, int Ef) {
    extern __shared__ float sm[];
    float* W1s   = sm;                  // 288*128
    float* b1s   = W1s + 288 * 128;     // 128
    float* W2s   = b1s + 128;           // 128
    float* stage = W2s + 128;           // NQ*4*288
    const int NQ = blockDim.x >> 7;
    float* red   = stage + NQ * 4 * 288; // NQ*16

    int tid = threadIdx.x;
    for (int i = tid; i < 288 * 128; i += blockDim.x) W1s[i] = W1[i];
    if (tid < 128) { b1s[tid] = b1[tid]; W2s[tid] = W2[tid]; }
    __syncthreads();
    float b2v = __ldg(&b2[0]);

    int group = tid >> 7;
    int lt    = tid & 127;
    int wrp   = lt >> 5;
    int lane  = lt & 31;
    float* st = stage + group * (4 * 288);

    int ntiles = (Ef + 3) >> 2;
    for (int base = blockIdx.x * NQ; base < ntiles; base += gridDim.x * NQ) {
        int tile = base + group;
        bool active = (tile < ntiles);
        int e0 = tile * 4;
        if (active) {
#pragma unroll
            for (int q = 0; q < 4; q++) {
                int e = e0 + q;
                float v1 = 0.0f, v2 = 0.0f;
                if (e < Ef) {
                    int s = __ldg(&fsrc[e]);
                    int d = __ldg(&fdst[e]);
                    v1 = h1[s * 128 + lt];
                    v2 = h1[d * 128 + lt];
                }
                st[q * 288 + lt]       = v1;
                st[q * 288 + 128 + lt] = v2;
                if (lt < 32) st[q * 288 + 256 + lt] = (e < Ef) ? eattr[e * 32 + lt] : 0.0f;
            }
        }
        __syncthreads();
        if (active) {
            int j = lt;
            float a0 = 0, a1 = 0, a2 = 0, a3 = 0;
            const float4* F0 = (const float4*)(st + 0);
            const float4* F1 = (const float4*)(st + 288);
            const float4* F2 = (const float4*)(st + 576);
            const float4* F3 = (const float4*)(st + 864);
#pragma unroll 8
            for (int k4 = 0; k4 < 72; k4++) {
                float4 x0 = F0[k4], x1 = F1[k4], x2 = F2[k4], x3 = F3[k4];
                int kb = k4 * 4;
                float w;
                w = W1s[(kb + 0) * 128 + j];
                a0 += x0.x * w; a1 += x1.x * w; a2 += x2.x * w; a3 += x3.x * w;
                w = W1s[(kb + 1) * 128 + j];
                a0 += x0.y * w; a1 += x1.y * w; a2 += x2.y * w; a3 += x3.y * w;
                w = W1s[(kb + 2) * 128 + j];
                a0 += x0.z * w; a1 += x1.z * w; a2 += x2.z * w; a3 += x3.z * w;
                w = W1s[(kb + 3) * 128 + j];
                a0 += x0.w * w; a1 += x1.w * w; a2 += x2.w * w; a3 += x3.w * w;
            }
            float bj = b1s[j], w2 = W2s[j];
            float h0v = fmaxf(a0 + bj, 0.0f) * w2;
            float h1v = fmaxf(a1 + bj, 0.0f) * w2;
            float h2v = fmaxf(a2 + bj, 0.0f) * w2;
            float h3v = fmaxf(a3 + bj, 0.0f) * w2;
#pragma unroll
            for (int off = 16; off; off >>= 1) {
                h0v += __shfl_xor_sync(0xffffffffu, h0v, off);
                h1v += __shfl_xor_sync(0xffffffffu, h1v, off);
                h2v += __shfl_xor_sync(0xffffffffu, h2v, off);
                h3v += __shfl_xor_sync(0xffffffffu, h3v, off);
            }
            if (lane == 0) {
                float* rg = red + group * 16;
                rg[0 * 4 + wrp] = h0v;
                rg[1 * 4 + wrp] = h1v;
                rg[2 * 4 + wrp] = h2v;
                rg[3 * 4 + wrp] = h3v;
            }
        }
        __syncthreads();
        if (active && lt < 4) {
            int e = e0 + lt;
            if (e < Ef) {
                float* rg = red + group * 16 + lt * 4;
                outp[e] = rg[0] + rg[1] + rg[2] + rg[3] + b2v;
            }
        }
    }
}

// ---------------------------------------------------------------------------
extern "C" void kernel_launch(void* const* d_in, const int* in_sizes, int n_in,
                              void* d_out, int out_size) {
    const float* x     = (const float*)d_in[0];
    const int*   ei    = (const int*)d_in[1];
    const int*   fei   = (const int*)d_in[2];
    const float* eattr = (const float*)d_in[3];
    const float* Wl0   = (const float*)d_in[4];
    const float* bl0   = (const float*)d_in[5];
    const float* Wr0   = (const float*)d_in[6];
    const float* Wl1   = (const float*)d_in[7];
    const float* bl1   = (const float*)d_in[8];
    const float* Wr1   = (const float*)d_in[9];
    const float* W1    = (const float*)d_in[10];
    const float* b1    = (const float*)d_in[11];
    const float* W2    = (const float*)d_in[12];
    const float* b2    = (const float*)d_in[13];
    float* outp = (float*)d_out;

    int E  = in_sizes[1] / 2;
    int Ef = in_sizes[2] / 2;
    const int* src  = ei;
    const int* dst  = ei + E;
    const int* fsrc = fei;
    const int* fdst = fei + Ef;

    float *agg_p, *cnt_p, *h0_p, *h1_p;
    cudaGetSymbolAddress((void**)&agg_p, g_agg);
    cudaGetSymbolAddress((void**)&cnt_p, g_cnt);
    cudaGetSymbolAddress((void**)&h0_p, g_h0);
    cudaGetSymbolAddress((void**)&h1_p, g_h1);

    const int smem0 = (2 * 64 * 128 + 128 + 4 * 8 * 64 + 16) * 4;
    const int smem1 = (2 * 128 * 128 + 128 + 4 * 8 * 128 + 16) * 4;
    const int smemC = (288 * 128 + 256 + 4 * 4 * 288 + 64) * 4;
    cudaFuncSetAttribute(sage_gemm_kernel<64, true>,
                         cudaFuncAttributeMaxDynamicSharedMemorySize, smem0);
    cudaFuncSetAttribute(sage_gemm_kernel<128, false>,
                         cudaFuncAttributeMaxDynamicSharedMemorySize, smem1);
    cudaFuncSetAttribute(classify_kernel,
                         cudaFuncAttributeMaxDynamicSharedMemorySize, smemC);

    // ---- Layer 0 ----
    zero_kernel<<<(N_NODES * 64 + 255) / 256, 256>>>(agg_p, N_NODES * 64);
    zero_kernel<<<(N_NODES + 255) / 256, 256>>>(cnt_p, N_NODES);
    count_kernel<<<(E + 255) / 256, 256>>>(dst, E, cnt_p);
    scatter_kernel<64><<<(E * 64 + 255) / 256, 256>>>(x, src, dst, E, agg_p);
    sage_gemm_kernel<64, true><<<444, 512, smem0>>>(agg_p, cnt_p, x, Wl0, bl0, Wr0, h0_p);

    // ---- Layer 1 ----
    zero_kernel<<<(N_NODES * 128 + 255) / 256, 256>>>(agg_p, N_NODES * 128);
    scatter_kernel<128><<<(E * 128 + 255) / 256, 256>>>(h0_p, src, dst, E, agg_p);
    sage_gemm_kernel<128, false><<<148, 512, smem1>>>(agg_p, cnt_p, h0_p, Wl1, bl1, Wr1, h1_p);

    // ---- Edge classifier ----
    classify_kernel<<<148, 512, smemC>>>(h1_p, fsrc, fdst, eattr, W1, b1, W2, b2, outp, Ef);
}

// round 4
// speedup vs baseline: 3.4023x; 3.4023x over previous
#include <cuda_runtime.h>
#include <cstdint>

#define N_NODES 100000

// Scratch (allocation-free rule: __device__ globals)
__device__ float g_agg[N_NODES * 128];
__device__ float g_cnt[N_NODES];
__device__ float g_h0[N_NODES * 128];
__device__ float g_h1[N_NODES * 128];

// ---------------------------------------------------------------------------
__device__ __forceinline__ uint32_t f2tf32(float x) {
    uint32_t u;
    asm("cvt.rna.tf32.f32 %0, %1;" : "=r"(u) : "f"(x));
    return u;
}

__device__ __forceinline__ void mma_tf32(float4& d, const float4 a, const float2 b) {
    asm("mma.sync.aligned.m16n8k8.row.col.f32.tf32.tf32.f32 "
        "{%0,%1,%2,%3}, {%4,%5,%6,%7}, {%8,%9}, {%0,%1,%2,%3};"
        : "+f"(d.x), "+f"(d.y), "+f"(d.z), "+f"(d.w)
        : "r"(__float_as_uint(a.x)), "r"(__float_as_uint(a.y)),
          "r"(__float_as_uint(a.z)), "r"(__float_as_uint(a.w)),
          "r"(__float_as_uint(b.x)), "r"(__float_as_uint(b.y)));
}

// B fragment slot (m16n8k8 tf32, row.col): k x n value -> permuted SMEM offset
__device__ __forceinline__ int b_slot(int k, int n) {
    return (((k >> 3) * 16 + (n >> 3)) * 32 + (n & 7) * 4 + (k & 3)) * 2 + ((k >> 2) & 1);
}

// ---------------------------------------------------------------------------
__global__ void count_kernel(const int* __restrict__ dst, int E, float* __restrict__ cnt) {
    int e = blockIdx.x * blockDim.x + threadIdx.x;
    if (e < E) atomicAdd(&cnt[dst[e]], 1.0f);
}

template <int F>
__global__ void scatter_v4_kernel(const float* __restrict__ feat,
                                  const int* __restrict__ src,
                                  const int* __restrict__ dst,
                                  int E, float* __restrict__ agg) {
    const int PER = F / 4;
    int id = blockIdx.x * blockDim.x + threadIdx.x;
    if (id >= E * PER) return;
    int e = id / PER;
    int g = id - e * PER;
    int s = __ldg(&src[e]);
    int d = __ldg(&dst[e]);
    float4 v = *(const float4*)(feat + (size_t)s * F + g * 4);
    float* a = agg + (size_t)d * F + g * 4;
    asm volatile("red.global.add.v4.f32 [%0], {%1, %2, %3, %4};"
                 :: "l"(a), "f"(v.x), "f"(v.y), "f"(v.z), "f"(v.w) : "memory");
}

// ---------------------------------------------------------------------------
// Fused SAGE layer via tf32 mma.sync:
//   out[n,:] = act( [agg[n,:]/max(cnt,1) | x[n,:]] @ [Wl;Wr] + bl )
// K = 2*featdim total. M-tile=128 nodes, N=128. Persistent CTAs, B in SMEM
// (fragment-permuted), A panels (128x32) double-buffered, fragment-permuted.
template <int K, bool RELU>
__launch_bounds__(256, 1)
__global__ void layer_mma_kernel(const float* __restrict__ agg,
                                 const float* __restrict__ cnt,
                                 const float* __restrict__ xin,
                                 const float* __restrict__ Wl,
                                 const float* __restrict__ bl,
                                 const float* __restrict__ Wr,
                                 float* __restrict__ outp) {
    extern __shared__ float sm[];
    float* Bsm = sm;                  // K*128 (permuted tf32)
    float* Asm = Bsm + K * 128;       // 2 * 4096 (two panels, permuted tf32)
    float* bs  = Asm + 8192;          // 128
    float* rcs = bs + 128;            // 128

    const int tid = threadIdx.x;
    const int FD = K / 2;

    for (int i = tid; i < K * 128; i += 256) {
        int k = i >> 7, n = i & 127;
        float w = (k < FD) ? Wl[k * 128 + n] : Wr[(k - FD) * 128 + n];
        Bsm[b_slot(k, n)] = __uint_as_float(f2tf32(w));
    }
    if (tid < 128) bs[tid] = bl[tid];
    __syncthreads();

    const int wid = tid >> 5, lane = tid & 31;
    const int wm = wid & 3, wn = wid >> 2;

    constexpr int P = K / 32;
    const int ntiles = (N_NODES + 127) >> 7;

    for (int tile = blockIdx.x; tile < ntiles; tile += gridDim.x) {
        const int n0 = tile << 7;
        if (tid < 128) {
            int node = min(n0 + tid, N_NODES - 1);
            rcs[tid] = 1.0f / fmaxf(cnt[node], 1.0f);
        }
        __syncthreads();

        auto stage = [&](int p, float* Af) {
#pragma unroll
            for (int it = 0; it < 4; it++) {
                int idx = tid + 256 * it;
                int r = idx >> 3, g = idx & 7;
                int node = min(n0 + r, N_NODES - 1);
                int c0 = p * 32 + g * 4;
                float4 v;
                if (c0 < FD) {
                    v = *(const float4*)(agg + (size_t)node * FD + c0);
                    float rc = rcs[r];
                    v.x *= rc; v.y *= rc; v.z *= rc; v.w *= rc;
                } else {
                    v = *(const float4*)(xin + (size_t)node * FD + (c0 - FD));
                }
                int kk = g >> 1, mt = r >> 4;
                int reg = ((r >> 3) & 1) | ((g & 1) << 1);
                int lb = ((kk * 8 + mt) * 32 + (r & 7) * 4);
                Af[(lb + 0) * 4 + reg] = __uint_as_float(f2tf32(v.x));
                Af[(lb + 1) * 4 + reg] = __uint_as_float(f2tf32(v.y));
                Af[(lb + 2) * 4 + reg] = __uint_as_float(f2tf32(v.z));
                Af[(lb + 3) * 4 + reg] = __uint_as_float(f2tf32(v.w));
            }
        };

        stage(0, Asm);
        __syncthreads();

        float4 d[2][8];
#pragma unroll
        for (int t = 0; t < 2; t++)
#pragma unroll
            for (int j = 0; j < 8; j++) d[t][j] = make_float4(0.f, 0.f, 0.f, 0.f);

        for (int p = 0; p < P; p++) {
            if (p + 1 < P) stage(p + 1, Asm + ((p + 1) & 1) * 4096);
            const float* Af = Asm + (p & 1) * 4096;
#pragma unroll
            for (int kk = 0; kk < 4; kk++) {
                float4 av0 = *(const float4*)&Af[((kk * 8 + wm * 2 + 0) * 32 + lane) * 4];
                float4 av1 = *(const float4*)&Af[((kk * 8 + wm * 2 + 1) * 32 + lane) * 4];
                int kt = p * 4 + kk;
#pragma unroll
                for (int j = 0; j < 8; j++) {
                    float2 bv = *(const float2*)&Bsm[((kt * 16 + wn * 8 + j) * 32 + lane) * 2];
                    mma_tf32(d[0][j], av0, bv);
                    mma_tf32(d[1][j], av1, bv);
                }
            }
            __syncthreads();
        }

        // epilogue
        const int gid = lane >> 2, tig = lane & 3;
#pragma unroll
        for (int t = 0; t < 2; t++) {
            int rlo = wm * 32 + t * 16 + gid;
            int rhi = rlo + 8;
            int nlo = n0 + rlo, nhi = n0 + rhi;
#pragma unroll
            for (int j = 0; j < 8; j++) {
                int col = wn * 64 + j * 8 + tig * 2;
                float ba = bs[col], bb = bs[col + 1];
                float2 lo = make_float2(d[t][j].x + ba, d[t][j].y + bb);
                float2 hi = make_float2(d[t][j].z + ba, d[t][j].w + bb);
                if (RELU) {
                    lo.x = fmaxf(lo.x, 0.f); lo.y = fmaxf(lo.y, 0.f);
                    hi.x = fmaxf(hi.x, 0.f); hi.y = fmaxf(hi.y, 0.f);
                }
                if (nlo < N_NODES) *(float2*)&outp[(size_t)nlo * 128 + col] = lo;
                if (nhi < N_NODES) *(float2*)&outp[(size_t)nhi * 128 + col] = hi;
            }
        }
        __syncthreads();
    }
}

// ---------------------------------------------------------------------------
// Classifier via tf32 mma.sync:
//   out[e] = b2 + W2 . relu( [h1[fsrc], h1[fdst], eattr] @ W1 + b1 )
// M-tile = 128 edges, N = 128, K = 288. W1 permuted in SMEM, persistent CTAs.
__launch_bounds__(256, 1)
__global__ void classify_mma_kernel(const float* __restrict__ h1,
                                    const int* __restrict__ fsrc,
                                    const int* __restrict__ fdst,
                                    const float* __restrict__ eattr,
                                    const float* __restrict__ W1,
                                    const float* __restrict__ b1,
                                    const float* __restrict__ W2,
                                    const float* __restrict__ b2,
                                    float* __restrict__ outp, int Ef) {
    extern __shared__ float sm[];
    float* Bsm  = sm;                 // 288*128 permuted tf32
    float* Asm  = Bsm + 288 * 128;    // 2 * 4096
    float* b1s  = Asm + 8192;         // 128
    float* w2s  = b1s + 128;          // 128
    float* red  = w2s + 128;          // 128
    int*   sidx = (int*)(red + 128);  // 128
    int*   didx = sidx + 128;         // 128

    const int tid = threadIdx.x;

    for (int i = tid; i < 288 * 128; i += 256) {
        int k = i >> 7, n = i & 127;
        Bsm[b_slot(k, n)] = __uint_as_float(f2tf32(W1[i]));
    }
    if (tid < 128) { b1s[tid] = b1[tid]; w2s[tid] = W2[tid]; }
    __syncthreads();
    const float b2v = __ldg(&b2[0]);

    const int wid = tid >> 5, lane = tid & 31;
    const int wm = wid & 3, wn = wid >> 2;
    const int gid = lane >> 2, tig = lane & 3;

    const int ntiles = (Ef + 127) >> 7;
    for (int tile = blockIdx.x; tile < ntiles; tile += gridDim.x) {
        const int e0 = tile << 7;
        if (tid < 128) {
            int e = min(e0 + tid, Ef - 1);
            sidx[tid] = __ldg(&fsrc[e]);
            didx[tid] = __ldg(&fdst[e]);
            red[tid] = 0.0f;
        }
        __syncthreads();

        auto stage = [&](int p, float* Af) {
#pragma unroll
            for (int it = 0; it < 4; it++) {
                int idx = tid + 256 * it;
                int r = idx >> 3, g = idx & 7;
                int c0 = p * 32 + g * 4;
                const float4* srcp;
                if (c0 < 128)
                    srcp = (const float4*)(h1 + (size_t)sidx[r] * 128 + c0);
                else if (c0 < 256)
                    srcp = (const float4*)(h1 + (size_t)didx[r] * 128 + (c0 - 128));
                else {
                    int e = min(e0 + r, Ef - 1);
                    srcp = (const float4*)(eattr + (size_t)e * 32 + (c0 - 256));
                }
                float4 v = *srcp;
                int kk = g >> 1, mt = r >> 4;
                int reg = ((r >> 3) & 1) | ((g & 1) << 1);
                int lb = ((kk * 8 + mt) * 32 + (r & 7) * 4);
                Af[(lb + 0) * 4 + reg] = __uint_as_float(f2tf32(v.x));
                Af[(lb + 1) * 4 + reg] = __uint_as_float(f2tf32(v.y));
                Af[(lb + 2) * 4 + reg] = __uint_as_float(f2tf32(v.z));
                Af[(lb + 3) * 4 + reg] = __uint_as_float(f2tf32(v.w));
            }
        };

        stage(0, Asm);
        __syncthreads();

        float4 d[2][8];
#pragma unroll
        for (int t = 0; t < 2; t++)
#pragma unroll
            for (int j = 0; j < 8; j++) d[t][j] = make_float4(0.f, 0.f, 0.f, 0.f);

        for (int p = 0; p < 9; p++) {
            if (p + 1 < 9) stage(p + 1, Asm + ((p + 1) & 1) * 4096);
            const float* Af = Asm + (p & 1) * 4096;
#pragma unroll
            for (int kk = 0; kk < 4; kk++) {
                float4 av0 = *(const float4*)&Af[((kk * 8 + wm * 2 + 0) * 32 + lane) * 4];
                float4 av1 = *(const float4*)&Af[((kk * 8 + wm * 2 + 1) * 32 + lane) * 4];
                int kt = p * 4 + kk;
#pragma unroll
                for (int j = 0; j < 8; j++) {
                    float2 bv = *(const float2*)&Bsm[((kt * 16 + wn * 8 + j) * 32 + lane) * 2];
                    mma_tf32(d[0][j], av0, bv);
                    mma_tf32(d[1][j], av1, bv);
                }
            }
            __syncthreads();
        }

        // epilogue: relu + dot with W2, reduce over the 128 hidden dims
        float s00 = 0.f, s01 = 0.f, s10 = 0.f, s11 = 0.f;
#pragma unroll
        for (int t = 0; t < 2; t++) {
#pragma unroll
            for (int j = 0; j < 8; j++) {
                int col = wn * 64 + j * 8 + tig * 2;
                float ba = b1s[col], bb = b1s[col + 1];
                float wa = w2s[col], wb = w2s[col + 1];
                float vlo = fmaxf(d[t][j].x + ba, 0.f) * wa + fmaxf(d[t][j].y + bb, 0.f) * wb;
                float vhi = fmaxf(d[t][j].z + ba, 0.f) * wa + fmaxf(d[t][j].w + bb, 0.f) * wb;
                if (t == 0) { s00 += vlo; s01 += vhi; }
                else        { s10 += vlo; s11 += vhi; }
            }
        }
#pragma unroll
        for (int off = 1; off <= 2; off <<= 1) {
            s00 += __shfl_xor_sync(0xffffffffu, s00, off);
            s01 += __shfl_xor_sync(0xffffffffu, s01, off);
            s10 += __shfl_xor_sync(0xffffffffu, s10, off);
            s11 += __shfl_xor_sync(0xffffffffu, s11, off);
        }
        if (tig == 0) {
            atomicAdd(&red[wm * 32 + 0 * 16 + gid + 0], s00);
            atomicAdd(&red[wm * 32 + 0 * 16 + gid + 8], s01);
            atomicAdd(&red[wm * 32 + 1 * 16 + gid + 0], s10);
            atomicAdd(&red[wm * 32 + 1 * 16 + gid + 8], s11);
        }
        __syncthreads();
        if (tid < 128) {
            int e = e0 + tid;
            if (e < Ef) outp[e] = red[tid] + b2v;
        }
        __syncthreads();
    }
}

// ---------------------------------------------------------------------------
extern "C" void kernel_launch(void* const* d_in, const int* in_sizes, int n_in,
                              void* d_out, int out_size) {
    const float* x     = (const float*)d_in[0];
    const int*   ei    = (const int*)d_in[1];
    const int*   fei   = (const int*)d_in[2];
    const float* eattr = (const float*)d_in[3];
    const float* Wl0   = (const float*)d_in[4];
    const float* bl0   = (const float*)d_in[5];
    const float* Wr0   = (const float*)d_in[6];
    const float* Wl1   = (const float*)d_in[7];
    const float* bl1   = (const float*)d_in[8];
    const float* Wr1   = (const float*)d_in[9];
    const float* W1    = (const float*)d_in[10];
    const float* b1    = (const float*)d_in[11];
    const float* W2    = (const float*)d_in[12];
    const float* b2    = (const float*)d_in[13];
    float* outp = (float*)d_out;

    int E  = in_sizes[1] / 2;
    int Ef = in_sizes[2] / 2;
    const int* src  = ei;
    const int* dst  = ei + E;
    const int* fsrc = fei;
    const int* fdst = fei + Ef;

    float *agg_p, *cnt_p, *h0_p, *h1_p;
    cudaGetSymbolAddress((void**)&agg_p, g_agg);
    cudaGetSymbolAddress((void**)&cnt_p, g_cnt);
    cudaGetSymbolAddress((void**)&h0_p, g_h0);
    cudaGetSymbolAddress((void**)&h1_p, g_h1);

    const int smemL0 = (128 * 128 + 8192 + 256) * 4;
    const int smemL1 = (256 * 128 + 8192 + 256) * 4;
    const int smemC  = (288 * 128 + 8192 + 384 + 256) * 4;
    cudaFuncSetAttribute(layer_mma_kernel<128, true>,
                         cudaFuncAttributeMaxDynamicSharedMemorySize, smemL0);
    cudaFuncSetAttribute(layer_mma_kernel<256, false>,
                         cudaFuncAttributeMaxDynamicSharedMemorySize, smemL1);
    cudaFuncSetAttribute(classify_mma_kernel,
                         cudaFuncAttributeMaxDynamicSharedMemorySize, smemC);

    // ---- Layer 0 ----
    cudaMemsetAsync(agg_p, 0, (size_t)N_NODES * 64 * sizeof(float), 0);
    cudaMemsetAsync(cnt_p, 0, (size_t)N_NODES * sizeof(float), 0);
    count_kernel<<<(E + 255) / 256, 256>>>(dst, E, cnt_p);
    scatter_v4_kernel<64><<<(E * 16 + 255) / 256, 256>>>(x, src, dst, E, agg_p);
    layer_mma_kernel<128, true><<<148, 256, smemL0>>>(agg_p, cnt_p, x, Wl0, bl0, Wr0, h0_p);

    // ---- Layer 1 ----
    cudaMemsetAsync(agg_p, 0, (size_t)N_NODES * 128 * sizeof(float), 0);
    scatter_v4_kernel<128><<<(E * 32 + 255) / 256, 256>>>(h0_p, src, dst, E, agg_p);
    layer_mma_kernel<256, false><<<148, 256, smemL1>>>(agg_p, cnt_p, h0_p, Wl1, bl1, Wr1, h1_p);

    // ---- Edge classifier ----
    classify_mma_kernel<<<148, 256, smemC>>>(h1_p, fsrc, fdst, eattr,
                                             W1, b1, W2, b2, outp, Ef);
}

// round 5
// speedup vs baseline: 3.7961x; 1.1157x over previous
#include <cuda_runtime.h>
#include <cstdint>

#define N_NODES 100000

// Scratch (allocation-free rule: __device__ globals)
__device__ float g_agg[N_NODES * 64];
__device__ float g_agg2[N_NODES * 128];
__device__ float g_cnt[N_NODES];
__device__ float g_h0[N_NODES * 128];
__device__ float g_h1[N_NODES * 128];

// ---------------------------------------------------------------------------
__device__ __forceinline__ uint32_t f2tf32(float x) {
    uint32_t u;
    asm("cvt.rna.tf32.f32 %0, %1;" : "=r"(u) : "f"(x));
    return u;
}

__device__ __forceinline__ void mma_tf32(float4& d, const float4 a, const float2 b) {
    asm("mma.sync.aligned.m16n8k8.row.col.f32.tf32.tf32.f32 "
        "{%0,%1,%2,%3}, {%4,%5,%6,%7}, {%8,%9}, {%0,%1,%2,%3};"
        : "+f"(d.x), "+f"(d.y), "+f"(d.z), "+f"(d.w)
        : "r"(__float_as_uint(a.x)), "r"(__float_as_uint(a.y)),
          "r"(__float_as_uint(a.z)), "r"(__float_as_uint(a.w)),
          "r"(__float_as_uint(b.x)), "r"(__float_as_uint(b.y)));
}

// B fragment slot (m16n8k8 tf32, row.col): k x n value -> permuted SMEM offset
__device__ __forceinline__ int b_slot(int k, int n) {
    return (((k >> 3) * 16 + (n >> 3)) * 32 + (n & 7) * 4 + (k & 3)) * 2 + ((k >> 2) & 1);
}

// ---------------------------------------------------------------------------
__global__ void zero_all_kernel(float* __restrict__ a, int na4,
                                float* __restrict__ b, int nb4,
                                float* __restrict__ c, int nc) {
    int i = blockIdx.x * blockDim.x + threadIdx.x;
    int stride = gridDim.x * blockDim.x;
    float4 z = make_float4(0.f, 0.f, 0.f, 0.f);
    for (int j = i; j < na4; j += stride) ((float4*)a)[j] = z;
    for (int j = i; j < nb4; j += stride) ((float4*)b)[j] = z;
    for (int j = i; j < nc; j += stride) c[j] = 0.f;
}

// scatter (64-wide) with fused degree count
__global__ void scatter64_count_kernel(const float* __restrict__ feat,
                                       const int* __restrict__ src,
                                       const int* __restrict__ dst,
                                       int E, float* __restrict__ agg,
                                       float* __restrict__ cnt) {
    int id = blockIdx.x * blockDim.x + threadIdx.x;
    if (id < E) atomicAdd(&cnt[__ldg(&dst[id])], 1.0f);
    if (id >= E * 16) return;
    int e = id >> 4;
    int g = id & 15;
    int s = __ldg(&src[e]);
    int d = __ldg(&dst[e]);
    float4 v = *(const float4*)(feat + (size_t)s * 64 + g * 4);
    float* a = agg + (size_t)d * 64 + g * 4;
    asm volatile("red.global.add.v4.f32 [%0], {%1, %2, %3, %4};"
                 :: "l"(a), "f"(v.x), "f"(v.y), "f"(v.z), "f"(v.w) : "memory");
}

__global__ void scatter128_kernel(const float* __restrict__ feat,
                                  const int* __restrict__ src,
                                  const int* __restrict__ dst,
                                  int E, float* __restrict__ agg) {
    int id = blockIdx.x * blockDim.x + threadIdx.x;
    if (id >= E * 32) return;
    int e = id >> 5;
    int g = id & 31;
    int s = __ldg(&src[e]);
    int d = __ldg(&dst[e]);
    float4 v = *(const float4*)(feat + (size_t)s * 128 + g * 4);
    float* a = agg + (size_t)d * 128 + g * 4;
    asm volatile("red.global.add.v4.f32 [%0], {%1, %2, %3, %4};"
                 :: "l"(a), "f"(v.x), "f"(v.y), "f"(v.z), "f"(v.w) : "memory");
}

// ---------------------------------------------------------------------------
// Fused SAGE layer via tf32 mma.sync, M-tile = 256 nodes, N = 128, K total.
//   out[n,:] = act( [agg[n,:]/max(cnt,1) | x[n,:]] @ [Wl;Wr] + bl )
// 8 warps: wm = wid&3 -> 64-row block (4 x m16), wn = wid>>2 -> 64-col block.
// A panels (256x32) double-buffered, fragment-permuted with lane^kk swizzle.
template <int K, bool RELU>
__launch_bounds__(256, 1)
__global__ void layer_mma_kernel(const float* __restrict__ agg,
                                 const float* __restrict__ cnt,
                                 const float* __restrict__ xin,
                                 const float* __restrict__ Wl,
                                 const float* __restrict__ bl,
                                 const float* __restrict__ Wr,
                                 float* __restrict__ outp) {
    extern __shared__ float sm[];
    float* Bsm = sm;                  // K*128 permuted tf32
    float* Asm = Bsm + K * 128;       // 2 * 8192
    float* bs  = Asm + 16384;         // 128
    float* rcs = bs + 128;            // 256

    const int tid = threadIdx.x;
    const int FD = K / 2;

    for (int i = tid; i < K * 128; i += 256) {
        int k = i >> 7, n = i & 127;
        float w = (k < FD) ? Wl[k * 128 + n] : Wr[(k - FD) * 128 + n];
        Bsm[b_slot(k, n)] = __uint_as_float(f2tf32(w));
    }
    if (tid < 128) bs[tid] = bl[tid];
    __syncthreads();

    const int wid = tid >> 5, lane = tid & 31;
    const int wm = wid & 3, wn = wid >> 2;
    const int gid = lane >> 2, tig = lane & 3;

    constexpr int P = K / 32;
    const int ntiles = (N_NODES + 255) >> 8;

    for (int tile = blockIdx.x; tile < ntiles; tile += gridDim.x) {
        const int n0 = tile << 8;
        {
            int node = min(n0 + tid, N_NODES - 1);
            rcs[tid] = 1.0f / fmaxf(cnt[node], 1.0f);
        }
        __syncthreads();

        auto stage = [&](int p, float* Af) {
#pragma unroll
            for (int it = 0; it < 8; it++) {
                int idx = tid + 256 * it;
                int r = idx >> 3, g = idx & 7;
                int node = min(n0 + r, N_NODES - 1);
                int c0 = p * 32 + g * 4;
                float4 v;
                if (c0 < FD) {
                    v = *(const float4*)(agg + (size_t)node * FD + c0);
                    float rc = rcs[r];
                    v.x *= rc; v.y *= rc; v.z *= rc; v.w *= rc;
                } else {
                    v = *(const float4*)(xin + (size_t)node * FD + (c0 - FD));
                }
                int kk = g >> 1, mt = r >> 4;
                int reg = ((r >> 3) & 1) | ((g & 1) << 1);
                int sbase = (kk * 16 + mt) * 32;
                int s0 = (r & 7) * 4;
                Af[(sbase + ((s0 + 0) ^ kk)) * 4 + reg] = __uint_as_float(f2tf32(v.x));
                Af[(sbase + ((s0 + 1) ^ kk)) * 4 + reg] = __uint_as_float(f2tf32(v.y));
                Af[(sbase + ((s0 + 2) ^ kk)) * 4 + reg] = __uint_as_float(f2tf32(v.z));
                Af[(sbase + ((s0 + 3) ^ kk)) * 4 + reg] = __uint_as_float(f2tf32(v.w));
            }
        };

        stage(0, Asm);
        __syncthreads();

        float4 d[4][8];
#pragma unroll
        for (int t = 0; t < 4; t++)
#pragma unroll
            for (int j = 0; j < 8; j++) d[t][j] = make_float4(0.f, 0.f, 0.f, 0.f);

        for (int p = 0; p < P; p++) {
            if (p + 1 < P) stage(p + 1, Asm + ((p + 1) & 1) * 8192);
            const float* Af = Asm + (p & 1) * 8192;
#pragma unroll
            for (int kk = 0; kk < 4; kk++) {
                float4 av[4];
#pragma unroll
                for (int t = 0; t < 4; t++)
                    av[t] = *(const float4*)&Af[((kk * 16 + wm * 4 + t) * 32 + (lane ^ kk)) * 4];
                int kt = p * 4 + kk;
#pragma unroll
                for (int j = 0; j < 8; j++) {
                    float2 bv = *(const float2*)&Bsm[((kt * 16 + wn * 8 + j) * 32 + lane) * 2];
#pragma unroll
                    for (int t = 0; t < 4; t++) mma_tf32(d[t][j], av[t], bv);
                }
            }
            __syncthreads();
        }

        // epilogue
#pragma unroll
        for (int t = 0; t < 4; t++) {
            int nlo = n0 + wm * 64 + t * 16 + gid;
            int nhi = nlo + 8;
#pragma unroll
            for (int j = 0; j < 8; j++) {
                int col = wn * 64 + j * 8 + tig * 2;
                float ba = bs[col], bb = bs[col + 1];
                float2 lo = make_float2(d[t][j].x + ba, d[t][j].y + bb);
                float2 hi = make_float2(d[t][j].z + ba, d[t][j].w + bb);
                if (RELU) {
                    lo.x = fmaxf(lo.x, 0.f); lo.y = fmaxf(lo.y, 0.f);
                    hi.x = fmaxf(hi.x, 0.f); hi.y = fmaxf(hi.y, 0.f);
                }
                if (nlo < N_NODES) *(float2*)&outp[(size_t)nlo * 128 + col] = lo;
                if (nhi < N_NODES) *(float2*)&outp[(size_t)nhi * 128 + col] = hi;
            }
        }
        __syncthreads();
    }
}

// ---------------------------------------------------------------------------
// Classifier via tf32 mma.sync, M-tile = 256 edges, N = 128, K = 288.
//   out[e] = b2 + W2 . relu( [h1[fsrc], h1[fdst], eattr] @ W1 + b1 )
__launch_bounds__(256, 1)
__global__ void classify_mma_kernel(const float* __restrict__ h1,
                                    const int* __restrict__ fsrc,
                                    const int* __restrict__ fdst,
                                    const float* __restrict__ eattr,
                                    const float* __restrict__ W1,
                                    const float* __restrict__ b1,
                                    const float* __restrict__ W2,
                                    const float* __restrict__ b2,
                                    float* __restrict__ outp, int Ef) {
    extern __shared__ float sm[];
    float* Bsm  = sm;                 // 288*128 permuted tf32 = 36864
    float* Asm  = Bsm + 36864;        // 2 * 8192
    float* b1s  = Asm + 16384;        // 128
    float* w2s  = b1s + 128;          // 128
    float* red  = w2s + 128;          // 256
    int*   sidx = (int*)(red + 256);  // 256
    int*   didx = sidx + 256;         // 256

    const int tid = threadIdx.x;

    for (int i = tid; i < 288 * 128; i += 256) {
        int k = i >> 7, n = i & 127;
        Bsm[b_slot(k, n)] = __uint_as_float(f2tf32(W1[i]));
    }
    if (tid < 128) { b1s[tid] = b1[tid]; w2s[tid] = W2[tid]; }
    __syncthreads();
    const float b2v = __ldg(&b2[0]);

    const int wid = tid >> 5, lane = tid & 31;
    const int wm = wid & 3, wn = wid >> 2;
    const int gid = lane >> 2, tig = lane & 3;

    const int ntiles = (Ef + 255) >> 8;
    for (int tile = blockIdx.x; tile < ntiles; tile += gridDim.x) {
        const int e0 = tile << 8;
        {
            int e = min(e0 + tid, Ef - 1);
            sidx[tid] = __ldg(&fsrc[e]);
            didx[tid] = __ldg(&fdst[e]);
            red[tid] = 0.0f;
        }
        __syncthreads();

        auto stage = [&](int p, float* Af) {
#pragma unroll
            for (int it = 0; it < 8; it++) {
                int idx = tid + 256 * it;
                int r = idx >> 3, g = idx & 7;
                int c0 = p * 32 + g * 4;
                const float4* srcp;
                if (c0 < 128)
                    srcp = (const float4*)(h1 + (size_t)sidx[r] * 128 + c0);
                else if (c0 < 256)
                    srcp = (const float4*)(h1 + (size_t)didx[r] * 128 + (c0 - 128));
                else {
                    int e = min(e0 + r, Ef - 1);
                    srcp = (const float4*)(eattr + (size_t)e * 32 + (c0 - 256));
                }
                float4 v = *srcp;
                int kk = g >> 1, mt = r >> 4;
                int reg = ((r >> 3) & 1) | ((g & 1) << 1);
                int sbase = (kk * 16 + mt) * 32;
                int s0 = (r & 7) * 4;
                Af[(sbase + ((s0 + 0) ^ kk)) * 4 + reg] = __uint_as_float(f2tf32(v.x));
                Af[(sbase + ((s0 + 1) ^ kk)) * 4 + reg] = __uint_as_float(f2tf32(v.y));
                Af[(sbase + ((s0 + 2) ^ kk)) * 4 + reg] = __uint_as_float(f2tf32(v.z));
                Af[(sbase + ((s0 + 3) ^ kk)) * 4 + reg] = __uint_as_float(f2tf32(v.w));
            }
        };

        stage(0, Asm);
        __syncthreads();

        float4 d[4][8];
#pragma unroll
        for (int t = 0; t < 4; t++)
#pragma unroll
            for (int j = 0; j < 8; j++) d[t][j] = make_float4(0.f, 0.f, 0.f, 0.f);

        for (int p = 0; p < 9; p++) {
            if (p + 1 < 9) stage(p + 1, Asm + ((p + 1) & 1) * 8192);
            const float* Af = Asm + (p & 1) * 8192;
#pragma unroll
            for (int kk = 0; kk < 4; kk++) {
                float4 av[4];
#pragma unroll
                for (int t = 0; t < 4; t++)
                    av[t] = *(const float4*)&Af[((kk * 16 + wm * 4 + t) * 32 + (lane ^ kk)) * 4];
                int kt = p * 4 + kk;
#pragma unroll
                for (int j = 0; j < 8; j++) {
                    float2 bv = *(const float2*)&Bsm[((kt * 16 + wn * 8 + j) * 32 + lane) * 2];
#pragma unroll
                    for (int t = 0; t < 4; t++) mma_tf32(d[t][j], av[t], bv);
                }
            }
            __syncthreads();
        }

        // epilogue: relu + dot with W2, reduce over 128 hidden dims
        float s_[4][2];
#pragma unroll
        for (int t = 0; t < 4; t++) { s_[t][0] = 0.f; s_[t][1] = 0.f; }
#pragma unroll
        for (int t = 0; t < 4; t++) {
#pragma unroll
            for (int j = 0; j < 8; j++) {
                int col = wn * 64 + j * 8 + tig * 2;
                float ba = b1s[col], bb = b1s[col + 1];
                float wa = w2s[col], wb = w2s[col + 1];
                s_[t][0] += fmaxf(d[t][j].x + ba, 0.f) * wa + fmaxf(d[t][j].y + bb, 0.f) * wb;
                s_[t][1] += fmaxf(d[t][j].z + ba, 0.f) * wa + fmaxf(d[t][j].w + bb, 0.f) * wb;
            }
        }
#pragma unroll
        for (int t = 0; t < 4; t++) {
            s_[t][0] += __shfl_xor_sync(0xffffffffu, s_[t][0], 1);
            s_[t][0] += __shfl_xor_sync(0xffffffffu, s_[t][0], 2);
            s_[t][1] += __shfl_xor_sync(0xffffffffu, s_[t][1], 1);
            s_[t][1] += __shfl_xor_sync(0xffffffffu, s_[t][1], 2);
        }
        if (tig == 0) {
#pragma unroll
            for (int t = 0; t < 4; t++) {
                atomicAdd(&red[wm * 64 + t * 16 + gid], s_[t][0]);
                atomicAdd(&red[wm * 64 + t * 16 + gid + 8], s_[t][1]);
            }
        }
        __syncthreads();
        {
            int e = e0 + tid;
            if (e < Ef) outp[e] = red[tid] + b2v;
        }
        __syncthreads();
    }
}

// ---------------------------------------------------------------------------
extern "C" void kernel_launch(void* const* d_in, const int* in_sizes, int n_in,
                              void* d_out, int out_size) {
    const float* x     = (const float*)d_in[0];
    const int*   ei    = (const int*)d_in[1];
    const int*   fei   = (const int*)d_in[2];
    const float* eattr = (const float*)d_in[3];
    const float* Wl0   = (const float*)d_in[4];
    const float* bl0   = (const float*)d_in[5];
    const float* Wr0   = (const float*)d_in[6];
    const float* Wl1   = (const float*)d_in[7];
    const float* bl1   = (const float*)d_in[8];
    const float* Wr1   = (const float*)d_in[9];
    const float* W1    = (const float*)d_in[10];
    const float* b1    = (const float*)d_in[11];
    const float* W2    = (const float*)d_in[12];
    const float* b2    = (const float*)d_in[13];
    float* outp = (float*)d_out;

    int E  = in_sizes[1] / 2;
    int Ef = in_sizes[2] / 2;
    const int* src  = ei;
    const int* dst  = ei + E;
    const int* fsrc = fei;
    const int* fdst = fei + Ef;

    float *agg_p, *agg2_p, *cnt_p, *h0_p, *h1_p;
    cudaGetSymbolAddress((void**)&agg_p, g_agg);
    cudaGetSymbolAddress((void**)&agg2_p, g_agg2);
    cudaGetSymbolAddress((void**)&cnt_p, g_cnt);
    cudaGetSymbolAddress((void**)&h0_p, g_h0);
    cudaGetSymbolAddress((void**)&h1_p, g_h1);

    const int smemL0 = (128 * 128 + 16384 + 384) * 4;
    const int smemL1 = (256 * 128 + 16384 + 384) * 4;
    const int smemC  = (288 * 128 + 16384 + 512) * 4 + 512 * 4;
    cudaFuncSetAttribute(layer_mma_kernel<128, true>,
                         cudaFuncAttributeMaxDynamicSharedMemorySize, smemL0);
    cudaFuncSetAttribute(layer_mma_kernel<256, false>,
                         cudaFuncAttributeMaxDynamicSharedMemorySize, smemL1);
    cudaFuncSetAttribute(classify_mma_kernel,
                         cudaFuncAttributeMaxDynamicSharedMemorySize, smemC);

    // launch 1: zero scratch (agg 64-wide, agg2 128-wide, cnt)
    zero_all_kernel<<<2048, 256>>>(agg_p, N_NODES * 16, agg2_p, N_NODES * 32,
                                   cnt_p, N_NODES);
    // launch 2: scatter x (64-wide) + degree count
    scatter64_count_kernel<<<(E * 16 + 255) / 256, 256>>>(x, src, dst, E, agg_p, cnt_p);
    // launch 3: layer 0
    layer_mma_kernel<128, true><<<148, 256, smemL0>>>(agg_p, cnt_p, x, Wl0, bl0, Wr0, h0_p);
    // launch 4: scatter h0 (128-wide)
    scatter128_kernel<<<(E * 32 + 255) / 256, 256>>>(h0_p, src, dst, E, agg2_p);
    // launch 5: layer 1
    layer_mma_kernel<256, false><<<148, 256, smemL1>>>(agg2_p, cnt_p, h0_p, Wl1, bl1, Wr1, h1_p);
    // launch 6: edge classifier (this one lands at ncu -s 5)
    classify_mma_kernel<<<148, 256, smemC>>>(h1_p, fsrc, fdst, eattr,
                                             W1, b1, W2, b2, outp, Ef);
}

// round 6
// speedup vs baseline: 4.4136x; 1.1627x over previous
#include <cuda_runtime.h>
#include <cuda_fp16.h>
#include <cstdint>

#define N_NODES 100000

// Scratch (allocation-free rule: __device__ globals)
__device__ float g_agg[N_NODES * 64];
__device__ float g_agg2[N_NODES * 128];
__device__ float g_cnt[N_NODES];
__device__ float g_h0[N_NODES * 128];
__device__ float g_h1[N_NODES * 128];

// ---------------------------------------------------------------------------
__device__ __forceinline__ void mma_f16(float4& d, const uint4 a, const uint2 b) {
    asm("mma.sync.aligned.m16n8k16.row.col.f32.f16.f16.f32 "
        "{%0,%1,%2,%3}, {%4,%5,%6,%7}, {%8,%9}, {%0,%1,%2,%3};"
        : "+f"(d.x), "+f"(d.y), "+f"(d.z), "+f"(d.w)
        : "r"(a.x), "r"(a.y), "r"(a.z), "r"(a.w), "r"(b.x), "r"(b.y));
}

__device__ __forceinline__ uint32_t packh2(float lo, float hi) {
    __half2 h = __floats2half2_rn(lo, hi);
    return *(uint32_t*)&h;
}

// ---------------------------------------------------------------------------
__global__ void zero_all_kernel(float* __restrict__ a, int na4,
                                float* __restrict__ b, int nb4,
                                float* __restrict__ c, int nc) {
    int i = blockIdx.x * blockDim.x + threadIdx.x;
    int stride = gridDim.x * blockDim.x;
    float4 z = make_float4(0.f, 0.f, 0.f, 0.f);
    for (int j = i; j < na4; j += stride) ((float4*)a)[j] = z;
    for (int j = i; j < nb4; j += stride) ((float4*)b)[j] = z;
    for (int j = i; j < nc; j += stride) c[j] = 0.f;
}

// scatter (64-wide) with fused degree count
__global__ void scatter64_count_kernel(const float* __restrict__ feat,
                                       const int* __restrict__ src,
                                       const int* __restrict__ dst,
                                       int E, float* __restrict__ agg,
                                       float* __restrict__ cnt) {
    int id = blockIdx.x * blockDim.x + threadIdx.x;
    if (id < E) atomicAdd(&cnt[__ldg(&dst[id])], 1.0f);
    if (id >= E * 16) return;
    int e = id >> 4;
    int g = id & 15;
    int s = __ldg(&src[e]);
    int d = __ldg(&dst[e]);
    float4 v = *(const float4*)(feat + (size_t)s * 64 + g * 4);
    float* a = agg + (size_t)d * 64 + g * 4;
    asm volatile("red.global.add.v4.f32 [%0], {%1, %2, %3, %4};"
                 :: "l"(a), "f"(v.x), "f"(v.y), "f"(v.z), "f"(v.w) : "memory");
}

// 128-wide scatter over a 64-column half (L2-resident working set per pass)
__global__ void scatter128_half_kernel(const float* __restrict__ feat,
                                       const int* __restrict__ src,
                                       const int* __restrict__ dst,
                                       int E, float* __restrict__ agg, int coff) {
    int id = blockIdx.x * blockDim.x + threadIdx.x;
    if (id >= E * 16) return;
    int e = id >> 4;
    int g = id & 15;
    int s = __ldg(&src[e]);
    int d = __ldg(&dst[e]);
    int col = coff + g * 4;
    float4 v = *(const float4*)(feat + (size_t)s * 128 + col);
    float* a = agg + (size_t)d * 128 + col;
    asm volatile("red.global.add.v4.f32 [%0], {%1, %2, %3, %4};"
                 :: "l"(a), "f"(v.x), "f"(v.y), "f"(v.z), "f"(v.w) : "memory");
}

// ---------------------------------------------------------------------------
// fp16 fragment layouts (m16n8k16, row.col, f32 accum):
// A slot (b32, per 32-k panel): [kt(2)][mt(16)][gid(8)][tig(4)][reg(4)]
//   thread (row r, k-group g) writes reg = ((r>>3)&1) | (half<<1) at
//   tig0, tig0+1 (the two k-pairs of its float4).
// B slot (b32): [kb(K/16)][nb(16)][lane(32)][reg(2)], pair = (k even, k odd).

// Fused SAGE layer via fp16 mma.sync, M-tile = 256 nodes, N = 128.
//   out[n,:] = act( [agg[n,:]/max(cnt,1) | x[n,:]] @ [Wl;Wr] + bl )
template <int K, bool RELU>
__launch_bounds__(256, 1)
__global__ void layer_mma_kernel(const float* __restrict__ agg,
                                 const float* __restrict__ cnt,
                                 const float* __restrict__ xin,
                                 const float* __restrict__ Wl,
                                 const float* __restrict__ bl,
                                 const float* __restrict__ Wr,
                                 float* __restrict__ outp) {
    extern __shared__ uint32_t usm[];
    uint32_t* Bsm = usm;                   // K*64 b32
    uint32_t* Asm = Bsm + K * 64;          // 2 * 4096 b32
    float* bs  = (float*)(Asm + 8192);     // 128
    float* rcs = bs + 128;                 // 256

    const int tid = threadIdx.x;
    const int FD = K / 2;

    // B init: pack fp16 pairs into fragment-permuted slots
    for (int s = tid; s < K * 64; s += 256) {
        int reg = s & 1, lane = (s >> 1) & 31, nb = (s >> 6) & 15, kb = s >> 10;
        int tig = lane & 3, gid = lane >> 2;
        int n = nb * 8 + gid;
        int k0 = kb * 16 + reg * 8 + tig * 2;
        float lo = (k0 < FD) ? Wl[k0 * 128 + n] : Wr[(k0 - FD) * 128 + n];
        float hi = (k0 + 1 < FD) ? Wl[(k0 + 1) * 128 + n] : Wr[(k0 + 1 - FD) * 128 + n];
        Bsm[s] = packh2(lo, hi);
    }
    if (tid < 128) bs[tid] = bl[tid];
    __syncthreads();

    const int wid = tid >> 5, lane = tid & 31;
    const int wm = wid & 3, wn = wid >> 2;
    const int gid = lane >> 2, tig = lane & 3;

    constexpr int P = K / 32;
    const int ntiles = (N_NODES + 255) >> 8;

    for (int tile = blockIdx.x; tile < ntiles; tile += gridDim.x) {
        const int n0 = tile << 8;
        {
            int node = min(n0 + tid, N_NODES - 1);
            rcs[tid] = 1.0f / fmaxf(cnt[node], 1.0f);
        }
        __syncthreads();

        auto stage = [&](int p, uint32_t* Af) {
#pragma unroll
            for (int it = 0; it < 8; it++) {
                int idx = tid + 256 * it;
                int r = idx >> 3, g = idx & 7;
                int node = min(n0 + r, N_NODES - 1);
                int c0 = p * 32 + g * 4;
                float4 v;
                if (c0 < FD) {
                    v = *(const float4*)(agg + (size_t)node * FD + c0);
                    float rc = rcs[r];
                    v.x *= rc; v.y *= rc; v.z *= rc; v.w *= rc;
                } else {
                    v = *(const float4*)(xin + (size_t)node * FD + (c0 - FD));
                }
                int kt = g >> 2, half = (g >> 1) & 1, tig0 = (g & 1) << 1;
                int reg = ((r >> 3) & 1) | (half << 1);
                int base = (((kt * 16 + (r >> 4)) * 32) + (r & 7) * 4);
                Af[(base + tig0) * 4 + reg]     = packh2(v.x, v.y);
                Af[(base + tig0 + 1) * 4 + reg] = packh2(v.z, v.w);
            }
        };

        stage(0, Asm);
        __syncthreads();

        float4 d[4][8];
#pragma unroll
        for (int t = 0; t < 4; t++)
#pragma unroll
            for (int j = 0; j < 8; j++) d[t][j] = make_float4(0.f, 0.f, 0.f, 0.f);

        for (int p = 0; p < P; p++) {
            if (p + 1 < P) stage(p + 1, Asm + ((p + 1) & 1) * 4096);
            const uint32_t* Af = Asm + (p & 1) * 4096;
#pragma unroll
            for (int kt = 0; kt < 2; kt++) {
                uint4 av[4];
#pragma unroll
                for (int t = 0; t < 4; t++)
                    av[t] = *(const uint4*)&Af[((kt * 16 + wm * 4 + t) * 32 + lane) * 4];
                int kb = p * 2 + kt;
#pragma unroll
                for (int j = 0; j < 8; j++) {
                    uint2 bv = *(const uint2*)&Bsm[((kb * 16 + wn * 8 + j) * 32 + lane) * 2];
#pragma unroll
                    for (int t = 0; t < 4; t++) mma_f16(d[t][j], av[t], bv);
                }
            }
            __syncthreads();
        }

        // epilogue
#pragma unroll
        for (int t = 0; t < 4; t++) {
            int nlo = n0 + wm * 64 + t * 16 + gid;
            int nhi = nlo + 8;
#pragma unroll
            for (int j = 0; j < 8; j++) {
                int col = wn * 64 + j * 8 + tig * 2;
                float ba = bs[col], bb = bs[col + 1];
                float2 lo = make_float2(d[t][j].x + ba, d[t][j].y + bb);
                float2 hi = make_float2(d[t][j].z + ba, d[t][j].w + bb);
                if (RELU) {
                    lo.x = fmaxf(lo.x, 0.f); lo.y = fmaxf(lo.y, 0.f);
                    hi.x = fmaxf(hi.x, 0.f); hi.y = fmaxf(hi.y, 0.f);
                }
                if (nlo < N_NODES) *(float2*)&outp[(size_t)nlo * 128 + col] = lo;
                if (nhi < N_NODES) *(float2*)&outp[(size_t)nhi * 128 + col] = hi;
            }
        }
        __syncthreads();
    }
}

// ---------------------------------------------------------------------------
// Classifier via fp16 mma.sync, M-tile = 256 edges, N = 128, K = 288.
//   out[e] = b2 + W2 . relu( [h1[fsrc], h1[fdst], eattr] @ W1 + b1 )
__launch_bounds__(256, 1)
__global__ void classify_mma_kernel(const float* __restrict__ h1,
                                    const int* __restrict__ fsrc,
                                    const int* __restrict__ fdst,
                                    const float* __restrict__ eattr,
                                    const float* __restrict__ W1,
                                    const float* __restrict__ b1,
                                    const float* __restrict__ W2,
                                    const float* __restrict__ b2,
                                    float* __restrict__ outp, int Ef) {
    extern __shared__ uint32_t usm[];
    uint32_t* Bsm = usm;                   // 288*64 = 18432 b32
    uint32_t* Asm = Bsm + 18432;           // 2 * 4096 b32
    float* b1s  = (float*)(Asm + 8192);    // 128
    float* w2s  = b1s + 128;               // 128
    float* red  = w2s + 128;               // 256
    int*   sidx = (int*)(red + 256);       // 256
    int*   didx = sidx + 256;              // 256

    const int tid = threadIdx.x;

    for (int s = tid; s < 288 * 64; s += 256) {
        int reg = s & 1, lane = (s >> 1) & 31, nb = (s >> 6) & 15, kb = s >> 10;
        int tigs = lane & 3, gids = lane >> 2;
        int n = nb * 8 + gids;
        int k0 = kb * 16 + reg * 8 + tigs * 2;
        Bsm[s] = packh2(W1[k0 * 128 + n], W1[(k0 + 1) * 128 + n]);
    }
    if (tid < 128) { b1s[tid] = b1[tid]; w2s[tid] = W2[tid]; }
    __syncthreads();
    const float b2v = __ldg(&b2[0]);

    const int wid = tid >> 5, lane = tid & 31;
    const int wm = wid & 3, wn = wid >> 2;
    const int gid = lane >> 2, tig = lane & 3;

    const int ntiles = (Ef + 255) >> 8;
    for (int tile = blockIdx.x; tile < ntiles; tile += gridDim.x) {
        const int e0 = tile << 8;
        {
            int e = min(e0 + tid, Ef - 1);
            sidx[tid] = __ldg(&fsrc[e]);
            didx[tid] = __ldg(&fdst[e]);
            red[tid] = 0.0f;
        }
        __syncthreads();

        auto stage = [&](int p, uint32_t* Af) {
#pragma unroll
            for (int it = 0; it < 8; it++) {
                int idx = tid + 256 * it;
                int r = idx >> 3, g = idx & 7;
                int c0 = p * 32 + g * 4;
                const float4* srcp;
                if (c0 < 128)
                    srcp = (const float4*)(h1 + (size_t)sidx[r] * 128 + c0);
                else if (c0 < 256)
                    srcp = (const float4*)(h1 + (size_t)didx[r] * 128 + (c0 - 128));
                else {
                    int e = min(e0 + r, Ef - 1);
                    srcp = (const float4*)(eattr + (size_t)e * 32 + (c0 - 256));
                }
                float4 v = *srcp;
                int kt = g >> 2, half = (g >> 1) & 1, tig0 = (g & 1) << 1;
                int reg = ((r >> 3) & 1) | (half << 1);
                int base = (((kt * 16 + (r >> 4)) * 32) + (r & 7) * 4);
                Af[(base + tig0) * 4 + reg]     = packh2(v.x, v.y);
                Af[(base + tig0 + 1) * 4 + reg] = packh2(v.z, v.w);
            }
        };

        stage(0, Asm);
        __syncthreads();

        float4 d[4][8];
#pragma unroll
        for (int t = 0; t < 4; t++)
#pragma unroll
            for (int j = 0; j < 8; j++) d[t][j] = make_float4(0.f, 0.f, 0.f, 0.f);

        for (int p = 0; p < 9; p++) {
            if (p + 1 < 9) stage(p + 1, Asm + ((p + 1) & 1) * 4096);
            const uint32_t* Af = Asm + (p & 1) * 4096;
#pragma unroll
            for (int kt = 0; kt < 2; kt++) {
                uint4 av[4];
#pragma unroll
                for (int t = 0; t < 4; t++)
                    av[t] = *(const uint4*)&Af[((kt * 16 + wm * 4 + t) * 32 + lane) * 4];
                int kb = p * 2 + kt;
#pragma unroll
                for (int j = 0; j < 8; j++) {
                    uint2 bv = *(const uint2*)&Bsm[((kb * 16 + wn * 8 + j) * 32 + lane) * 2];
#pragma unroll
                    for (int t = 0; t < 4; t++) mma_f16(d[t][j], av[t], bv);
                }
            }
            __syncthreads();
        }

        // epilogue: relu + dot with W2, reduce over 128 hidden dims
        float s_[4][2];
#pragma unroll
        for (int t = 0; t < 4; t++) { s_[t][0] = 0.f; s_[t][1] = 0.f; }
#pragma unroll
        for (int t = 0; t < 4; t++) {
#pragma unroll
            for (int j = 0; j < 8; j++) {
                int col = wn * 64 + j * 8 + tig * 2;
                float ba = b1s[col], bb = b1s[col + 1];
                float wa = w2s[col], wb = w2s[col + 1];
                s_[t][0] += fmaxf(d[t][j].x + ba, 0.f) * wa + fmaxf(d[t][j].y + bb, 0.f) * wb;
                s_[t][1] += fmaxf(d[t][j].z + ba, 0.f) * wa + fmaxf(d[t][j].w + bb, 0.f) * wb;
            }
        }
#pragma unroll
        for (int t = 0; t < 4; t++) {
            s_[t][0] += __shfl_xor_sync(0xffffffffu, s_[t][0], 1);
            s_[t][0] += __shfl_xor_sync(0xffffffffu, s_[t][0], 2);
            s_[t][1] += __shfl_xor_sync(0xffffffffu, s_[t][1], 1);
            s_[t][1] += __shfl_xor_sync(0xffffffffu, s_[t][1], 2);
        }
        if (tig == 0) {
#pragma unroll
            for (int t = 0; t < 4; t++) {
                atomicAdd(&red[wm * 64 + t * 16 + gid], s_[t][0]);
                atomicAdd(&red[wm * 64 + t * 16 + gid + 8], s_[t][1]);
            }
        }
        __syncthreads();
        {
            int e = e0 + tid;
            if (e < Ef) outp[e] = red[tid] + b2v;
        }
        __syncthreads();
    }
}

// ---------------------------------------------------------------------------
extern "C" void kernel_launch(void* const* d_in, const int* in_sizes, int n_in,
                              void* d_out, int out_size) {
    const float* x     = (const float*)d_in[0];
    const int*   ei    = (const int*)d_in[1];
    const int*   fei   = (const int*)d_in[2];
    const float* eattr = (const float*)d_in[3];
    const float* Wl0   = (const float*)d_in[4];
    const float* bl0   = (const float*)d_in[5];
    const float* Wr0   = (const float*)d_in[6];
    const float* Wl1   = (const float*)d_in[7];
    const float* bl1   = (const float*)d_in[8];
    const float* Wr1   = (const float*)d_in[9];
    const float* W1    = (const float*)d_in[10];
    const float* b1    = (const float*)d_in[11];
    const float* W2    = (const float*)d_in[12];
    const float* b2    = (const float*)d_in[13];
    float* outp = (float*)d_out;

    int E  = in_sizes[1] / 2;
    int Ef = in_sizes[2] / 2;
    const int* src  = ei;
    const int* dst  = ei + E;
    const int* fsrc = fei;
    const int* fdst = fei + Ef;

    float *agg_p, *agg2_p, *cnt_p, *h0_p, *h1_p;
    cudaGetSymbolAddress((void**)&agg_p, g_agg);
    cudaGetSymbolAddress((void**)&agg2_p, g_agg2);
    cudaGetSymbolAddress((void**)&cnt_p, g_cnt);
    cudaGetSymbolAddress((void**)&h0_p, g_h0);
    cudaGetSymbolAddress((void**)&h1_p, g_h1);

    const int smemL0 = (128 * 64 + 8192) * 4 + 384 * 4;
    const int smemL1 = (256 * 64 + 8192) * 4 + 384 * 4;
    const int smemC  = (18432 + 8192) * 4 + (512 + 512) * 4;
    cudaFuncSetAttribute(layer_mma_kernel<128, true>,
                         cudaFuncAttributeMaxDynamicSharedMemorySize, smemL0);
    cudaFuncSetAttribute(layer_mma_kernel<256, false>,
                         cudaFuncAttributeMaxDynamicSharedMemorySize, smemL1);
    cudaFuncSetAttribute(classify_mma_kernel,
                         cudaFuncAttributeMaxDynamicSharedMemorySize, smemC);

    // 1: zero scratch
    zero_all_kernel<<<2048, 256>>>(agg_p, N_NODES * 16, agg2_p, N_NODES * 32,
                                   cnt_p, N_NODES);
    // 2: scatter x (64-wide) + degree count
    scatter64_count_kernel<<<(E * 16 + 255) / 256, 256>>>(x, src, dst, E, agg_p, cnt_p);
    // 3: layer 0
    layer_mma_kernel<128, true><<<148, 256, smemL0>>>(agg_p, cnt_p, x, Wl0, bl0, Wr0, h0_p);
    // 4,5: scatter h0 (two 64-col halves, each L2-resident)
    scatter128_half_kernel<<<(E * 16 + 255) / 256, 256>>>(h0_p, src, dst, E, agg2_p, 0);
    scatter128_half_kernel<<<(E * 16 + 255) / 256, 256>>>(h0_p, src, dst, E, agg2_p, 64);
    // 6: layer 1
    layer_mma_kernel<256, false><<<148, 256, smemL1>>>(agg2_p, cnt_p, h0_p, Wl1, bl1, Wr1, h1_p);
    // 7: edge classifier
    classify_mma_kernel<<<148, 256, smemC>>>(h1_p, fsrc, fdst, eattr,
                                             W1, b1, W2, b2, outp, Ef);
}

// round 7
// speedup vs baseline: 5.8235x; 1.3194x over previous
#include <cuda_runtime.h>
#include <cuda_fp16.h>
#include <cstdint>

#define N_NODES 100000
#define EF_MAX  500000

// Scratch (allocation-free rule: __device__ globals)
__device__ float    g_agg[N_NODES * 64];
__device__ float    g_agg2[N_NODES * 128];
__device__ float    g_cnt[N_NODES];
__device__ float    g_h0[N_NODES * 128];
__device__ uint32_t g_xh[N_NODES * 32];      // x as half2
__device__ uint32_t g_h0h[N_NODES * 64];     // h0 as half2
__device__ uint32_t g_h1h[N_NODES * 64];     // h1 as half2
__device__ uint32_t g_aggh[N_NODES * 64];    // scaled agg as half2 (both layers)
__device__ uint32_t g_eattrh[EF_MAX * 16];   // edge_attr as half2
__device__ uint32_t g_B0[128 * 64];          // prepacked weight fragments
__device__ uint32_t g_B1[256 * 64];
__device__ uint32_t g_BC[288 * 64];

// ---------------------------------------------------------------------------
__device__ __forceinline__ void mma_f16(float4& d, const uint4 a, const uint2 b) {
    asm("mma.sync.aligned.m16n8k16.row.col.f32.f16.f16.f32 "
        "{%0,%1,%2,%3}, {%4,%5,%6,%7}, {%8,%9}, {%0,%1,%2,%3};"
        : "+f"(d.x), "+f"(d.y), "+f"(d.z), "+f"(d.w)
        : "r"(a.x), "r"(a.y), "r"(a.z), "r"(a.w), "r"(b.x), "r"(b.y));
}

__device__ __forceinline__ uint32_t packh2(float lo, float hi) {
    __half2 h = __floats2half2_rn(lo, hi);
    return *(uint32_t*)&h;
}

// B fragment pack: slot s of a K x 128 weight [Wl;Wr] (FD rows each)
__device__ __forceinline__ uint32_t pack_w(int s, int FD,
                                           const float* __restrict__ Wl,
                                           const float* __restrict__ Wr) {
    int reg = s & 1, lane = (s >> 1) & 31, nb = (s >> 6) & 15, kb = s >> 10;
    int tig = lane & 3, gid = lane >> 2;
    int n = nb * 8 + gid;
    int k0 = kb * 16 + reg * 8 + tig * 2;
    float lo = (k0 < FD) ? Wl[k0 * 128 + n] : Wr[(k0 - FD) * 128 + n];
    float hi = (k0 + 1 < FD) ? Wl[(k0 + 1) * 128 + n] : Wr[(k0 + 1 - FD) * 128 + n];
    return packh2(lo, hi);
}

// ---------------------------------------------------------------------------
// prep: zero scratch, convert x/eattr to fp16, prepack all weight fragments
__global__ void prep_kernel(const float* __restrict__ x,
                            const float* __restrict__ eattr,
                            const float* __restrict__ Wl0, const float* __restrict__ Wr0,
                            const float* __restrict__ Wl1, const float* __restrict__ Wr1,
                            const float* __restrict__ W1,
                            float* __restrict__ agg, float* __restrict__ agg2,
                            float* __restrict__ cnt,
                            uint32_t* __restrict__ xh, uint32_t* __restrict__ eattrh,
                            uint32_t* __restrict__ B0, uint32_t* __restrict__ B1,
                            uint32_t* __restrict__ BC, int Ef) {
    int i0 = blockIdx.x * blockDim.x + threadIdx.x;
    int stride = gridDim.x * blockDim.x;
    float4 z4 = make_float4(0.f, 0.f, 0.f, 0.f);
    for (int j = i0; j < N_NODES * 16; j += stride) ((float4*)agg)[j] = z4;
    for (int j = i0; j < N_NODES * 32; j += stride) ((float4*)agg2)[j] = z4;
    for (int j = i0; j < N_NODES; j += stride) cnt[j] = 0.f;
    for (int j = i0; j < N_NODES * 32; j += stride) {
        float2 v = ((const float2*)x)[j];
        xh[j] = packh2(v.x, v.y);
    }
    for (int j = i0; j < Ef * 16; j += stride) {
        float2 v = ((const float2*)eattr)[j];
        eattrh[j] = packh2(v.x, v.y);
    }
    for (int s = i0; s < 128 * 64; s += stride) B0[s] = pack_w(s, 64, Wl0, Wr0);
    for (int s = i0; s < 256 * 64; s += stride) B1[s] = pack_w(s, 128, Wl1, Wr1);
    for (int s = i0; s < 288 * 64; s += stride) BC[s] = pack_w(s, 288, W1, W1);
}

// scatter (64-wide) with fused degree count
__global__ void scatter64_count_kernel(const float* __restrict__ feat,
                                       const int* __restrict__ src,
                                       const int* __restrict__ dst,
                                       int E, float* __restrict__ agg,
                                       float* __restrict__ cnt) {
    int id = blockIdx.x * blockDim.x + threadIdx.x;
    if (id < E) atomicAdd(&cnt[__ldg(&dst[id])], 1.0f);
    if (id >= E * 16) return;
    int e = id >> 4;
    int g = id & 15;
    int s = __ldg(&src[e]);
    int d = __ldg(&dst[e]);
    float4 v = *(const float4*)(feat + (size_t)s * 64 + g * 4);
    float* a = agg + (size_t)d * 64 + g * 4;
    asm volatile("red.global.add.v4.f32 [%0], {%1, %2, %3, %4};"
                 :: "l"(a), "f"(v.x), "f"(v.y), "f"(v.z), "f"(v.w) : "memory");
}

// 128-wide scatter over a 64-column half (L2-resident working set per pass)
__global__ void scatter128_half_kernel(const float* __restrict__ feat,
                                       const int* __restrict__ src,
                                       const int* __restrict__ dst,
                                       int E, float* __restrict__ agg, int coff) {
    int id = blockIdx.x * blockDim.x + threadIdx.x;
    if (id >= E * 16) return;
    int e = id >> 4;
    int g = id & 15;
    int s = __ldg(&src[e]);
    int d = __ldg(&dst[e]);
    int col = coff + g * 4;
    float4 v = *(const float4*)(feat + (size_t)s * 128 + col);
    float* a = agg + (size_t)d * 128 + col;
    asm volatile("red.global.add.v4.f32 [%0], {%1, %2, %3, %4};"
                 :: "l"(a), "f"(v.x), "f"(v.y), "f"(v.z), "f"(v.w) : "memory");
}

// aggh[n,k] = half(agg[n,k] / max(cnt[n],1)) — packed half2, 8 floats per job
template <int FD8>
__global__ void conv_scale_half_kernel(const float* __restrict__ agg,
                                       const float* __restrict__ cnt,
                                       uint32_t* __restrict__ outh) {
    int idx = blockIdx.x * blockDim.x + threadIdx.x;
    if (idx >= N_NODES * FD8) return;
    int n = idx / FD8;
    int g = idx - n * FD8;
    float rc = 1.0f / fmaxf(__ldg(&cnt[n]), 1.0f);
    const float4* a = (const float4*)(agg + (size_t)n * FD8 * 8 + g * 8);
    float4 v0 = a[0], v1 = a[1];
    uint4 o;
    o.x = packh2(v0.x * rc, v0.y * rc);
    o.y = packh2(v0.z * rc, v0.w * rc);
    o.z = packh2(v1.x * rc, v1.y * rc);
    o.w = packh2(v1.z * rc, v1.w * rc);
    *(uint4*)(outh + (size_t)n * FD8 * 4 + g * 4) = o;
}

// ---------------------------------------------------------------------------
// Fused SAGE layer via fp16 mma.sync, M-tile = 256 nodes, N = 128.
// A sources are pre-packed fp16: aggh (scaled mean) | xh. B prepacked global.
template <int K, bool RELU, bool WF32>
__launch_bounds__(256, 1)
__global__ void layer_mma_kernel(const uint32_t* __restrict__ aggh,
                                 const uint32_t* __restrict__ xh,
                                 const uint32_t* __restrict__ Bg,
                                 const float* __restrict__ bl,
                                 float* __restrict__ outf,
                                 uint32_t* __restrict__ outh) {
    extern __shared__ uint32_t usm[];
    uint32_t* Bsm = usm;                   // K*64 b32
    uint32_t* Asm = Bsm + K * 64;          // 2 * 4096 b32
    float* bs = (float*)(Asm + 8192);      // 128

    const int tid = threadIdx.x;
    const int FD = K / 2;
    const int FD2 = FD / 2;  // u32 per row per source

    for (int i = tid; i < K * 16; i += 256)
        ((uint4*)Bsm)[i] = ((const uint4*)Bg)[i];
    if (tid < 128) bs[tid] = bl[tid];
    __syncthreads();

    const int wid = tid >> 5, lane = tid & 31;
    const int wm = wid & 3, wn = wid >> 2;
    const int gid = lane >> 2, tig = lane & 3;

    constexpr int P = K / 32;
    const int ntiles = (N_NODES + 255) >> 8;

    for (int tile = blockIdx.x; tile < ntiles; tile += gridDim.x) {
        const int n0 = tile << 8;

        auto stage = [&](int p, uint32_t* Af) {
            int c0 = p * 32;  // halves offset in full row
            const uint32_t* src;
            int cu;  // u32 offset within source row
            if (c0 < FD) { src = aggh; cu = c0 >> 1; }
            else         { src = xh;   cu = (c0 - FD) >> 1; }
#pragma unroll
            for (int it = 0; it < 4; it++) {
                int idx = tid + 256 * it;       // 0..1023
                int r = idx >> 2, g8 = idx & 3;
                int node = min(n0 + r, N_NODES - 1);
                uint4 v = *(const uint4*)(src + (size_t)node * FD2 + cu + g8 * 4);
                int kt = g8 >> 1, khalf = g8 & 1;
                int reg = ((r >> 3) & 1) | (khalf << 1);
                uint32_t* s = &Af[(((kt * 16 + (r >> 4)) * 32) + (r & 7) * 4) * 4 + reg];
                s[0] = v.x; s[4] = v.y; s[8] = v.z; s[12] = v.w;
            }
        };

        stage(0, Asm);
        __syncthreads();

        float4 d[4][8];
#pragma unroll
        for (int t = 0; t < 4; t++)
#pragma unroll
            for (int j = 0; j < 8; j++) d[t][j] = make_float4(0.f, 0.f, 0.f, 0.f);

        for (int p = 0; p < P; p++) {
            if (p + 1 < P) stage(p + 1, Asm + ((p + 1) & 1) * 4096);
            const uint32_t* Af = Asm + (p & 1) * 4096;
#pragma unroll
            for (int kt = 0; kt < 2; kt++) {
                uint4 av[4];
#pragma unroll
                for (int t = 0; t < 4; t++)
                    av[t] = *(const uint4*)&Af[((kt * 16 + wm * 4 + t) * 32 + lane) * 4];
                int kb = p * 2 + kt;
#pragma unroll
                for (int j = 0; j < 8; j++) {
                    uint2 bv = *(const uint2*)&Bsm[((kb * 16 + wn * 8 + j) * 32 + lane) * 2];
#pragma unroll
                    for (int t = 0; t < 4; t++) mma_f16(d[t][j], av[t], bv);
                }
            }
            __syncthreads();
        }

        // epilogue: bias (+relu), write fp16 (and fp32 if needed)
#pragma unroll
        for (int t = 0; t < 4; t++) {
            int nlo = n0 + wm * 64 + t * 16 + gid;
            int nhi = nlo + 8;
#pragma unroll
            for (int j = 0; j < 8; j++) {
                int col = wn * 64 + j * 8 + tig * 2;
                float ba = bs[col], bb = bs[col + 1];
                float2 lo = make_float2(d[t][j].x + ba, d[t][j].y + bb);
                float2 hi = make_float2(d[t][j].z + ba, d[t][j].w + bb);
                if (RELU) {
                    lo.x = fmaxf(lo.x, 0.f); lo.y = fmaxf(lo.y, 0.f);
                    hi.x = fmaxf(hi.x, 0.f); hi.y = fmaxf(hi.y, 0.f);
                }
                if (nlo < N_NODES) {
                    if (WF32) *(float2*)&outf[(size_t)nlo * 128 + col] = lo;
                    outh[(size_t)nlo * 64 + (col >> 1)] = packh2(lo.x, lo.y);
                }
                if (nhi < N_NODES) {
                    if (WF32) *(float2*)&outf[(size_t)nhi * 128 + col] = hi;
                    outh[(size_t)nhi * 64 + (col >> 1)] = packh2(hi.x, hi.y);
                }
            }
        }
        __syncthreads();
    }
}

// ---------------------------------------------------------------------------
// Classifier via fp16 mma.sync, M-tile = 256 edges, N = 128, K = 288.
//   out[e] = b2 + W2 . relu( [h1[fsrc], h1[fdst], eattr] @ W1 + b1 )
// All A sources pre-packed fp16; W1 fragments prepacked in global.
__launch_bounds__(256, 1)
__global__ void classify_mma_kernel(const uint32_t* __restrict__ h1h,
                                    const int* __restrict__ fsrc,
                                    const int* __restrict__ fdst,
                                    const uint32_t* __restrict__ eattrh,
                                    const uint32_t* __restrict__ Bg,
                                    const float* __restrict__ b1,
                                    const float* __restrict__ W2,
                                    const float* __restrict__ b2,
                                    float* __restrict__ outp, int Ef) {
    extern __shared__ uint32_t usm[];
    uint32_t* Bsm = usm;                   // 288*64 = 18432 b32
    uint32_t* Asm = Bsm + 18432;           // 2 * 4096 b32
    float* b1s  = (float*)(Asm + 8192);    // 128
    float* w2s  = b1s + 128;               // 128
    float* red  = w2s + 128;               // 256
    int*   sidx = (int*)(red + 256);       // 256
    int*   didx = sidx + 256;              // 256

    const int tid = threadIdx.x;

    for (int i = tid; i < 4608; i += 256)
        ((uint4*)Bsm)[i] = ((const uint4*)Bg)[i];
    if (tid < 128) { b1s[tid] = b1[tid]; w2s[tid] = W2[tid]; }
    __syncthreads();
    const float b2v = __ldg(&b2[0]);

    const int wid = tid >> 5, lane = tid & 31;
    const int wm = wid & 3, wn = wid >> 2;
    const int gid = lane >> 2, tig = lane & 3;

    const int ntiles = (Ef + 255) >> 8;
    for (int tile = blockIdx.x; tile < ntiles; tile += gridDim.x) {
        const int e0 = tile << 8;
        {
            int e = min(e0 + tid, Ef - 1);
            sidx[tid] = __ldg(&fsrc[e]);
            didx[tid] = __ldg(&fdst[e]);
            red[tid] = 0.0f;
        }
        __syncthreads();

        auto stage = [&](int p, uint32_t* Af) {
#pragma unroll
            for (int it = 0; it < 4; it++) {
                int idx = tid + 256 * it;       // 0..1023
                int r = idx >> 2, g8 = idx & 3;
                const uint32_t* sp;
                if (p < 4)
                    sp = h1h + (size_t)sidx[r] * 64 + p * 16 + g8 * 4;
                else if (p < 8)
                    sp = h1h + (size_t)didx[r] * 64 + (p - 4) * 16 + g8 * 4;
                else {
                    int e = min(e0 + r, Ef - 1);
                    sp = eattrh + (size_t)e * 16 + g8 * 4;
                }
                uint4 v = *(const uint4*)sp;
                int kt = g8 >> 1, khalf = g8 & 1;
                int reg = ((r >> 3) & 1) | (khalf << 1);
                uint32_t* s = &Af[(((kt * 16 + (r >> 4)) * 32) + (r & 7) * 4) * 4 + reg];
                s[0] = v.x; s[4] = v.y; s[8] = v.z; s[12] = v.w;
            }
        };

        stage(0, Asm);
        __syncthreads();

        float4 d[4][8];
#pragma unroll
        for (int t = 0; t < 4; t++)
#pragma unroll
            for (int j = 0; j < 8; j++) d[t][j] = make_float4(0.f, 0.f, 0.f, 0.f);

        for (int p = 0; p < 9; p++) {
            if (p + 1 < 9) stage(p + 1, Asm + ((p + 1) & 1) * 4096);
            const uint32_t* Af = Asm + (p & 1) * 4096;
#pragma unroll
            for (int kt = 0; kt < 2; kt++) {
                uint4 av[4];
#pragma unroll
                for (int t = 0; t < 4; t++)
                    av[t] = *(const uint4*)&Af[((kt * 16 + wm * 4 + t) * 32 + lane) * 4];
                int kb = p * 2 + kt;
#pragma unroll
                for (int j = 0; j < 8; j++) {
                    uint2 bv = *(const uint2*)&Bsm[((kb * 16 + wn * 8 + j) * 32 + lane) * 2];
#pragma unroll
                    for (int t = 0; t < 4; t++) mma_f16(d[t][j], av[t], bv);
                }
            }
            __syncthreads();
        }

        // epilogue: relu + dot with W2, reduce over 128 hidden dims
        float s_[4][2];
#pragma unroll
        for (int t = 0; t < 4; t++) { s_[t][0] = 0.f; s_[t][1] = 0.f; }
#pragma unroll
        for (int t = 0; t < 4; t++) {
#pragma unroll
            for (int j = 0; j < 8; j++) {
                int col = wn * 64 + j * 8 + tig * 2;
                float ba = b1s[col], bb = b1s[col + 1];
                float wa = w2s[col], wb = w2s[col + 1];
                s_[t][0] += fmaxf(d[t][j].x + ba, 0.f) * wa + fmaxf(d[t][j].y + bb, 0.f) * wb;
                s_[t][1] += fmaxf(d[t][j].z + ba, 0.f) * wa + fmaxf(d[t][j].w + bb, 0.f) * wb;
            }
        }
#pragma unroll
        for (int t = 0; t < 4; t++) {
            s_[t][0] += __shfl_xor_sync(0xffffffffu, s_[t][0], 1);
            s_[t][0] += __shfl_xor_sync(0xffffffffu, s_[t][0], 2);
            s_[t][1] += __shfl_xor_sync(0xffffffffu, s_[t][1], 1);
            s_[t][1] += __shfl_xor_sync(0xffffffffu, s_[t][1], 2);
        }
        if (tig == 0) {
#pragma unroll
            for (int t = 0; t < 4; t++) {
                atomicAdd(&red[wm * 64 + t * 16 + gid], s_[t][0]);
                atomicAdd(&red[wm * 64 + t * 16 + gid + 8], s_[t][1]);
            }
        }
        __syncthreads();
        {
            int e = e0 + tid;
            if (e < Ef) outp[e] = red[tid] + b2v;
        }
        __syncthreads();
    }
}

// ---------------------------------------------------------------------------
extern "C" void kernel_launch(void* const* d_in, const int* in_sizes, int n_in,
                              void* d_out, int out_size) {
    const float* x     = (const float*)d_in[0];
    const int*   ei    = (const int*)d_in[1];
    const int*   fei   = (const int*)d_in[2];
    const float* eattr = (const float*)d_in[3];
    const float* Wl0   = (const float*)d_in[4];
    const float* bl0   = (const float*)d_in[5];
    const float* Wr0   = (const float*)d_in[6];
    const float* Wl1   = (const float*)d_in[7];
    const float* bl1   = (const float*)d_in[8];
    const float* Wr1   = (const float*)d_in[9];
    const float* W1    = (const float*)d_in[10];
    const float* b1    = (const float*)d_in[11];
    const float* W2    = (const float*)d_in[12];
    const float* b2    = (const float*)d_in[13];
    float* outp = (float*)d_out;

    int E  = in_sizes[1] / 2;
    int Ef = in_sizes[2] / 2;
    const int* src  = ei;
    const int* dst  = ei + E;
    const int* fsrc = fei;
    const int* fdst = fei + Ef;

    float *agg_p, *agg2_p, *cnt_p, *h0_p;
    uint32_t *xh_p, *h0h_p, *h1h_p, *aggh_p, *eattrh_p, *B0_p, *B1_p, *BC_p;
    cudaGetSymbolAddress((void**)&agg_p, g_agg);
    cudaGetSymbolAddress((void**)&agg2_p, g_agg2);
    cudaGetSymbolAddress((void**)&cnt_p, g_cnt);
    cudaGetSymbolAddress((void**)&h0_p, g_h0);
    cudaGetSymbolAddress((void**)&xh_p, g_xh);
    cudaGetSymbolAddress((void**)&h0h_p, g_h0h);
    cudaGetSymbolAddress((void**)&h1h_p, g_h1h);
    cudaGetSymbolAddress((void**)&aggh_p, g_aggh);
    cudaGetSymbolAddress((void**)&eattrh_p, g_eattrh);
    cudaGetSymbolAddress((void**)&B0_p, g_B0);
    cudaGetSymbolAddress((void**)&B1_p, g_B1);
    cudaGetSymbolAddress((void**)&BC_p, g_BC);

    const int smemL0 = (128 * 64 + 8192 + 128) * 4;
    const int smemL1 = (256 * 64 + 8192 + 128) * 4;
    const int smemC  = (18432 + 8192 + 512) * 4 + 512 * 4;
    cudaFuncSetAttribute(layer_mma_kernel<128, true, true>,
                         cudaFuncAttributeMaxDynamicSharedMemorySize, smemL0);
    cudaFuncSetAttribute(layer_mma_kernel<256, false, false>,
                         cudaFuncAttributeMaxDynamicSharedMemorySize, smemL1);
    cudaFuncSetAttribute(classify_mma_kernel,
                         cudaFuncAttributeMaxDynamicSharedMemorySize, smemC);

    // 1: prep (zero scratch, fp16 conversions, weight prepack)
    prep_kernel<<<2048, 256>>>(x, eattr, Wl0, Wr0, Wl1, Wr1, W1,
                               agg_p, agg2_p, cnt_p, xh_p, eattrh_p,
                               B0_p, B1_p, BC_p, Ef);
    // 2: scatter x (64-wide) + degree count
    scatter64_count_kernel<<<(E * 16 + 255) / 256, 256>>>(x, src, dst, E, agg_p, cnt_p);
    // 3: aggh0 = half(agg / cnt)
    conv_scale_half_kernel<8><<<(N_NODES * 8 + 255) / 256, 256>>>(agg_p, cnt_p, aggh_p);
    // 4: layer 0 (writes h0 fp32 + h0h fp16)
    layer_mma_kernel<128, true, true><<<148, 256, smemL0>>>(aggh_p, xh_p, B0_p, bl0,
                                                            h0_p, h0h_p);
    // 5,6: scatter h0 (two 64-col halves, each L2-resident)
    scatter128_half_kernel<<<(E * 16 + 255) / 256, 256>>>(h0_p, src, dst, E, agg2_p, 0);
    scatter128_half_kernel<<<(E * 16 + 255) / 256, 256>>>(h0_p, src, dst, E, agg2_p, 64);
    // 7: aggh1 = half(agg2 / cnt)
    conv_scale_half_kernel<16><<<(N_NODES * 16 + 255) / 256, 256>>>(agg2_p, cnt_p, aggh_p);
    // 8: layer 1 (writes h1h fp16 only)
    layer_mma_kernel<256, false, false><<<148, 256, smemL1>>>(aggh_p, h0h_p, B1_p, bl1,
                                                              nullptr, h1h_p);
    // 9: edge classifier
    classify_mma_kernel<<<148, 256, smemC>>>(h1h_p, fsrc, fdst, eattrh_p,
                                             BC_p, b1, W2, b2, outp, Ef);
}

// round 9
// speedup vs baseline: 6.4494x; 1.1075x over previous
#include <cuda_runtime.h>
#include <cuda_fp16.h>
#include <cstdint>

#define N_NODES 100000
#define EF_MAX  500000

// Scratch (allocation-free rule: __device__ globals)
__device__ float    g_agg[N_NODES * 64];
__device__ float    g_agg2[N_NODES * 128];
__device__ float    g_cnt[N_NODES];
__device__ float    g_h0[N_NODES * 128];
__device__ uint32_t g_xh[N_NODES * 32];      // x as half2
__device__ uint32_t g_h0h[N_NODES * 64];     // h0 as half2
__device__ uint32_t g_h1h[N_NODES * 64];     // h1 as half2
__device__ uint32_t g_aggh[N_NODES * 64];    // scaled agg as half2 (both layers)
__device__ uint32_t g_eattrh[EF_MAX * 16];   // edge_attr as half2
__device__ uint32_t g_B0[128 * 64];          // prepacked weight fragments
__device__ uint32_t g_B1[256 * 64];
__device__ uint32_t g_BC[288 * 64];

// ---------------------------------------------------------------------------
__device__ __forceinline__ void mma_f16(float4& d, const uint4 a, const uint2 b) {
    asm("mma.sync.aligned.m16n8k16.row.col.f32.f16.f16.f32 "
        "{%0,%1,%2,%3}, {%4,%5,%6,%7}, {%8,%9}, {%0,%1,%2,%3};"
        : "+f"(d.x), "+f"(d.y), "+f"(d.z), "+f"(d.w)
        : "r"(a.x), "r"(a.y), "r"(a.z), "r"(a.w), "r"(b.x), "r"(b.y));
}

__device__ __forceinline__ uint32_t packh2(float lo, float hi) {
    __half2 h = __floats2half2_rn(lo, hi);
    return *(uint32_t*)&h;
}

// B fragment pack: slot s of a K x 128 weight [Wl;Wr] (FD rows each)
__device__ __forceinline__ uint32_t pack_w(int s, int FD,
                                           const float* __restrict__ Wl,
                                           const float* __restrict__ Wr) {
    int reg = s & 1, lane = (s >> 1) & 31, nb = (s >> 6) & 15, kb = s >> 10;
    int tig = lane & 3, gid = lane >> 2;
    int n = nb * 8 + gid;
    int k0 = kb * 16 + reg * 8 + tig * 2;
    float lo = (k0 < FD) ? Wl[k0 * 128 + n] : Wr[(k0 - FD) * 128 + n];
    float hi = (k0 + 1 < FD) ? Wl[(k0 + 1) * 128 + n] : Wr[(k0 + 1 - FD) * 128 + n];
    return packh2(lo, hi);
}

// ---------------------------------------------------------------------------
// prep: zero scratch, convert x/eattr to fp16, prepack all weight fragments
__global__ void prep_kernel(const float* __restrict__ x,
                            const float* __restrict__ eattr,
                            const float* __restrict__ Wl0, const float* __restrict__ Wr0,
                            const float* __restrict__ Wl1, const float* __restrict__ Wr1,
                            const float* __restrict__ W1,
                            float* __restrict__ agg, float* __restrict__ agg2,
                            float* __restrict__ cnt,
                            uint32_t* __restrict__ xh, uint32_t* __restrict__ eattrh,
                            uint32_t* __restrict__ B0, uint32_t* __restrict__ B1,
                            uint32_t* __restrict__ BC, int Ef) {
    int i0 = blockIdx.x * blockDim.x + threadIdx.x;
    int stride = gridDim.x * blockDim.x;
    float4 z4 = make_float4(0.f, 0.f, 0.f, 0.f);
    for (int j = i0; j < N_NODES * 16; j += stride) ((float4*)agg)[j] = z4;
    for (int j = i0; j < N_NODES * 32; j += stride) ((float4*)agg2)[j] = z4;
    for (int j = i0; j < N_NODES; j += stride) cnt[j] = 0.f;
    for (int j = i0; j < N_NODES * 32; j += stride) {
        float2 v = ((const float2*)x)[j];
        xh[j] = packh2(v.x, v.y);
    }
    for (int j = i0; j < Ef * 16; j += stride) {
        float2 v = ((const float2*)eattr)[j];
        eattrh[j] = packh2(v.x, v.y);
    }
    for (int s = i0; s < 128 * 64; s += stride) B0[s] = pack_w(s, 64, Wl0, Wr0);
    for (int s = i0; s < 256 * 64; s += stride) B1[s] = pack_w(s, 128, Wl1, Wr1);
    for (int s = i0; s < 288 * 64; s += stride) BC[s] = pack_w(s, 288, W1, W1);
}

// scatter (64-wide) with fused degree count
__global__ void scatter64_count_kernel(const float* __restrict__ feat,
                                       const int* __restrict__ src,
                                       const int* __restrict__ dst,
                                       int E, float* __restrict__ agg,
                                       float* __restrict__ cnt) {
    int id = blockIdx.x * blockDim.x + threadIdx.x;
    if (id < E) atomicAdd(&cnt[__ldg(&dst[id])], 1.0f);
    if (id >= E * 16) return;
    int e = id >> 4;
    int g = id & 15;
    int s = __ldg(&src[e]);
    int d = __ldg(&dst[e]);
    float4 v = *(const float4*)(feat + (size_t)s * 64 + g * 4);
    float* a = agg + (size_t)d * 64 + g * 4;
    asm volatile("red.global.add.v4.f32 [%0], {%1, %2, %3, %4};"
                 :: "l"(a), "f"(v.x), "f"(v.y), "f"(v.z), "f"(v.w) : "memory");
}

// 128-wide scatter over a 64-column half (L2-resident working set per pass)
__global__ void scatter128_half_kernel(const float* __restrict__ feat,
                                       const int* __restrict__ src,
                                       const int* __restrict__ dst,
                                       int E, float* __restrict__ agg, int coff) {
    int id = blockIdx.x * blockDim.x + threadIdx.x;
    if (id >= E * 16) return;
    int e = id >> 4;
    int g = id & 15;
    int s = __ldg(&src[e]);
    int d = __ldg(&dst[e]);
    int col = coff + g * 4;
    float4 v = *(const float4*)(feat + (size_t)s * 128 + col);
    float* a = agg + (size_t)d * 128 + col;
    asm volatile("red.global.add.v4.f32 [%0], {%1, %2, %3, %4};"
                 :: "l"(a), "f"(v.x), "f"(v.y), "f"(v.z), "f"(v.w) : "memory");
}

// aggh[n,k] = half(agg[n,k] / max(cnt[n],1)) — packed half2, 8 floats per job
template <int FD8>
__global__ void conv_scale_half_kernel(const float* __restrict__ agg,
                                       const float* __restrict__ cnt,
                                       uint32_t* __restrict__ outh) {
    int idx = blockIdx.x * blockDim.x + threadIdx.x;
    if (idx >= N_NODES * FD8) return;
    int n = idx / FD8;
    int g = idx - n * FD8;
    float rc = 1.0f / fmaxf(__ldg(&cnt[n]), 1.0f);
    const float4* a = (const float4*)(agg + (size_t)n * FD8 * 8 + g * 8);
    float4 v0 = a[0], v1 = a[1];
    uint4 o;
    o.x = packh2(v0.x * rc, v0.y * rc);
    o.y = packh2(v0.z * rc, v0.w * rc);
    o.z = packh2(v1.x * rc, v1.y * rc);
    o.w = packh2(v1.z * rc, v1.w * rc);
    *(uint4*)(outh + (size_t)n * FD8 * 4 + g * 4) = o;
}

// ---------------------------------------------------------------------------
// Fused SAGE layer via fp16 mma.sync, M-tile = 256 nodes, N = 128,
// 512 threads = 16 warps: wm = wid&7 (32 rows), wn = wid>>3 (64 cols).
template <int K, bool RELU, bool WF32>
__launch_bounds__(512, 1)
__global__ void layer_mma_kernel(const uint32_t* __restrict__ aggh,
                                 const uint32_t* __restrict__ xh,
                                 const uint32_t* __restrict__ Bg,
                                 const float* __restrict__ bl,
                                 float* __restrict__ outf,
                                 uint32_t* __restrict__ outh) {
    extern __shared__ uint32_t usm[];
    uint32_t* Bsm = usm;                   // K*64 b32
    uint32_t* Asm = Bsm + K * 64;          // 2 * 4096 b32
    float* bs = (float*)(Asm + 8192);      // 128

    const int tid = threadIdx.x;
    const int FD = K / 2;
    const int FD2 = FD / 2;  // u32 per row per source

    for (int i = tid; i < K * 16; i += 512)
        ((uint4*)Bsm)[i] = ((const uint4*)Bg)[i];
    if (tid < 128) bs[tid] = bl[tid];
    __syncthreads();

    const int wid = tid >> 5, lane = tid & 31;
    const int wm = wid & 7, wn = wid >> 3;
    const int gid = lane >> 2, tig = lane & 3;

    constexpr int P = K / 32;
    const int ntiles = (N_NODES + 255) >> 8;

    for (int tile = blockIdx.x; tile < ntiles; tile += gridDim.x) {
        const int n0 = tile << 8;

        auto stage = [&](int p, uint32_t* Af) {
            int c0 = p * 32;
            const uint32_t* src;
            int cu;
            if (c0 < FD) { src = aggh; cu = c0 >> 1; }
            else         { src = xh;   cu = (c0 - FD) >> 1; }
#pragma unroll
            for (int it = 0; it < 2; it++) {
                int idx = tid + 512 * it;       // 0..1023
                int r = idx >> 2, g8 = idx & 3;
                int node = min(n0 + r, N_NODES - 1);
                uint4 v = *(const uint4*)(src + (size_t)node * FD2 + cu + g8 * 4);
                int kt = g8 >> 1, khalf = g8 & 1;
                int reg = ((r >> 3) & 1) | (khalf << 1);
                uint32_t* s = &Af[(((kt * 16 + (r >> 4)) * 32) + (r & 7) * 4) * 4 + reg];
                s[0] = v.x; s[4] = v.y; s[8] = v.z; s[12] = v.w;
            }
        };

        stage(0, Asm);
        __syncthreads();

        float4 d[2][8];
#pragma unroll
        for (int t = 0; t < 2; t++)
#pragma unroll
            for (int j = 0; j < 8; j++) d[t][j] = make_float4(0.f, 0.f, 0.f, 0.f);

        for (int p = 0; p < P; p++) {
            if (p + 1 < P) stage(p + 1, Asm + ((p + 1) & 1) * 4096);
            const uint32_t* Af = Asm + (p & 1) * 4096;
#pragma unroll
            for (int kt = 0; kt < 2; kt++) {
                uint4 av[2];
#pragma unroll
                for (int t = 0; t < 2; t++)
                    av[t] = *(const uint4*)&Af[((kt * 16 + wm * 2 + t) * 32 + lane) * 4];
                int kb = p * 2 + kt;
#pragma unroll
                for (int j = 0; j < 8; j++) {
                    uint2 bv = *(const uint2*)&Bsm[((kb * 16 + wn * 8 + j) * 32 + lane) * 2];
#pragma unroll
                    for (int t = 0; t < 2; t++) mma_f16(d[t][j], av[t], bv);
                }
            }
            __syncthreads();
        }

        // epilogue: bias (+relu), write fp16 (and fp32 if needed)
#pragma unroll
        for (int t = 0; t < 2; t++) {
            int nlo = n0 + wm * 32 + t * 16 + gid;
            int nhi = nlo + 8;
#pragma unroll
            for (int j = 0; j < 8; j++) {
                int col = wn * 64 + j * 8 + tig * 2;
                float ba = bs[col], bb = bs[col + 1];
                float2 lo = make_float2(d[t][j].x + ba, d[t][j].y + bb);
                float2 hi = make_float2(d[t][j].z + ba, d[t][j].w + bb);
                if (RELU) {
                    lo.x = fmaxf(lo.x, 0.f); lo.y = fmaxf(lo.y, 0.f);
                    hi.x = fmaxf(hi.x, 0.f); hi.y = fmaxf(hi.y, 0.f);
                }
                if (nlo < N_NODES) {
                    if (WF32) *(float2*)&outf[(size_t)nlo * 128 + col] = lo;
                    outh[(size_t)nlo * 64 + (col >> 1)] = packh2(lo.x, lo.y);
                }
                if (nhi < N_NODES) {
                    if (WF32) *(float2*)&outf[(size_t)nhi * 128 + col] = hi;
                    outh[(size_t)nhi * 64 + (col >> 1)] = packh2(hi.x, hi.y);
                }
            }
        }
        __syncthreads();
    }
}

// ---------------------------------------------------------------------------
// Classifier via fp16 mma.sync, M-tile = 256 edges, N = 128, K = 288,
// 512 threads = 16 warps.
__launch_bounds__(512, 1)
__global__ void classify_mma_kernel(const uint32_t* __restrict__ h1h,
                                    const int* __restrict__ fsrc,
                                    const int* __restrict__ fdst,
                                    const uint32_t* __restrict__ eattrh,
                                    const uint32_t* __restrict__ Bg,
                                    const float* __restrict__ b1,
                                    const float* __restrict__ W2,
                                    const float* __restrict__ b2,
                                    float* __restrict__ outp, int Ef) {
    extern __shared__ uint32_t usm[];
    uint32_t* Bsm = usm;                   // 288*64 = 18432 b32
    uint32_t* Asm = Bsm + 18432;           // 2 * 4096 b32
    float* b1s  = (float*)(Asm + 8192);    // 128
    float* w2s  = b1s + 128;               // 128
    float* red  = w2s + 128;               // 256
    int*   sidx = (int*)(red + 256);       // 256
    int*   didx = sidx + 256;              // 256

    const int tid = threadIdx.x;

    for (int i = tid; i < 4608; i += 512)
        ((uint4*)Bsm)[i] = ((const uint4*)Bg)[i];
    if (tid < 128) { b1s[tid] = b1[tid]; w2s[tid] = W2[tid]; }
    __syncthreads();
    const float b2v = __ldg(&b2[0]);

    const int wid = tid >> 5, lane = tid & 31;
    const int wm = wid & 7, wn = wid >> 3;
    const int gid = lane >> 2, tig = lane & 3;

    const int ntiles = (Ef + 255) >> 8;
    for (int tile = blockIdx.x; tile < ntiles; tile += gridDim.x) {
        const int e0 = tile << 8;
        if (tid < 256) {
            int e = min(e0 + tid, Ef - 1);
            sidx[tid] = __ldg(&fsrc[e]);
            didx[tid] = __ldg(&fdst[e]);
            red[tid] = 0.0f;
        }
        __syncthreads();

        auto stage = [&](int p, uint32_t* Af) {
#pragma unroll
            for (int it = 0; it < 2; it++) {
                int idx = tid + 512 * it;       // 0..1023
                int r = idx >> 2, g8 = idx & 3;
                const uint32_t* sp;
                if (p < 4)
                    sp = h1h + (size_t)sidx[r] * 64 + p * 16 + g8 * 4;
                else if (p < 8)
                    sp = h1h + (size_t)didx[r] * 64 + (p - 4) * 16 + g8 * 4;
                else {
                    int e = min(e0 + r, Ef - 1);
                    sp = eattrh + (size_t)e * 16 + g8 * 4;
                }
                uint4 v = *(const uint4*)sp;
                int kt = g8 >> 1, khalf = g8 & 1;
                int reg = ((r >> 3) & 1) | (khalf << 1);
                uint32_t* s = &Af[(((kt * 16 + (r >> 4)) * 32) + (r & 7) * 4) * 4 + reg];
                s[0] = v.x; s[4] = v.y; s[8] = v.z; s[12] = v.w;
            }
        };

        stage(0, Asm);
        __syncthreads();

        float4 d[2][8];
#pragma unroll
        for (int t = 0; t < 2; t++)
#pragma unroll
            for (int j = 0; j < 8; j++) d[t][j] = make_float4(0.f, 0.f, 0.f, 0.f);

        for (int p = 0; p < 9; p++) {
            if (p + 1 < 9) stage(p + 1, Asm + ((p + 1) & 1) * 4096);
            const uint32_t* Af = Asm + (p & 1) * 4096;
#pragma unroll
            for (int kt = 0; kt < 2; kt++) {
                uint4 av[2];
#pragma unroll
                for (int t = 0; t < 2; t++)
                    av[t] = *(const uint4*)&Af[((kt * 16 + wm * 2 + t) * 32 + lane) * 4];
                int kb = p * 2 + kt;
#pragma unroll
                for (int j = 0; j < 8; j++) {
                    uint2 bv = *(const uint2*)&Bsm[((kb * 16 + wn * 8 + j) * 32 + lane) * 2];
#pragma unroll
                    for (int t = 0; t < 2; t++) mma_f16(d[t][j], av[t], bv);
                }
            }
            __syncthreads();
        }

        // epilogue: relu + dot with W2, reduce over 128 hidden dims
        float s_[2][2];
#pragma unroll
        for (int t = 0; t < 2; t++) { s_[t][0] = 0.f; s_[t][1] = 0.f; }
#pragma unroll
        for (int t = 0; t < 2; t++) {
#pragma unroll
            for (int j = 0; j < 8; j++) {
                int col = wn * 64 + j * 8 + tig * 2;
                float ba = b1s[col], bb = b1s[col + 1];
                float wa = w2s[col], wb = w2s[col + 1];
                s_[t][0] += fmaxf(d[t][j].x + ba, 0.f) * wa + fmaxf(d[t][j].y + bb, 0.f) * wb;
                s_[t][1] += fmaxf(d[t][j].z + ba, 0.f) * wa + fmaxf(d[t][j].w + bb, 0.f) * wb;
            }
        }
#pragma unroll
        for (int t = 0; t < 2; t++) {
            s_[t][0] += __shfl_xor_sync(0xffffffffu, s_[t][0], 1);
            s_[t][0] += __shfl_xor_sync(0xffffffffu, s_[t][0], 2);
            s_[t][1] += __shfl_xor_sync(0xffffffffu, s_[t][1], 1);
            s_[t][1] += __shfl_xor_sync(0xffffffffu, s_[t][1], 2);
        }
        if (tig == 0) {
#pragma unroll
            for (int t = 0; t < 2; t++) {
                atomicAdd(&red[wm * 32 + t * 16 + gid], s_[t][0]);
                atomicAdd(&red[wm * 32 + t * 16 + gid + 8], s_[t][1]);
            }
        }
        __syncthreads();
        if (tid < 256) {
            int e = e0 + tid;
            if (e < Ef) outp[e] = red[tid] + b2v;
        }
        __syncthreads();
    }
}

// ---------------------------------------------------------------------------
extern "C" void kernel_launch(void* const* d_in, const int* in_sizes, int n_in,
                              void* d_out, int out_size) {
    const float* x     = (const float*)d_in[0];
    const int*   ei    = (const int*)d_in[1];
    const int*   fei   = (const int*)d_in[2];
    const float* eattr = (const float*)d_in[3];
    const float* Wl0   = (const float*)d_in[4];
    const float* bl0   = (const float*)d_in[5];
    const float* Wr0   = (const float*)d_in[6];
    const float* Wl1   = (const float*)d_in[7];
    const float* bl1   = (const float*)d_in[8];
    const float* Wr1   = (const float*)d_in[9];
    const float* W1    = (const float*)d_in[10];
    const float* b1    = (const float*)d_in[11];
    const float* W2    = (const float*)d_in[12];
    const float* b2    = (const float*)d_in[13];
    float* outp = (float*)d_out;

    int E  = in_sizes[1] / 2;
    int Ef = in_sizes[2] / 2;
    const int* src  = ei;
    const int* dst  = ei + E;
    const int* fsrc = fei;
    const int* fdst = fei + Ef;

    float *agg_p, *agg2_p, *cnt_p, *h0_p;
    uint32_t *xh_p, *h0h_p, *h1h_p, *aggh_p, *eattrh_p, *B0_p, *B1_p, *BC_p;
    cudaGetSymbolAddress((void**)&agg_p, g_agg);
    cudaGetSymbolAddress((void**)&agg2_p, g_agg2);
    cudaGetSymbolAddress((void**)&cnt_p, g_cnt);
    cudaGetSymbolAddress((void**)&h0_p, g_h0);
    cudaGetSymbolAddress((void**)&xh_p, g_xh);
    cudaGetSymbolAddress((void**)&h0h_p, g_h0h);
    cudaGetSymbolAddress((void**)&h1h_p, g_h1h);
    cudaGetSymbolAddress((void**)&aggh_p, g_aggh);
    cudaGetSymbolAddress((void**)&eattrh_p, g_eattrh);
    cudaGetSymbolAddress((void**)&B0_p, g_B0);
    cudaGetSymbolAddress((void**)&B1_p, g_B1);
    cudaGetSymbolAddress((void**)&BC_p, g_BC);

    const int smemL0 = (128 * 64 + 8192 + 128) * 4;
    const int smemL1 = (256 * 64 + 8192 + 128) * 4;
    const int smemC  = (18432 + 8192 + 512) * 4 + 512 * 4;
    cudaFuncSetAttribute(layer_mma_kernel<128, true, true>,
                         cudaFuncAttributeMaxDynamicSharedMemorySize, smemL0);
    cudaFuncSetAttribute(layer_mma_kernel<256, false, false>,
                         cudaFuncAttributeMaxDynamicSharedMemorySize, smemL1);
    cudaFuncSetAttribute(classify_mma_kernel,
                         cudaFuncAttributeMaxDynamicSharedMemorySize, smemC);

    // 1: prep (zero scratch, fp16 conversions, weight prepack)
    prep_kernel<<<2048, 256>>>(x, eattr, Wl0, Wr0, Wl1, Wr1, W1,
                               agg_p, agg2_p, cnt_p, xh_p, eattrh_p,
                               B0_p, B1_p, BC_p, Ef);
    // 2: scatter x (64-wide) + degree count
    scatter64_count_kernel<<<(E * 16 + 255) / 256, 256>>>(x, src, dst, E, agg_p, cnt_p);
    // 3: aggh0 = half(agg / cnt)
    conv_scale_half_kernel<8><<<(N_NODES * 8 + 255) / 256, 256>>>(agg_p, cnt_p, aggh_p);
    // 4: layer 0 (writes h0 fp32 + h0h fp16)
    layer_mma_kernel<128, true, true><<<148, 512, smemL0>>>(aggh_p, xh_p, B0_p, bl0,
                                                            h0_p, h0h_p);
    // 5,6: scatter h0 (two 64-col halves, each L2-resident)
    scatter128_half_kernel<<<(E * 16 + 255) / 256, 256>>>(h0_p, src, dst, E, agg2_p, 0);
    scatter128_half_kernel<<<(E * 16 + 255) / 256, 256>>>(h0_p, src, dst, E, agg2_p, 64);
    // 7: aggh1 = half(agg2 / cnt)
    conv_scale_half_kernel<16><<<(N_NODES * 16 + 255) / 256, 256>>>(agg2_p, cnt_p, aggh_p);
    // 8: layer 1 (writes h1h fp16 only)
    layer_mma_kernel<256, false, false><<<148, 512, smemL1>>>(aggh_p, h0h_p, B1_p, bl1,
                                                              nullptr, h1h_p);
    // 9: edge classifier
    classify_mma_kernel<<<148, 512, smemC>>>(h1h_p, fsrc, fdst, eattrh_p,
                                             BC_p, b1, W2, b2, outp, Ef);
}

// round 14
// speedup vs baseline: 6.4542x; 1.0007x over previous
#include <cuda_runtime.h>
#include <cuda_fp16.h>
#include <cstdint>

#define N_NODES 100000
#define EF_MAX  500000

// Scratch (allocation-free rule: __device__ globals)
__device__ float    g_agg[N_NODES * 64];
__device__ float    g_agg2[N_NODES * 128];
__device__ float    g_cnt[N_NODES];
__device__ uint32_t g_xh[N_NODES * 32];      // x as half2
__device__ uint32_t g_h0h[N_NODES * 64];     // h0 as half2
__device__ uint32_t g_h1h[N_NODES * 64];     // h1 as half2
__device__ uint32_t g_aggh[N_NODES * 64];    // scaled agg as half2 (both layers)
__device__ uint32_t g_eattrh[EF_MAX * 16];   // edge_attr as half2
__device__ uint32_t g_B0[128 * 64];          // prepacked weight fragments
__device__ uint32_t g_B1[256 * 64];
__device__ uint32_t g_BC[288 * 64];

// ---------------------------------------------------------------------------
__device__ __forceinline__ void mma_f16(float4& d, const uint4 a, const uint2 b) {
    asm("mma.sync.aligned.m16n8k16.row.col.f32.f16.f16.f32 "
        "{%0,%1,%2,%3}, {%4,%5,%6,%7}, {%8,%9}, {%0,%1,%2,%3};"
        : "+f"(d.x), "+f"(d.y), "+f"(d.z), "+f"(d.w)
        : "r"(a.x), "r"(a.y), "r"(a.z), "r"(a.w), "r"(b.x), "r"(b.y));
}

__device__ __forceinline__ uint32_t packh2(float lo, float hi) {
    __half2 h = __floats2half2_rn(lo, hi);
    return *(uint32_t*)&h;
}

// B fragment pack: slot s of a K x 128 weight [Wl;Wr] (FD rows each)
__device__ __forceinline__ uint32_t pack_w(int s, int FD,
                                           const float* __restrict__ Wl,
                                           const float* __restrict__ Wr) {
    int reg = s & 1, lane = (s >> 1) & 31, nb = (s >> 6) & 15, kb = s >> 10;
    int tig = lane & 3, gid = lane >> 2;
    int n = nb * 8 + gid;
    int k0 = kb * 16 + reg * 8 + tig * 2;
    float lo = (k0 < FD) ? Wl[k0 * 128 + n] : Wr[(k0 - FD) * 128 + n];
    float hi = (k0 + 1 < FD) ? Wl[(k0 + 1) * 128 + n] : Wr[(k0 + 1 - FD) * 128 + n];
    return packh2(lo, hi);
}

// Store one staged uint4 into the A fragment slot layout
__device__ __forceinline__ void sts_frag(uint32_t* __restrict__ buf,
                                         int idx, const uint4 v) {
    int r = idx >> 2, g8 = idx & 3;
    int kt = g8 >> 1, khalf = g8 & 1;
    int reg = ((r >> 3) & 1) | (khalf << 1);
    uint32_t* s = &buf[(((kt * 16 + (r >> 4)) * 32) + (r & 7) * 4) * 4 + reg];
    s[0] = v.x; s[4] = v.y; s[8] = v.z; s[12] = v.w;
}

// ---------------------------------------------------------------------------
// prep: zero scratch, convert x/eattr to fp16, prepack all weight fragments
__global__ void prep_kernel(const float* __restrict__ x,
                            const float* __restrict__ eattr,
                            const float* __restrict__ Wl0, const float* __restrict__ Wr0,
                            const float* __restrict__ Wl1, const float* __restrict__ Wr1,
                            const float* __restrict__ W1,
                            float* __restrict__ agg, float* __restrict__ agg2,
                            float* __restrict__ cnt,
                            uint32_t* __restrict__ xh, uint32_t* __restrict__ eattrh,
                            uint32_t* __restrict__ B0, uint32_t* __restrict__ B1,
                            uint32_t* __restrict__ BC, int Ef) {
    int i0 = blockIdx.x * blockDim.x + threadIdx.x;
    int stride = gridDim.x * blockDim.x;
    float4 z4 = make_float4(0.f, 0.f, 0.f, 0.f);
    for (int j = i0; j < N_NODES * 16; j += stride) ((float4*)agg)[j] = z4;
    for (int j = i0; j < N_NODES * 32; j += stride) ((float4*)agg2)[j] = z4;
    for (int j = i0; j < N_NODES; j += stride) cnt[j] = 0.f;
    for (int j = i0; j < N_NODES * 32; j += stride) {
        float2 v = ((const float2*)x)[j];
        xh[j] = packh2(v.x, v.y);
    }
    for (int j = i0; j < Ef * 16; j += stride) {
        float2 v = ((const float2*)eattr)[j];
        eattrh[j] = packh2(v.x, v.y);
    }
    for (int s = i0; s < 128 * 64; s += stride) B0[s] = pack_w(s, 64, Wl0, Wr0);
    for (int s = i0; s < 256 * 64; s += stride) B1[s] = pack_w(s, 128, Wl1, Wr1);
    for (int s = i0; s < 288 * 64; s += stride) BC[s] = pack_w(s, 288, W1, W1);
}

// scatter (64-wide, fp32 x) with fused degree count
__global__ void scatter64_count_kernel(const float* __restrict__ feat,
                                       const int* __restrict__ src,
                                       const int* __restrict__ dst,
                                       int E, float* __restrict__ agg,
                                       float* __restrict__ cnt) {
    int id = blockIdx.x * blockDim.x + threadIdx.x;
    if (id < E) atomicAdd(&cnt[__ldg(&dst[id])], 1.0f);
    if (id >= E * 16) return;
    int e = id >> 4;
    int g = id & 15;
    int s = __ldg(&src[e]);
    int d = __ldg(&dst[e]);
    float4 v = *(const float4*)(feat + (size_t)s * 64 + g * 4);
    float* a = agg + (size_t)d * 64 + g * 4;
    asm volatile("red.global.add.v4.f32 [%0], {%1, %2, %3, %4};"
                 :: "l"(a), "f"(v.x), "f"(v.y), "f"(v.z), "f"(v.w) : "memory");
}

// 128-wide scatter reading fp16 h0 — FULL 128 columns (32 groups of 4)
__global__ void scatter128h_kernel(const uint32_t* __restrict__ feath,
                                   const int* __restrict__ src,
                                   const int* __restrict__ dst,
                                   int E, float* __restrict__ agg) {
    int id = blockIdx.x * blockDim.x + threadIdx.x;
    if (id >= E * 32) return;
    int e = id >> 5;
    int g = id & 31;
    int s = __ldg(&src[e]);
    int d = __ldg(&dst[e]);
    uint2 v = *(const uint2*)(feath + (size_t)s * 64 + g * 2);
    float2 a = __half22float2(*(__half2*)&v.x);
    float2 b = __half22float2(*(__half2*)&v.y);
    float* ap = agg + (size_t)d * 128 + g * 4;
    asm volatile("red.global.add.v4.f32 [%0], {%1, %2, %3, %4};"
                 :: "l"(ap), "f"(a.x), "f"(a.y), "f"(b.x), "f"(b.y) : "memory");
}

// aggh[n,k] = half(agg[n,k] / max(cnt[n],1)) — packed half2, 8 floats per job
template <int FD8>
__global__ void conv_scale_half_kernel(const float* __restrict__ agg,
                                       const float* __restrict__ cnt,
                                       uint32_t* __restrict__ outh) {
    int idx = blockIdx.x * blockDim.x + threadIdx.x;
    if (idx >= N_NODES * FD8) return;
    int n = idx / FD8;
    int g = idx - n * FD8;
    float rc = 1.0f / fmaxf(__ldg(&cnt[n]), 1.0f);
    const float4* a = (const float4*)(agg + (size_t)n * FD8 * 8 + g * 8);
    float4 v0 = a[0], v1 = a[1];
    uint4 o;
    o.x = packh2(v0.x * rc, v0.y * rc);
    o.y = packh2(v0.z * rc, v0.w * rc);
    o.z = packh2(v1.x * rc, v1.y * rc);
    o.w = packh2(v1.z * rc, v1.w * rc);
    *(uint4*)(outh + (size_t)n * FD8 * 4 + g * 4) = o;
}

// ---------------------------------------------------------------------------
// Fused SAGE layer via fp16 mma.sync, M-tile = 256 nodes, N = 128,
// 512 threads = 16 warps. Register-pipelined staging (2-panel lookahead,
// one __syncthreads per panel).
template <int K, bool RELU>
__launch_bounds__(512, 1)
__global__ void layer_mma_kernel(const uint32_t* __restrict__ aggh,
                                 const uint32_t* __restrict__ xh,
                                 const uint32_t* __restrict__ Bg,
                                 const float* __restrict__ bl,
                                 uint32_t* __restrict__ outh) {
    extern __shared__ uint32_t usm[];
    uint32_t* Bsm = usm;                   // K*64 b32
    uint32_t* Asm = Bsm + K * 64;          // 2 * 4096 b32
    float* bs = (float*)(Asm + 8192);      // 128

    const int tid = threadIdx.x;
    const int FD = K / 2;
    const int FD2 = FD / 2;

    for (int i = tid; i < K * 16; i += 512)
        ((uint4*)Bsm)[i] = ((const uint4*)Bg)[i];
    if (tid < 128) bs[tid] = bl[tid];
    __syncthreads();

    const int wid = tid >> 5, lane = tid & 31;
    const int wm = wid & 7, wn = wid >> 3;
    const int gid = lane >> 2, tig = lane & 3;

    constexpr int P = K / 32;
    const int ntiles = (N_NODES + 255) >> 8;

    for (int tile = blockIdx.x; tile < ntiles; tile += gridDim.x) {
        const int n0 = tile << 8;

        auto ldg_panel = [&](int p, uint4* vv) {
            int c0 = p * 32;
            const uint32_t* src;
            int cu;
            if (c0 < FD) { src = aggh; cu = c0 >> 1; }
            else         { src = xh;   cu = (c0 - FD) >> 1; }
#pragma unroll
            for (int it = 0; it < 2; it++) {
                int idx = tid + 512 * it;
                int r = idx >> 2, g8 = idx & 3;
                int node = min(n0 + r, N_NODES - 1);
                vv[it] = *(const uint4*)(src + (size_t)node * FD2 + cu + g8 * 4);
            }
        };
        auto sts_panel = [&](const uint4* vv, uint32_t* buf) {
#pragma unroll
            for (int it = 0; it < 2; it++) sts_frag(buf, tid + 512 * it, vv[it]);
        };

        uint4 V[2][2];
        ldg_panel(0, V[0]);
        ldg_panel(1, V[1]);
        sts_panel(V[0], Asm);
        __syncthreads();

        float4 d[2][8];
#pragma unroll
        for (int t = 0; t < 2; t++)
#pragma unroll
            for (int j = 0; j < 8; j++) d[t][j] = make_float4(0.f, 0.f, 0.f, 0.f);

        for (int p = 0; p < P; p++) {
            if (p + 1 < P) sts_panel(V[(p + 1) & 1], Asm + ((p + 1) & 1) * 4096);
            if (p + 2 < P) ldg_panel(p + 2, V[p & 1]);
            const uint32_t* Af = Asm + (p & 1) * 4096;
#pragma unroll
            for (int kt = 0; kt < 2; kt++) {
                uint4 av[2];
#pragma unroll
                for (int t = 0; t < 2; t++)
                    av[t] = *(const uint4*)&Af[((kt * 16 + wm * 2 + t) * 32 + lane) * 4];
                int kb = p * 2 + kt;
#pragma unroll
                for (int j = 0; j < 8; j++) {
                    uint2 bv = *(const uint2*)&Bsm[((kb * 16 + wn * 8 + j) * 32 + lane) * 2];
#pragma unroll
                    for (int t = 0; t < 2; t++) mma_f16(d[t][j], av[t], bv);
                }
            }
            __syncthreads();
        }

        // epilogue: bias (+relu), write fp16
#pragma unroll
        for (int t = 0; t < 2; t++) {
            int nlo = n0 + wm * 32 + t * 16 + gid;
            int nhi = nlo + 8;
#pragma unroll
            for (int j = 0; j < 8; j++) {
                int col = wn * 64 + j * 8 + tig * 2;
                float ba = bs[col], bb = bs[col + 1];
                float2 lo = make_float2(d[t][j].x + ba, d[t][j].y + bb);
                float2 hi = make_float2(d[t][j].z + ba, d[t][j].w + bb);
                if (RELU) {
                    lo.x = fmaxf(lo.x, 0.f); lo.y = fmaxf(lo.y, 0.f);
                    hi.x = fmaxf(hi.x, 0.f); hi.y = fmaxf(hi.y, 0.f);
                }
                if (nlo < N_NODES) outh[(size_t)nlo * 64 + (col >> 1)] = packh2(lo.x, lo.y);
                if (nhi < N_NODES) outh[(size_t)nhi * 64 + (col >> 1)] = packh2(hi.x, hi.y);
            }
        }
        __syncthreads();
    }
}

// ---------------------------------------------------------------------------
// Classifier via fp16 mma.sync, M-tile = 256 edges, N = 128, K = 288,
// 512 threads = 16 warps, register-pipelined staging.
__launch_bounds__(512, 1)
__global__ void classify_mma_kernel(const uint32_t* __restrict__ h1h,
                                    const int* __restrict__ fsrc,
                                    const int* __restrict__ fdst,
                                    const uint32_t* __restrict__ eattrh,
                                    const uint32_t* __restrict__ Bg,
                                    const float* __restrict__ b1,
                                    const float* __restrict__ W2,
                                    const float* __restrict__ b2,
                                    float* __restrict__ outp, int Ef) {
    extern __shared__ uint32_t usm[];
    uint32_t* Bsm = usm;                   // 288*64 = 18432 b32
    uint32_t* Asm = Bsm + 18432;           // 2 * 4096 b32
    float* b1s  = (float*)(Asm + 8192);    // 128
    float* w2s  = b1s + 128;               // 128
    float* red  = w2s + 128;               // 256
    int*   sidx = (int*)(red + 256);       // 256
    int*   didx = sidx + 256;              // 256

    const int tid = threadIdx.x;

    for (int i = tid; i < 4608; i += 512)
        ((uint4*)Bsm)[i] = ((const uint4*)Bg)[i];
    if (tid < 128) { b1s[tid] = b1[tid]; w2s[tid] = W2[tid]; }
    __syncthreads();
    const float b2v = __ldg(&b2[0]);

    const int wid = tid >> 5, lane = tid & 31;
    const int wm = wid & 7, wn = wid >> 3;
    const int gid = lane >> 2, tig = lane & 3;

    const int ntiles = (Ef + 255) >> 8;
    for (int tile = blockIdx.x; tile < ntiles; tile += gridDim.x) {
        const int e0 = tile << 8;
        if (tid < 256) {
            int e = min(e0 + tid, Ef - 1);
            sidx[tid] = __ldg(&fsrc[e]);
            didx[tid] = __ldg(&fdst[e]);
            red[tid] = 0.0f;
        }
        __syncthreads();

        auto ldg_panel = [&](int p, uint4* vv) {
#pragma unroll
            for (int it = 0; it < 2; it++) {
                int idx = tid + 512 * it;
                int r = idx >> 2, g8 = idx & 3;
                const uint32_t* sp;
                if (p < 4)
                    sp = h1h + (size_t)sidx[r] * 64 + p * 16 + g8 * 4;
                else if (p < 8)
                    sp = h1h + (size_t)didx[r] * 64 + (p - 4) * 16 + g8 * 4;
                else {
                    int e = min(e0 + r, Ef - 1);
                    sp = eattrh + (size_t)e * 16 + g8 * 4;
                }
                vv[it] = *(const uint4*)sp;
            }
        };
        auto sts_panel = [&](const uint4* vv, uint32_t* buf) {
#pragma unroll
            for (int it = 0; it < 2; it++) sts_frag(buf, tid + 512 * it, vv[it]);
        };

        uint4 V[2][2];
        ldg_panel(0, V[0]);
        ldg_panel(1, V[1]);
        sts_panel(V[0], Asm);
        __syncthreads();

        float4 d[2][8];
#pragma unroll
        for (int t = 0; t < 2; t++)
#pragma unroll
            for (int j = 0; j < 8; j++) d[t][j] = make_float4(0.f, 0.f, 0.f, 0.f);

        for (int p = 0; p < 9; p++) {
            if (p + 1 < 9) sts_panel(V[(p + 1) & 1], Asm + ((p + 1) & 1) * 4096);
            if (p + 2 < 9) ldg_panel(p + 2, V[p & 1]);
            const uint32_t* Af = Asm + (p & 1) * 4096;
#pragma unroll
            for (int kt = 0; kt < 2; kt++) {
                uint4 av[2];
#pragma unroll
                for (int t = 0; t < 2; t++)
                    av[t] = *(const uint4*)&Af[((kt * 16 + wm * 2 + t) * 32 + lane) * 4];
                int kb = p * 2 + kt;
#pragma unroll
                for (int j = 0; j < 8; j++) {
                    uint2 bv = *(const uint2*)&Bsm[((kb * 16 + wn * 8 + j) * 32 + lane) * 2];
#pragma unroll
                    for (int t = 0; t < 2; t++) mma_f16(d[t][j], av[t], bv);
                }
            }
            __syncthreads();
        }

        // epilogue: relu + dot with W2, reduce over 128 hidden dims
        float s_[2][2];
#pragma unroll
        for (int t = 0; t < 2; t++) { s_[t][0] = 0.f; s_[t][1] = 0.f; }
#pragma unroll
        for (int t = 0; t < 2; t++) {
#pragma unroll
            for (int j = 0; j < 8; j++) {
                int col = wn * 64 + j * 8 + tig * 2;
                float ba = b1s[col], bb = b1s[col + 1];
                float wa = w2s[col], wb = w2s[col + 1];
                s_[t][0] += fmaxf(d[t][j].x + ba, 0.f) * wa + fmaxf(d[t][j].y + bb, 0.f) * wb;
                s_[t][1] += fmaxf(d[t][j].z + ba, 0.f) * wa + fmaxf(d[t][j].w + bb, 0.f) * wb;
            }
        }
#pragma unroll
        for (int t = 0; t < 2; t++) {
            s_[t][0] += __shfl_xor_sync(0xffffffffu, s_[t][0], 1);
            s_[t][0] += __shfl_xor_sync(0xffffffffu, s_[t][0], 2);
            s_[t][1] += __shfl_xor_sync(0xffffffffu, s_[t][1], 1);
            s_[t][1] += __shfl_xor_sync(0xffffffffu, s_[t][1], 2);
        }
        if (tig == 0) {
#pragma unroll
            for (int t = 0; t < 2; t++) {
                atomicAdd(&red[wm * 32 + t * 16 + gid], s_[t][0]);
                atomicAdd(&red[wm * 32 + t * 16 + gid + 8], s_[t][1]);
            }
        }
        __syncthreads();
        if (tid < 256) {
            int e = e0 + tid;
            if (e < Ef) outp[e] = red[tid] + b2v;
        }
        __syncthreads();
    }
}

// ---------------------------------------------------------------------------
extern "C" void kernel_launch(void* const* d_in, const int* in_sizes, int n_in,
                              void* d_out, int out_size) {
    const float* x     = (const float*)d_in[0];
    const int*   ei    = (const int*)d_in[1];
    const int*   fei   = (const int*)d_in[2];
    const float* eattr = (const float*)d_in[3];
    const float* Wl0   = (const float*)d_in[4];
    const float* bl0   = (const float*)d_in[5];
    const float* Wr0   = (const float*)d_in[6];
    const float* Wl1   = (const float*)d_in[7];
    const float* bl1   = (const float*)d_in[8];
    const float* Wr1   = (const float*)d_in[9];
    const float* W1    = (const float*)d_in[10];
    const float* b1    = (const float*)d_in[11];
    const float* W2    = (const float*)d_in[12];
    const float* b2    = (const float*)d_in[13];
    float* outp = (float*)d_out;

    int E  = in_sizes[1] / 2;
    int Ef = in_sizes[2] / 2;
    const int* src  = ei;
    const int* dst  = ei + E;
    const int* fsrc = fei;
    const int* fdst = fei + Ef;

    float *agg_p, *agg2_p, *cnt_p;
    uint32_t *xh_p, *h0h_p, *h1h_p, *aggh_p, *eattrh_p, *B0_p, *B1_p, *BC_p;
    cudaGetSymbolAddress((void**)&agg_p, g_agg);
    cudaGetSymbolAddress((void**)&agg2_p, g_agg2);
    cudaGetSymbolAddress((void**)&cnt_p, g_cnt);
    cudaGetSymbolAddress((void**)&xh_p, g_xh);
    cudaGetSymbolAddress((void**)&h0h_p, g_h0h);
    cudaGetSymbolAddress((void**)&h1h_p, g_h1h);
    cudaGetSymbolAddress((void**)&aggh_p, g_aggh);
    cudaGetSymbolAddress((void**)&eattrh_p, g_eattrh);
    cudaGetSymbolAddress((void**)&B0_p, g_B0);
    cudaGetSymbolAddress((void**)&B1_p, g_B1);
    cudaGetSymbolAddress((void**)&BC_p, g_BC);

    const int smemL0 = (128 * 64 + 8192 + 128) * 4;
    const int smemL1 = (256 * 64 + 8192 + 128) * 4;
    const int smemC  = (18432 + 8192 + 512) * 4 + 512 * 4;
    cudaFuncSetAttribute(layer_mma_kernel<128, true>,
                         cudaFuncAttributeMaxDynamicSharedMemorySize, smemL0);
    cudaFuncSetAttribute(layer_mma_kernel<256, false>,
                         cudaFuncAttributeMaxDynamicSharedMemorySize, smemL1);
    cudaFuncSetAttribute(classify_mma_kernel,
                         cudaFuncAttributeMaxDynamicSharedMemorySize, smemC);

    // 1: prep (zero scratch, fp16 conversions, weight prepack)
    prep_kernel<<<2048, 256>>>(x, eattr, Wl0, Wr0, Wl1, Wr1, W1,
                               agg_p, agg2_p, cnt_p, xh_p, eattrh_p,
                               B0_p, B1_p, BC_p, Ef);
    // 2: scatter x (64-wide fp32) + degree count
    scatter64_count_kernel<<<(E * 16 + 255) / 256, 256>>>(x, src, dst, E, agg_p, cnt_p);
    // 3: aggh0 = half(agg / cnt)
    conv_scale_half_kernel<8><<<(N_NODES * 8 + 255) / 256, 256>>>(agg_p, cnt_p, aggh_p);
    // 4: layer 0 (writes h0h fp16 only)
    layer_mma_kernel<128, true><<<148, 512, smemL0>>>(aggh_p, xh_p, B0_p, bl0, h0h_p);
    // 5: scatter h0h (fp16 reads, fp32 atomics, FULL 128 columns)
    scatter128h_kernel<<<(E * 32 + 255) / 256, 256>>>(h0h_p, src, dst, E, agg2_p);
    // 6: aggh1 = half(agg2 / cnt)
    conv_scale_half_kernel<16><<<(N_NODES * 16 + 255) / 256, 256>>>(agg2_p, cnt_p, aggh_p);
    // 7: layer 1 (writes h1h fp16)
    layer_mma_kernel<256, false><<<148, 512, smemL1>>>(aggh_p, h0h_p, B1_p, bl1, h1h_p);
    // 8: edge classifier
    classify_mma_kernel<<<148, 512, smemC>>>(h1h_p, fsrc, fdst, eattrh_p,
                                             BC_p, b1, W2, b2, outp, Ef);
}

// round 15
// speedup vs baseline: 6.8875x; 1.0671x over previous
#include <cuda_runtime.h>
#include <cuda_fp16.h>
#include <cstdint>

#define N_NODES 100000
#define EF_MAX  500000

// Scratch (allocation-free rule: __device__ globals)
__device__ float    g_agg[N_NODES * 64];
__device__ float    g_agg2[N_NODES * 128];
__device__ float    g_cnt[N_NODES];
__device__ uint32_t g_xh[N_NODES * 32];      // x as half2
__device__ uint32_t g_h0h[N_NODES * 64];     // h0 as half2
__device__ uint32_t g_h1h[N_NODES * 64];     // h1 as half2
__device__ uint32_t g_aggh[N_NODES * 64];    // scaled agg as half2 (both layers)
__device__ uint32_t g_eattrh[EF_MAX * 16];   // edge_attr as half2
__device__ uint32_t g_B0[128 * 64];          // prepacked weight fragments
__device__ uint32_t g_B1[256 * 64];
__device__ uint32_t g_BC[288 * 64];

// ---------------------------------------------------------------------------
__device__ __forceinline__ void mma_f16(float4& d, const uint4 a, const uint2 b) {
    asm("mma.sync.aligned.m16n8k16.row.col.f32.f16.f16.f32 "
        "{%0,%1,%2,%3}, {%4,%5,%6,%7}, {%8,%9}, {%0,%1,%2,%3};"
        : "+f"(d.x), "+f"(d.y), "+f"(d.z), "+f"(d.w)
        : "r"(a.x), "r"(a.y), "r"(a.z), "r"(a.w), "r"(b.x), "r"(b.y));
}

__device__ __forceinline__ uint32_t packh2(float lo, float hi) {
    __half2 h = __floats2half2_rn(lo, hi);
    return *(uint32_t*)&h;
}

// B fragment pack: slot s of a K x 128 weight [Wl;Wr] (FD rows each)
__device__ __forceinline__ uint32_t pack_w(int s, int FD,
                                           const float* __restrict__ Wl,
                                           const float* __restrict__ Wr) {
    int reg = s & 1, lane = (s >> 1) & 31, nb = (s >> 6) & 15, kb = s >> 10;
    int tig = lane & 3, gid = lane >> 2;
    int n = nb * 8 + gid;
    int k0 = kb * 16 + reg * 8 + tig * 2;
    float lo = (k0 < FD) ? Wl[k0 * 128 + n] : Wr[(k0 - FD) * 128 + n];
    float hi = (k0 + 1 < FD) ? Wl[(k0 + 1) * 128 + n] : Wr[(k0 + 1 - FD) * 128 + n];
    return packh2(lo, hi);
}

// Store one staged uint4 into the A fragment slot layout (M-tile = 128):
// panel buffer = 2048 u32: [kt(2)][mt(8)][slot(32)][reg(4)]
__device__ __forceinline__ void sts_frag(uint32_t* __restrict__ buf,
                                         int idx, const uint4 v) {
    int r = idx >> 2, g8 = idx & 3;
    int kt = g8 >> 1, khalf = g8 & 1;
    int reg = ((r >> 3) & 1) | (khalf << 1);
    uint32_t* s = &buf[(((kt * 8 + (r >> 4)) * 32) + (r & 7) * 4) * 4 + reg];
    s[0] = v.x; s[4] = v.y; s[8] = v.z; s[12] = v.w;
}

// ---------------------------------------------------------------------------
// prep: zero scratch, convert x/eattr to fp16, prepack all weight fragments
__global__ void prep_kernel(const float* __restrict__ x,
                            const float* __restrict__ eattr,
                            const float* __restrict__ Wl0, const float* __restrict__ Wr0,
                            const float* __restrict__ Wl1, const float* __restrict__ Wr1,
                            const float* __restrict__ W1,
                            float* __restrict__ agg, float* __restrict__ agg2,
                            float* __restrict__ cnt,
                            uint32_t* __restrict__ xh, uint32_t* __restrict__ eattrh,
                            uint32_t* __restrict__ B0, uint32_t* __restrict__ B1,
                            uint32_t* __restrict__ BC, int Ef) {
    int i0 = blockIdx.x * blockDim.x + threadIdx.x;
    int stride = gridDim.x * blockDim.x;
    float4 z4 = make_float4(0.f, 0.f, 0.f, 0.f);
    for (int j = i0; j < N_NODES * 16; j += stride) ((float4*)agg)[j] = z4;
    for (int j = i0; j < N_NODES * 32; j += stride) ((float4*)agg2)[j] = z4;
    for (int j = i0; j < N_NODES; j += stride) cnt[j] = 0.f;
    for (int j = i0; j < N_NODES * 32; j += stride) {
        float2 v = ((const float2*)x)[j];
        xh[j] = packh2(v.x, v.y);
    }
    for (int j = i0; j < Ef * 16; j += stride) {
        float2 v = ((const float2*)eattr)[j];
        eattrh[j] = packh2(v.x, v.y);
    }
    for (int s = i0; s < 128 * 64; s += stride) B0[s] = pack_w(s, 64, Wl0, Wr0);
    for (int s = i0; s < 256 * 64; s += stride) B1[s] = pack_w(s, 128, Wl1, Wr1);
    for (int s = i0; s < 288 * 64; s += stride) BC[s] = pack_w(s, 288, W1, W1);
}

// scatter (64-wide, fp32 x) with fused degree count
__global__ void scatter64_count_kernel(const float* __restrict__ feat,
                                       const int* __restrict__ src,
                                       const int* __restrict__ dst,
                                       int E, float* __restrict__ agg,
                                       float* __restrict__ cnt) {
    int id = blockIdx.x * blockDim.x + threadIdx.x;
    if (id < E) atomicAdd(&cnt[__ldg(&dst[id])], 1.0f);
    if (id >= E * 16) return;
    int e = id >> 4;
    int g = id & 15;
    int s = __ldg(&src[e]);
    int d = __ldg(&dst[e]);
    float4 v = *(const float4*)(feat + (size_t)s * 64 + g * 4);
    float* a = agg + (size_t)d * 64 + g * 4;
    asm volatile("red.global.add.v4.f32 [%0], {%1, %2, %3, %4};"
                 :: "l"(a), "f"(v.x), "f"(v.y), "f"(v.z), "f"(v.w) : "memory");
}

// 128-wide scatter reading fp16 h0 — FULL 128 columns (32 groups of 4)
__global__ void scatter128h_kernel(const uint32_t* __restrict__ feath,
                                   const int* __restrict__ src,
                                   const int* __restrict__ dst,
                                   int E, float* __restrict__ agg) {
    int id = blockIdx.x * blockDim.x + threadIdx.x;
    if (id >= E * 32) return;
    int e = id >> 5;
    int g = id & 31;
    int s = __ldg(&src[e]);
    int d = __ldg(&dst[e]);
    uint2 v = *(const uint2*)(feath + (size_t)s * 64 + g * 2);
    float2 a = __half22float2(*(__half2*)&v.x);
    float2 b = __half22float2(*(__half2*)&v.y);
    float* ap = agg + (size_t)d * 128 + g * 4;
    asm volatile("red.global.add.v4.f32 [%0], {%1, %2, %3, %4};"
                 :: "l"(ap), "f"(a.x), "f"(a.y), "f"(b.x), "f"(b.y) : "memory");
}

// aggh[n,k] = half(agg[n,k] / max(cnt[n],1)) — packed half2, 8 floats per job
template <int FD8>
__global__ void conv_scale_half_kernel(const float* __restrict__ agg,
                                       const float* __restrict__ cnt,
                                       uint32_t* __restrict__ outh) {
    int idx = blockIdx.x * blockDim.x + threadIdx.x;
    if (idx >= N_NODES * FD8) return;
    int n = idx / FD8;
    int g = idx - n * FD8;
    float rc = 1.0f / fmaxf(__ldg(&cnt[n]), 1.0f);
    const float4* a = (const float4*)(agg + (size_t)n * FD8 * 8 + g * 8);
    float4 v0 = a[0], v1 = a[1];
    uint4 o;
    o.x = packh2(v0.x * rc, v0.y * rc);
    o.y = packh2(v0.z * rc, v0.w * rc);
    o.z = packh2(v1.x * rc, v1.y * rc);
    o.w = packh2(v1.z * rc, v1.w * rc);
    *(uint4*)(outh + (size_t)n * FD8 * 4 + g * 4) = o;
}

// ---------------------------------------------------------------------------
// Fused SAGE layer via fp16 mma.sync, M-tile = 128 nodes, N = 128.
// 256 threads = 8 warps (wm 0-3 -> 32 rows, wn 0-1 -> 64 cols), 2 CTAs/SM.
// Register-pipelined staging (2-panel lookahead, 1 barrier/panel).
template <int K, bool RELU>
__launch_bounds__(256, 2)
__global__ void layer_mma_kernel(const uint32_t* __restrict__ aggh,
                                 const uint32_t* __restrict__ xh,
                                 const uint32_t* __restrict__ Bg,
                                 const float* __restrict__ bl,
                                 uint32_t* __restrict__ outh) {
    extern __shared__ uint32_t usm[];
    uint32_t* Bsm = usm;                   // K*64 b32
    uint32_t* Asm = Bsm + K * 64;          // 2 * 2048 b32
    float* bs = (float*)(Asm + 4096);      // 128

    const int tid = threadIdx.x;
    const int FD = K / 2;
    const int FD2 = FD / 2;

    for (int i = tid; i < K * 16; i += 256)
        ((uint4*)Bsm)[i] = ((const uint4*)Bg)[i];
    if (tid < 128) bs[tid] = bl[tid];
    __syncthreads();

    const int wid = tid >> 5, lane = tid & 31;
    const int wm = wid & 3, wn = wid >> 2;
    const int gid = lane >> 2, tig = lane & 3;

    constexpr int P = K / 32;
    const int ntiles = (N_NODES + 127) >> 7;

    for (int tile = blockIdx.x; tile < ntiles; tile += gridDim.x) {
        const int n0 = tile << 7;

        auto ldg_panel = [&](int p, uint4* vv) {
            int c0 = p * 32;
            const uint32_t* src;
            int cu;
            if (c0 < FD) { src = aggh; cu = c0 >> 1; }
            else         { src = xh;   cu = (c0 - FD) >> 1; }
#pragma unroll
            for (int it = 0; it < 2; it++) {
                int idx = tid + 256 * it;      // 0..511
                int r = idx >> 2, g8 = idx & 3;
                int node = min(n0 + r, N_NODES - 1);
                vv[it] = *(const uint4*)(src + (size_t)node * FD2 + cu + g8 * 4);
            }
        };
        auto sts_panel = [&](const uint4* vv, uint32_t* buf) {
#pragma unroll
            for (int it = 0; it < 2; it++) sts_frag(buf, tid + 256 * it, vv[it]);
        };

        uint4 V[2][2];
        ldg_panel(0, V[0]);
        ldg_panel(1, V[1]);
        sts_panel(V[0], Asm);
        __syncthreads();

        float4 d[2][8];
#pragma unroll
        for (int t = 0; t < 2; t++)
#pragma unroll
            for (int j = 0; j < 8; j++) d[t][j] = make_float4(0.f, 0.f, 0.f, 0.f);

        for (int p = 0; p < P; p++) {
            if (p + 1 < P) sts_panel(V[(p + 1) & 1], Asm + ((p + 1) & 1) * 2048);
            if (p + 2 < P) ldg_panel(p + 2, V[p & 1]);
            const uint32_t* Af = Asm + (p & 1) * 2048;
#pragma unroll
            for (int kt = 0; kt < 2; kt++) {
                uint4 av[2];
#pragma unroll
                for (int t = 0; t < 2; t++)
                    av[t] = *(const uint4*)&Af[((kt * 8 + wm * 2 + t) * 32 + lane) * 4];
                int kb = p * 2 + kt;
#pragma unroll
                for (int j = 0; j < 8; j++) {
                    uint2 bv = *(const uint2*)&Bsm[((kb * 16 + wn * 8 + j) * 32 + lane) * 2];
#pragma unroll
                    for (int t = 0; t < 2; t++) mma_f16(d[t][j], av[t], bv);
                }
            }
            __syncthreads();
        }

        // epilogue: bias (+relu), write fp16
#pragma unroll
        for (int t = 0; t < 2; t++) {
            int nlo = n0 + wm * 32 + t * 16 + gid;
            int nhi = nlo + 8;
#pragma unroll
            for (int j = 0; j < 8; j++) {
                int col = wn * 64 + j * 8 + tig * 2;
                float ba = bs[col], bb = bs[col + 1];
                float2 lo = make_float2(d[t][j].x + ba, d[t][j].y + bb);
                float2 hi = make_float2(d[t][j].z + ba, d[t][j].w + bb);
                if (RELU) {
                    lo.x = fmaxf(lo.x, 0.f); lo.y = fmaxf(lo.y, 0.f);
                    hi.x = fmaxf(hi.x, 0.f); hi.y = fmaxf(hi.y, 0.f);
                }
                if (nlo < N_NODES) outh[(size_t)nlo * 64 + (col >> 1)] = packh2(lo.x, lo.y);
                if (nhi < N_NODES) outh[(size_t)nhi * 64 + (col >> 1)] = packh2(hi.x, hi.y);
            }
        }
        __syncthreads();
    }
}

// ---------------------------------------------------------------------------
// Classifier via fp16 mma.sync, M-tile = 128 edges, N = 128, K = 288,
// 256 threads = 8 warps, 2 CTAs/SM, register-pipelined staging.
__launch_bounds__(256, 2)
__global__ void classify_mma_kernel(const uint32_t* __restrict__ h1h,
                                    const int* __restrict__ fsrc,
                                    const int* __restrict__ fdst,
                                    const uint32_t* __restrict__ eattrh,
                                    const uint32_t* __restrict__ Bg,
                                    const float* __restrict__ b1,
                                    const float* __restrict__ W2,
                                    const float* __restrict__ b2,
                                    float* __restrict__ outp, int Ef) {
    extern __shared__ uint32_t usm[];
    uint32_t* Bsm = usm;                   // 288*64 = 18432 b32
    uint32_t* Asm = Bsm + 18432;           // 2 * 2048 b32
    float* b1s  = (float*)(Asm + 4096);    // 128
    float* w2s  = b1s + 128;               // 128
    float* red  = w2s + 128;               // 128
    int*   sidx = (int*)(red + 128);       // 128
    int*   didx = sidx + 128;              // 128

    const int tid = threadIdx.x;

    for (int i = tid; i < 4608; i += 256)
        ((uint4*)Bsm)[i] = ((const uint4*)Bg)[i];
    if (tid < 128) { b1s[tid] = b1[tid]; w2s[tid] = W2[tid]; }
    __syncthreads();
    const float b2v = __ldg(&b2[0]);

    const int wid = tid >> 5, lane = tid & 31;
    const int wm = wid & 3, wn = wid >> 2;
    const int gid = lane >> 2, tig = lane & 3;

    const int ntiles = (Ef + 127) >> 7;
    for (int tile = blockIdx.x; tile < ntiles; tile += gridDim.x) {
        const int e0 = tile << 7;
        if (tid < 128) {
            int e = min(e0 + tid, Ef - 1);
            sidx[tid] = __ldg(&fsrc[e]);
            didx[tid] = __ldg(&fdst[e]);
            red[tid] = 0.0f;
        }
        __syncthreads();

        auto ldg_panel = [&](int p, uint4* vv) {
#pragma unroll
            for (int it = 0; it < 2; it++) {
                int idx = tid + 256 * it;      // 0..511
                int r = idx >> 2, g8 = idx & 3;
                const uint32_t* sp;
                if (p < 4)
                    sp = h1h + (size_t)sidx[r] * 64 + p * 16 + g8 * 4;
                else if (p < 8)
                    sp = h1h + (size_t)didx[r] * 64 + (p - 4) * 16 + g8 * 4;
                else {
                    int e = min(e0 + r, Ef - 1);
                    sp = eattrh + (size_t)e * 16 + g8 * 4;
                }
                vv[it] = *(const uint4*)sp;
            }
        };
        auto sts_panel = [&](const uint4* vv, uint32_t* buf) {
#pragma unroll
            for (int it = 0; it < 2; it++) sts_frag(buf, tid + 256 * it, vv[it]);
        };

        uint4 V[2][2];
        ldg_panel(0, V[0]);
        ldg_panel(1, V[1]);
        sts_panel(V[0], Asm);
        __syncthreads();

        float4 d[2][8];
#pragma unroll
        for (int t = 0; t < 2; t++)
#pragma unroll
            for (int j = 0; j < 8; j++) d[t][j] = make_float4(0.f, 0.f, 0.f, 0.f);

        for (int p = 0; p < 9; p++) {
            if (p + 1 < 9) sts_panel(V[(p + 1) & 1], Asm + ((p + 1) & 1) * 2048);
            if (p + 2 < 9) ldg_panel(p + 2, V[p & 1]);
            const uint32_t* Af = Asm + (p & 1) * 2048;
#pragma unroll
            for (int kt = 0; kt < 2; kt++) {
                uint4 av[2];
#pragma unroll
                for (int t = 0; t < 2; t++)
                    av[t] = *(const uint4*)&Af[((kt * 8 + wm * 2 + t) * 32 + lane) * 4];
                int kb = p * 2 + kt;
#pragma unroll
                for (int j = 0; j < 8; j++) {
                    uint2 bv = *(const uint2*)&Bsm[((kb * 16 + wn * 8 + j) * 32 + lane) * 2];
#pragma unroll
                    for (int t = 0; t < 2; t++) mma_f16(d[t][j], av[t], bv);
                }
            }
            __syncthreads();
        }

        // epilogue: relu + dot with W2, reduce over 128 hidden dims
        float s_[2][2];
#pragma unroll
        for (int t = 0; t < 2; t++) { s_[t][0] = 0.f; s_[t][1] = 0.f; }
#pragma unroll
        for (int t = 0; t < 2; t++) {
#pragma unroll
            for (int j = 0; j < 8; j++) {
                int col = wn * 64 + j * 8 + tig * 2;
                float ba = b1s[col], bb = b1s[col + 1];
                float wa = w2s[col], wb = w2s[col + 1];
                s_[t][0] += fmaxf(d[t][j].x + ba, 0.f) * wa + fmaxf(d[t][j].y + bb, 0.f) * wb;
                s_[t][1] += fmaxf(d[t][j].z + ba, 0.f) * wa + fmaxf(d[t][j].w + bb, 0.f) * wb;
            }
        }
#pragma unroll
        for (int t = 0; t < 2; t++) {
            s_[t][0] += __shfl_xor_sync(0xffffffffu, s_[t][0], 1);
            s_[t][0] += __shfl_xor_sync(0xffffffffu, s_[t][0], 2);
            s_[t][1] += __shfl_xor_sync(0xffffffffu, s_[t][1], 1);
            s_[t][1] += __shfl_xor_sync(0xffffffffu, s_[t][1], 2);
        }
        if (tig == 0) {
#pragma unroll
            for (int t = 0; t < 2; t++) {
                atomicAdd(&red[wm * 32 + t * 16 + gid], s_[t][0]);
                atomicAdd(&red[wm * 32 + t * 16 + gid + 8], s_[t][1]);
            }
        }
        __syncthreads();
        if (tid < 128) {
            int e = e0 + tid;
            if (e < Ef) outp[e] = red[tid] + b2v;
        }
        __syncthreads();
    }
}

// ---------------------------------------------------------------------------
extern "C" void kernel_launch(void* const* d_in, const int* in_sizes, int n_in,
                              void* d_out, int out_size) {
    const float* x     = (const float*)d_in[0];
    const int*   ei    = (const int*)d_in[1];
    const int*   fei   = (const int*)d_in[2];
    const float* eattr = (const float*)d_in[3];
    const float* Wl0   = (const float*)d_in[4];
    const float* bl0   = (const float*)d_in[5];
    const float* Wr0   = (const float*)d_in[6];
    const float* Wl1   = (const float*)d_in[7];
    const float* bl1   = (const float*)d_in[8];
    const float* Wr1   = (const float*)d_in[9];
    const float* W1    = (const float*)d_in[10];
    const float* b1    = (const float*)d_in[11];
    const float* W2    = (const float*)d_in[12];
    const float* b2    = (const float*)d_in[13];
    float* outp = (float*)d_out;

    int E  = in_sizes[1] / 2;
    int Ef = in_sizes[2] / 2;
    const int* src  = ei;
    const int* dst  = ei + E;
    const int* fsrc = fei;
    const int* fdst = fei + Ef;

    float *agg_p, *agg2_p, *cnt_p;
    uint32_t *xh_p, *h0h_p, *h1h_p, *aggh_p, *eattrh_p, *B0_p, *B1_p, *BC_p;
    cudaGetSymbolAddress((void**)&agg_p, g_agg);
    cudaGetSymbolAddress((void**)&agg2_p, g_agg2);
    cudaGetSymbolAddress((void**)&cnt_p, g_cnt);
    cudaGetSymbolAddress((void**)&xh_p, g_xh);
    cudaGetSymbolAddress((void**)&h0h_p, g_h0h);
    cudaGetSymbolAddress((void**)&h1h_p, g_h1h);
    cudaGetSymbolAddress((void**)&aggh_p, g_aggh);
    cudaGetSymbolAddress((void**)&eattrh_p, g_eattrh);
    cudaGetSymbolAddress((void**)&B0_p, g_B0);
    cudaGetSymbolAddress((void**)&B1_p, g_B1);
    cudaGetSymbolAddress((void**)&BC_p, g_BC);

    const int smemL0 = (128 * 64 + 4096 + 128) * 4;
    const int smemL1 = (256 * 64 + 4096 + 128) * 4;
    const int smemC  = (18432 + 4096 + 384) * 4 + 256 * 4;
    cudaFuncSetAttribute(layer_mma_kernel<128, true>,
                         cudaFuncAttributeMaxDynamicSharedMemorySize, smemL0);
    cudaFuncSetAttribute(layer_mma_kernel<256, false>,
                         cudaFuncAttributeMaxDynamicSharedMemorySize, smemL1);
    cudaFuncSetAttribute(classify_mma_kernel,
                         cudaFuncAttributeMaxDynamicSharedMemorySize, smemC);

    // 1: prep (zero scratch, fp16 conversions, weight prepack)
    prep_kernel<<<2048, 256>>>(x, eattr, Wl0, Wr0, Wl1, Wr1, W1,
                               agg_p, agg2_p, cnt_p, xh_p, eattrh_p,
                               B0_p, B1_p, BC_p, Ef);
    // 2: scatter x (64-wide fp32) + degree count
    scatter64_count_kernel<<<(E * 16 + 255) / 256, 256>>>(x, src, dst, E, agg_p, cnt_p);
    // 3: aggh0 = half(agg / cnt)
    conv_scale_half_kernel<8><<<(N_NODES * 8 + 255) / 256, 256>>>(agg_p, cnt_p, aggh_p);
    // 4: layer 0 (writes h0h fp16 only), 2 CTAs/SM
    layer_mma_kernel<128, true><<<296, 256, smemL0>>>(aggh_p, xh_p, B0_p, bl0, h0h_p);
    // 5: scatter h0h (fp16 reads, fp32 atomics, full 128 columns)
    scatter128h_kernel<<<(E * 32 + 255) / 256, 256>>>(h0h_p, src, dst, E, agg2_p);
    // 6: aggh1 = half(agg2 / cnt)
    conv_scale_half_kernel<16><<<(N_NODES * 16 + 255) / 256, 256>>>(agg2_p, cnt_p, aggh_p);
    // 7: layer 1 (writes h1h fp16), 2 CTAs/SM
    layer_mma_kernel<256, false><<<296, 256, smemL1>>>(aggh_p, h0h_p, B1_p, bl1, h1h_p);
    // 8: edge classifier, 2 CTAs/SM
    classify_mma_kernel<<<296, 256, smemC>>>(h1h_p, fsrc, fdst, eattrh_p,
                                             BC_p, b1, W2, b2, outp, Ef);
}

// round 16
// speedup vs baseline: 8.5535x; 1.2419x over previous
#include <cuda_runtime.h>
#include <cuda_fp16.h>
#include <cstdint>

#define N_NODES 100000
#define E_MAX   800000
#define EF_MAX  500000
#define SCAN_NB ((N_NODES + 255) / 256)   // 391

// Scratch (allocation-free rule: __device__ globals)
__device__ int      g_deg[N_NODES];
__device__ int      g_cur[N_NODES];
__device__ int      g_off[N_NODES];
__device__ int      g_bsum[SCAN_NB];
__device__ int      g_adj[E_MAX];
__device__ uint32_t g_xh[N_NODES * 32];      // x as half2
__device__ uint32_t g_h0h[N_NODES * 64];     // h0 as half2
__device__ uint32_t g_h1h[N_NODES * 64];     // h1 as half2
__device__ uint32_t g_aggh[N_NODES * 64];    // scaled mean agg as half2
__device__ uint32_t g_eattrh[EF_MAX * 16];   // edge_attr as half2
__device__ uint32_t g_B0[128 * 64];          // prepacked weight fragments
__device__ uint32_t g_B1[256 * 64];
__device__ uint32_t g_BC[288 * 64];

// ---------------------------------------------------------------------------
__device__ __forceinline__ void mma_f16(float4& d, const uint4 a, const uint2 b) {
    asm("mma.sync.aligned.m16n8k16.row.col.f32.f16.f16.f32 "
        "{%0,%1,%2,%3}, {%4,%5,%6,%7}, {%8,%9}, {%0,%1,%2,%3};"
        : "+f"(d.x), "+f"(d.y), "+f"(d.z), "+f"(d.w)
        : "r"(a.x), "r"(a.y), "r"(a.z), "r"(a.w), "r"(b.x), "r"(b.y));
}

__device__ __forceinline__ uint32_t packh2(float lo, float hi) {
    __half2 h = __floats2half2_rn(lo, hi);
    return *(uint32_t*)&h;
}

// B fragment pack: slot s of a K x 128 weight [Wl;Wr] (FD rows each)
__device__ __forceinline__ uint32_t pack_w(int s, int FD,
                                           const float* __restrict__ Wl,
                                           const float* __restrict__ Wr) {
    int reg = s & 1, lane = (s >> 1) & 31, nb = (s >> 6) & 15, kb = s >> 10;
    int tig = lane & 3, gid = lane >> 2;
    int n = nb * 8 + gid;
    int k0 = kb * 16 + reg * 8 + tig * 2;
    float lo = (k0 < FD) ? Wl[k0 * 128 + n] : Wr[(k0 - FD) * 128 + n];
    float hi = (k0 + 1 < FD) ? Wl[(k0 + 1) * 128 + n] : Wr[(k0 + 1 - FD) * 128 + n];
    return packh2(lo, hi);
}

// Store one staged uint4 into the A fragment slot layout (M-tile = 128)
__device__ __forceinline__ void sts_frag(uint32_t* __restrict__ buf,
                                         int idx, const uint4 v) {
    int r = idx >> 2, g8 = idx & 3;
    int kt = g8 >> 1, khalf = g8 & 1;
    int reg = ((r >> 3) & 1) | (khalf << 1);
    uint32_t* s = &buf[(((kt * 8 + (r >> 4)) * 32) + (r & 7) * 4) * 4 + reg];
    s[0] = v.x; s[4] = v.y; s[8] = v.z; s[12] = v.w;
}

// ---------------------------------------------------------------------------
// prep: zero deg/cur, convert x/eattr to fp16, prepack weight fragments
__global__ void prep_kernel(const float* __restrict__ x,
                            const float* __restrict__ eattr,
                            const float* __restrict__ Wl0, const float* __restrict__ Wr0,
                            const float* __restrict__ Wl1, const float* __restrict__ Wr1,
                            const float* __restrict__ W1,
                            int* __restrict__ deg, int* __restrict__ cur,
                            uint32_t* __restrict__ xh, uint32_t* __restrict__ eattrh,
                            uint32_t* __restrict__ B0, uint32_t* __restrict__ B1,
                            uint32_t* __restrict__ BC, int Ef) {
    int i0 = blockIdx.x * blockDim.x + threadIdx.x;
    int stride = gridDim.x * blockDim.x;
    for (int j = i0; j < N_NODES; j += stride) { deg[j] = 0; cur[j] = 0; }
    for (int j = i0; j < N_NODES * 32; j += stride) {
        float2 v = ((const float2*)x)[j];
        xh[j] = packh2(v.x, v.y);
    }
    for (int j = i0; j < Ef * 16; j += stride) {
        float2 v = ((const float2*)eattr)[j];
        eattrh[j] = packh2(v.x, v.y);
    }
    for (int s = i0; s < 128 * 64; s += stride) B0[s] = pack_w(s, 64, Wl0, Wr0);
    for (int s = i0; s < 256 * 64; s += stride) B1[s] = pack_w(s, 128, Wl1, Wr1);
    for (int s = i0; s < 288 * 64; s += stride) BC[s] = pack_w(s, 288, W1, W1);
}

__global__ void count_deg_kernel(const int* __restrict__ dst, int E,
                                 int* __restrict__ deg) {
    int e = blockIdx.x * blockDim.x + threadIdx.x;
    if (e < E) atomicAdd(&deg[dst[e]], 1);
}

// block-level exclusive scan of deg -> off (partial), block sums -> bsum
__global__ void scan1_kernel(const int* __restrict__ deg,
                             int* __restrict__ off, int* __restrict__ bsum) {
    __shared__ int sh[256];
    int tid = threadIdx.x;
    int i = blockIdx.x * 256 + tid;
    int v = (i < N_NODES) ? deg[i] : 0;
    sh[tid] = v;
    __syncthreads();
    for (int ofs = 1; ofs < 256; ofs <<= 1) {
        int t = (tid >= ofs) ? sh[tid - ofs] : 0;
        __syncthreads();
        sh[tid] += t;
        __syncthreads();
    }
    if (i < N_NODES) off[i] = sh[tid] - v;
    if (tid == 255) bsum[blockIdx.x] = sh[255];
}

// add prefix of block sums to each element
__global__ void scan2_kernel(const int* __restrict__ bsum, int* __restrict__ off) {
    __shared__ int sh[256];
    int tid = threadIdx.x;
    int b = blockIdx.x;
    int acc = 0;
    for (int j = tid; j < b; j += 256) acc += bsum[j];
    sh[tid] = acc;
    __syncthreads();
    for (int ofs = 128; ofs; ofs >>= 1) {
        if (tid < ofs) sh[tid] += sh[tid + ofs];
        __syncthreads();
    }
    int base = sh[0];
    int i = b * 256 + tid;
    if (i < N_NODES) off[i] += base;
}

__global__ void fill_adj_kernel(const int* __restrict__ src,
                                const int* __restrict__ dst, int E,
                                const int* __restrict__ off,
                                int* __restrict__ cur, int* __restrict__ adj) {
    int e = blockIdx.x * blockDim.x + threadIdx.x;
    if (e >= E) return;
    int d = __ldg(&dst[e]);
    int pos = atomicAdd(&cur[d], 1);
    adj[off[d] + pos] = __ldg(&src[e]);
}

// gather-mean over fp32 x (64 cols): warp per node, lane = float2 cols
__global__ void gather_mean_f32_kernel(const float* __restrict__ x,
                                       const int* __restrict__ off,
                                       const int* __restrict__ deg,
                                       const int* __restrict__ adj,
                                       uint32_t* __restrict__ aggh) {
    int warp = (blockIdx.x * blockDim.x + threadIdx.x) >> 5;
    int lane = threadIdx.x & 31;
    if (warp >= N_NODES) return;
    int o = __ldg(&off[warp]);
    int dg = __ldg(&deg[warp]);
    float ax = 0.f, ay = 0.f;
    int j = 0;
    for (; j + 1 < dg; j += 2) {
        int s0 = __ldg(&adj[o + j]);
        int s1 = __ldg(&adj[o + j + 1]);
        float2 v0 = *(const float2*)(x + (size_t)s0 * 64 + lane * 2);
        float2 v1 = *(const float2*)(x + (size_t)s1 * 64 + lane * 2);
        ax += v0.x; ay += v0.y;
        ax += v1.x; ay += v1.y;
    }
    if (j < dg) {
        int s0 = __ldg(&adj[o + j]);
        float2 v0 = *(const float2*)(x + (size_t)s0 * 64 + lane * 2);
        ax += v0.x; ay += v0.y;
    }
    float rc = 1.0f / fmaxf((float)dg, 1.0f);
    aggh[(size_t)warp * 32 + lane] = packh2(ax * rc, ay * rc);
}

// gather-mean over fp16 h0 (128 cols = 64 u32): warp per node, lane = 2 u32
__global__ void gather_mean_h_kernel(const uint32_t* __restrict__ feath,
                                     const int* __restrict__ off,
                                     const int* __restrict__ deg,
                                     const int* __restrict__ adj,
                                     uint32_t* __restrict__ aggh) {
    int warp = (blockIdx.x * blockDim.x + threadIdx.x) >> 5;
    int lane = threadIdx.x & 31;
    if (warp >= N_NODES) return;
    int o = __ldg(&off[warp]);
    int dg = __ldg(&deg[warp]);
    float a0 = 0.f, a1 = 0.f, a2 = 0.f, a3 = 0.f;
    int j = 0;
    for (; j + 1 < dg; j += 2) {
        int s0 = __ldg(&adj[o + j]);
        int s1 = __ldg(&adj[o + j + 1]);
        uint32_t u0 = feath[(size_t)s0 * 64 + lane];
        uint32_t u1 = feath[(size_t)s0 * 64 + 32 + lane];
        uint32_t w0 = feath[(size_t)s1 * 64 + lane];
        uint32_t w1 = feath[(size_t)s1 * 64 + 32 + lane];
        float2 f;
        f = __half22float2(*(__half2*)&u0); a0 += f.x; a1 += f.y;
        f = __half22float2(*(__half2*)&u1); a2 += f.x; a3 += f.y;
        f = __half22float2(*(__half2*)&w0); a0 += f.x; a1 += f.y;
        f = __half22float2(*(__half2*)&w1); a2 += f.x; a3 += f.y;
    }
    if (j < dg) {
        int s0 = __ldg(&adj[o + j]);
        uint32_t u0 = feath[(size_t)s0 * 64 + lane];
        uint32_t u1 = feath[(size_t)s0 * 64 + 32 + lane];
        float2 f;
        f = __half22float2(*(__half2*)&u0); a0 += f.x; a1 += f.y;
        f = __half22float2(*(__half2*)&u1); a2 += f.x; a3 += f.y;
    }
    float rc = 1.0f / fmaxf((float)dg, 1.0f);
    aggh[(size_t)warp * 64 + lane]      = packh2(a0 * rc, a1 * rc);
    aggh[(size_t)warp * 64 + 32 + lane] = packh2(a2 * rc, a3 * rc);
}

// ---------------------------------------------------------------------------
// Fused SAGE layer via fp16 mma.sync, M-tile = 128 nodes, N = 128.
// 256 threads = 8 warps, 2 CTAs/SM, register-pipelined staging.
template <int K, bool RELU>
__launch_bounds__(256, 2)
__global__ void layer_mma_kernel(const uint32_t* __restrict__ aggh,
                                 const uint32_t* __restrict__ xh,
                                 const uint32_t* __restrict__ Bg,
                                 const float* __restrict__ bl,
                                 uint32_t* __restrict__ outh) {
    extern __shared__ uint32_t usm[];
    uint32_t* Bsm = usm;                   // K*64 b32
    uint32_t* Asm = Bsm + K * 64;          // 2 * 2048 b32
    float* bs = (float*)(Asm + 4096);      // 128

    const int tid = threadIdx.x;
    const int FD = K / 2;
    const int FD2 = FD / 2;

    for (int i = tid; i < K * 16; i += 256)
        ((uint4*)Bsm)[i] = ((const uint4*)Bg)[i];
    if (tid < 128) bs[tid] = bl[tid];
    __syncthreads();

    const int wid = tid >> 5, lane = tid & 31;
    const int wm = wid & 3, wn = wid >> 2;
    const int gid = lane >> 2, tig = lane & 3;

    constexpr int P = K / 32;
    const int ntiles = (N_NODES + 127) >> 7;

    for (int tile = blockIdx.x; tile < ntiles; tile += gridDim.x) {
        const int n0 = tile << 7;

        auto ldg_panel = [&](int p, uint4* vv) {
            int c0 = p * 32;
            const uint32_t* src;
            int cu;
            if (c0 < FD) { src = aggh; cu = c0 >> 1; }
            else         { src = xh;   cu = (c0 - FD) >> 1; }
#pragma unroll
            for (int it = 0; it < 2; it++) {
                int idx = tid + 256 * it;
                int r = idx >> 2, g8 = idx & 3;
                int node = min(n0 + r, N_NODES - 1);
                vv[it] = *(const uint4*)(src + (size_t)node * FD2 + cu + g8 * 4);
            }
        };
        auto sts_panel = [&](const uint4* vv, uint32_t* buf) {
#pragma unroll
            for (int it = 0; it < 2; it++) sts_frag(buf, tid + 256 * it, vv[it]);
        };

        uint4 V[2][2];
        ldg_panel(0, V[0]);
        ldg_panel(1, V[1]);
        sts_panel(V[0], Asm);
        __syncthreads();

        float4 d[2][8];
#pragma unroll
        for (int t = 0; t < 2; t++)
#pragma unroll
            for (int j = 0; j < 8; j++) d[t][j] = make_float4(0.f, 0.f, 0.f, 0.f);

        for (int p = 0; p < P; p++) {
            if (p + 1 < P) sts_panel(V[(p + 1) & 1], Asm + ((p + 1) & 1) * 2048);
            if (p + 2 < P) ldg_panel(p + 2, V[p & 1]);
            const uint32_t* Af = Asm + (p & 1) * 2048;
#pragma unroll
            for (int kt = 0; kt < 2; kt++) {
                uint4 av[2];
#pragma unroll
                for (int t = 0; t < 2; t++)
                    av[t] = *(const uint4*)&Af[((kt * 8 + wm * 2 + t) * 32 + lane) * 4];
                int kb = p * 2 + kt;
#pragma unroll
                for (int j = 0; j < 8; j++) {
                    uint2 bv = *(const uint2*)&Bsm[((kb * 16 + wn * 8 + j) * 32 + lane) * 2];
#pragma unroll
                    for (int t = 0; t < 2; t++) mma_f16(d[t][j], av[t], bv);
                }
            }
            __syncthreads();
        }

        // epilogue: bias (+relu), write fp16
#pragma unroll
        for (int t = 0; t < 2; t++) {
            int nlo = n0 + wm * 32 + t * 16 + gid;
            int nhi = nlo + 8;
#pragma unroll
            for (int j = 0; j < 8; j++) {
                int col = wn * 64 + j * 8 + tig * 2;
                float ba = bs[col], bb = bs[col + 1];
                float2 lo = make_float2(d[t][j].x + ba, d[t][j].y + bb);
                float2 hi = make_float2(d[t][j].z + ba, d[t][j].w + bb);
                if (RELU) {
                    lo.x = fmaxf(lo.x, 0.f); lo.y = fmaxf(lo.y, 0.f);
                    hi.x = fmaxf(hi.x, 0.f); hi.y = fmaxf(hi.y, 0.f);
                }
                if (nlo < N_NODES) outh[(size_t)nlo * 64 + (col >> 1)] = packh2(lo.x, lo.y);
                if (nhi < N_NODES) outh[(size_t)nhi * 64 + (col >> 1)] = packh2(hi.x, hi.y);
            }
        }
        __syncthreads();
    }
}

// ---------------------------------------------------------------------------
// Classifier via fp16 mma.sync, M-tile = 128 edges, N = 128, K = 288,
// 256 threads = 8 warps, 2 CTAs/SM, register-pipelined staging.
__launch_bounds__(256, 2)
__global__ void classify_mma_kernel(const uint32_t* __restrict__ h1h,
                                    const int* __restrict__ fsrc,
                                    const int* __restrict__ fdst,
                                    const uint32_t* __restrict__ eattrh,
                                    const uint32_t* __restrict__ Bg,
                                    const float* __restrict__ b1,
                                    const float* __restrict__ W2,
                                    const float* __restrict__ b2,
                                    float* __restrict__ outp, int Ef) {
    extern __shared__ uint32_t usm[];
    uint32_t* Bsm = usm;                   // 288*64 = 18432 b32
    uint32_t* Asm = Bsm + 18432;           // 2 * 2048 b32
    float* b1s  = (float*)(Asm + 4096);    // 128
    float* w2s  = b1s + 128;               // 128
    float* red  = w2s + 128;               // 128
    int*   sidx = (int*)(red + 128);       // 128
    int*   didx = sidx + 128;              // 128

    const int tid = threadIdx.x;

    for (int i = tid; i < 4608; i += 256)
        ((uint4*)Bsm)[i] = ((const uint4*)Bg)[i];
    if (tid < 128) { b1s[tid] = b1[tid]; w2s[tid] = W2[tid]; }
    __syncthreads();
    const float b2v = __ldg(&b2[0]);

    const int wid = tid >> 5, lane = tid & 31;
    const int wm = wid & 3, wn = wid >> 2;
    const int gid = lane >> 2, tig = lane & 3;

    const int ntiles = (Ef + 127) >> 7;
    for (int tile = blockIdx.x; tile < ntiles; tile += gridDim.x) {
        const int e0 = tile << 7;
        if (tid < 128) {
            int e = min(e0 + tid, Ef - 1);
            sidx[tid] = __ldg(&fsrc[e]);
            didx[tid] = __ldg(&fdst[e]);
            red[tid] = 0.0f;
        }
        __syncthreads();

        auto ldg_panel = [&](int p, uint4* vv) {
#pragma unroll
            for (int it = 0; it < 2; it++) {
                int idx = tid + 256 * it;
                int r = idx >> 2, g8 = idx & 3;
                const uint32_t* sp;
                if (p < 4)
                    sp = h1h + (size_t)sidx[r] * 64 + p * 16 + g8 * 4;
                else if (p < 8)
                    sp = h1h + (size_t)didx[r] * 64 + (p - 4) * 16 + g8 * 4;
                else {
                    int e = min(e0 + r, Ef - 1);
                    sp = eattrh + (size_t)e * 16 + g8 * 4;
                }
                vv[it] = *(const uint4*)sp;
            }
        };
        auto sts_panel = [&](const uint4* vv, uint32_t* buf) {
#pragma unroll
            for (int it = 0; it < 2; it++) sts_frag(buf, tid + 256 * it, vv[it]);
        };

        uint4 V[2][2];
        ldg_panel(0, V[0]);
        ldg_panel(1, V[1]);
        sts_panel(V[0], Asm);
        __syncthreads();

        float4 d[2][8];
#pragma unroll
        for (int t = 0; t < 2; t++)
#pragma unroll
            for (int j = 0; j < 8; j++) d[t][j] = make_float4(0.f, 0.f, 0.f, 0.f);

        for (int p = 0; p < 9; p++) {
            if (p + 1 < 9) sts_panel(V[(p + 1) & 1], Asm + ((p + 1) & 1) * 2048);
            if (p + 2 < 9) ldg_panel(p + 2, V[p & 1]);
            const uint32_t* Af = Asm + (p & 1) * 2048;
#pragma unroll
            for (int kt = 0; kt < 2; kt++) {
                uint4 av[2];
#pragma unroll
                for (int t = 0; t < 2; t++)
                    av[t] = *(const uint4*)&Af[((kt * 8 + wm * 2 + t) * 32 + lane) * 4];
                int kb = p * 2 + kt;
#pragma unroll
                for (int j = 0; j < 8; j++) {
                    uint2 bv = *(const uint2*)&Bsm[((kb * 16 + wn * 8 + j) * 32 + lane) * 2];
#pragma unroll
                    for (int t = 0; t < 2; t++) mma_f16(d[t][j], av[t], bv);
                }
            }
            __syncthreads();
        }

        // epilogue: relu + dot with W2, reduce over 128 hidden dims
        float s_[2][2];
#pragma unroll
        for (int t = 0; t < 2; t++) { s_[t][0] = 0.f; s_[t][1] = 0.f; }
#pragma unroll
        for (int t = 0; t < 2; t++) {
#pragma unroll
            for (int j = 0; j < 8; j++) {
                int col = wn * 64 + j * 8 + tig * 2;
                float ba = b1s[col], bb = b1s[col + 1];
                float wa = w2s[col], wb = w2s[col + 1];
                s_[t][0] += fmaxf(d[t][j].x + ba, 0.f) * wa + fmaxf(d[t][j].y + bb, 0.f) * wb;
                s_[t][1] += fmaxf(d[t][j].z + ba, 0.f) * wa + fmaxf(d[t][j].w + bb, 0.f) * wb;
            }
        }
#pragma unroll
        for (int t = 0; t < 2; t++) {
            s_[t][0] += __shfl_xor_sync(0xffffffffu, s_[t][0], 1);
            s_[t][0] += __shfl_xor_sync(0xffffffffu, s_[t][0], 2);
            s_[t][1] += __shfl_xor_sync(0xffffffffu, s_[t][1], 1);
            s_[t][1] += __shfl_xor_sync(0xffffffffu, s_[t][1], 2);
        }
        if (tig == 0) {
#pragma unroll
            for (int t = 0; t < 2; t++) {
                atomicAdd(&red[wm * 32 + t * 16 + gid], s_[t][0]);
                atomicAdd(&red[wm * 32 + t * 16 + gid + 8], s_[t][1]);
            }
        }
        __syncthreads();
        if (tid < 128) {
            int e = e0 + tid;
            if (e < Ef) outp[e] = red[tid] + b2v;
        }
        __syncthreads();
    }
}

// ---------------------------------------------------------------------------
extern "C" void kernel_launch(void* const* d_in, const int* in_sizes, int n_in,
                              void* d_out, int out_size) {
    const float* x     = (const float*)d_in[0];
    const int*   ei    = (const int*)d_in[1];
    const int*   fei   = (const int*)d_in[2];
    const float* eattr = (const float*)d_in[3];
    const float* Wl0   = (const float*)d_in[4];
    const float* bl0   = (const float*)d_in[5];
    const float* Wr0   = (const float*)d_in[6];
    const float* Wl1   = (const float*)d_in[7];
    const float* bl1   = (const float*)d_in[8];
    const float* Wr1   = (const float*)d_in[9];
    const float* W1    = (const float*)d_in[10];
    const float* b1    = (const float*)d_in[11];
    const float* W2    = (const float*)d_in[12];
    const float* b2    = (const float*)d_in[13];
    float* outp = (float*)d_out;

    int E  = in_sizes[1] / 2;
    int Ef = in_sizes[2] / 2;
    const int* src  = ei;
    const int* dst  = ei + E;
    const int* fsrc = fei;
    const int* fdst = fei + Ef;

    int *deg_p, *cur_p, *off_p, *bsum_p, *adj_p;
    uint32_t *xh_p, *h0h_p, *h1h_p, *aggh_p, *eattrh_p, *B0_p, *B1_p, *BC_p;
    cudaGetSymbolAddress((void**)&deg_p, g_deg);
    cudaGetSymbolAddress((void**)&cur_p, g_cur);
    cudaGetSymbolAddress((void**)&off_p, g_off);
    cudaGetSymbolAddress((void**)&bsum_p, g_bsum);
    cudaGetSymbolAddress((void**)&adj_p, g_adj);
    cudaGetSymbolAddress((void**)&xh_p, g_xh);
    cudaGetSymbolAddress((void**)&h0h_p, g_h0h);
    cudaGetSymbolAddress((void**)&h1h_p, g_h1h);
    cudaGetSymbolAddress((void**)&aggh_p, g_aggh);
    cudaGetSymbolAddress((void**)&eattrh_p, g_eattrh);
    cudaGetSymbolAddress((void**)&B0_p, g_B0);
    cudaGetSymbolAddress((void**)&B1_p, g_B1);
    cudaGetSymbolAddress((void**)&BC_p, g_BC);

    const int smemL0 = (128 * 64 + 4096 + 128) * 4;
    const int smemL1 = (256 * 64 + 4096 + 128) * 4;
    const int smemC  = (18432 + 4096 + 384) * 4 + 256 * 4;
    cudaFuncSetAttribute(layer_mma_kernel<128, true>,
                         cudaFuncAttributeMaxDynamicSharedMemorySize, smemL0);
    cudaFuncSetAttribute(layer_mma_kernel<256, false>,
                         cudaFuncAttributeMaxDynamicSharedMemorySize, smemL1);
    cudaFuncSetAttribute(classify_mma_kernel,
                         cudaFuncAttributeMaxDynamicSharedMemorySize, smemC);

    // 1: prep (zero deg/cur, fp16 conversions, weight prepack)
    prep_kernel<<<2048, 256>>>(x, eattr, Wl0, Wr0, Wl1, Wr1, W1,
                               deg_p, cur_p, xh_p, eattrh_p,
                               B0_p, B1_p, BC_p, Ef);
    // 2-5: CSR build (degree count -> offsets -> adjacency fill)
    count_deg_kernel<<<(E + 255) / 256, 256>>>(dst, E, deg_p);
    scan1_kernel<<<SCAN_NB, 256>>>(deg_p, off_p, bsum_p);
    scan2_kernel<<<SCAN_NB, 256>>>(bsum_p, off_p);
    fill_adj_kernel<<<(E + 255) / 256, 256>>>(src, dst, E, off_p, cur_p, adj_p);
    // 6: layer-0 mean aggregation (gather fp32 x, write fp16 aggh)
    gather_mean_f32_kernel<<<(N_NODES * 32 + 255) / 256, 256>>>(x, off_p, deg_p,
                                                                adj_p, aggh_p);
    // 7: layer 0 mma
    layer_mma_kernel<128, true><<<296, 256, smemL0>>>(aggh_p, xh_p, B0_p, bl0, h0h_p);
    // 8: layer-1 mean aggregation (gather fp16 h0, write fp16 aggh)
    gather_mean_h_kernel<<<(N_NODES * 32 + 255) / 256, 256>>>(h0h_p, off_p, deg_p,
                                                              adj_p, aggh_p);
    // 9: layer 1 mma
    layer_mma_kernel<256, false><<<296, 256, smemL1>>>(aggh_p, h0h_p, B1_p, bl1, h1h_p);
    // 10: edge classifier
    classify_mma_kernel<<<296, 256, smemC>>>(h1h_p, fsrc, fdst, eattrh_p,
                                             BC_p, b1, W2, b2, outp, Ef);
}

// round 17
// speedup vs baseline: 13.0193x; 1.5221x over previous
#include <cuda_runtime.h>
#include <cuda_fp16.h>
#include <cstdint>

#define N_NODES 100000
#define E_MAX   800000
#define EF_MAX  500000
#define SCAN_NB ((N_NODES + 255) / 256)   // 391

// Scratch (allocation-free rule: __device__ globals)
__device__ int      g_deg[N_NODES];
__device__ int      g_cur[N_NODES];
__device__ int      g_off[N_NODES];
__device__ int      g_bsum[SCAN_NB];
__device__ int      g_adj[E_MAX];
__device__ uint32_t g_xh[N_NODES * 32];      // x as half2
__device__ uint32_t g_h0h[N_NODES * 64];     // h0 as half2
__device__ uint32_t g_h1h[N_NODES * 64];     // h1 as half2
__device__ uint32_t g_aggh[N_NODES * 64];    // scaled mean agg as half2
__device__ uint32_t g_eattrh[EF_MAX * 16];   // edge_attr as half2
__device__ uint32_t g_B0[128 * 64];          // prepacked weight fragments
__device__ uint32_t g_B1[256 * 64];
__device__ uint32_t g_BC[288 * 64];

// ---------------------------------------------------------------------------
__device__ __forceinline__ void mma_f16(float4& d, const uint4 a, const uint2 b) {
    asm("mma.sync.aligned.m16n8k16.row.col.f32.f16.f16.f32 "
        "{%0,%1,%2,%3}, {%4,%5,%6,%7}, {%8,%9}, {%0,%1,%2,%3};"
        : "+f"(d.x), "+f"(d.y), "+f"(d.z), "+f"(d.w)
        : "r"(a.x), "r"(a.y), "r"(a.z), "r"(a.w), "r"(b.x), "r"(b.y));
}

__device__ __forceinline__ uint32_t packh2(float lo, float hi) {
    __half2 h = __floats2half2_rn(lo, hi);
    return *(uint32_t*)&h;
}

__device__ __forceinline__ uint4 ldsm_x4(uint32_t addr) {
    uint4 r;
    asm volatile("ldmatrix.sync.aligned.m8n8.x4.shared.b16 {%0,%1,%2,%3}, [%4];"
                 : "=r"(r.x), "=r"(r.y), "=r"(r.z), "=r"(r.w) : "r"(addr));
    return r;
}

#define CP_ASYNC16(dst, src) \
    asm volatile("cp.async.cg.shared.global [%0], [%1], 16;" :: "r"(dst), "l"(src) : "memory")
#define CP_COMMIT() asm volatile("cp.async.commit_group;" ::: "memory")
#define CP_WAIT2()  asm volatile("cp.async.wait_group 2;" ::: "memory")

// A panel SMEM layout: 128 rows x 4 chunks (16B), swizzle ch ^ ((r>>1)&3)
__device__ __forceinline__ uint32_t a_off(int row, int chunk) {
    return (uint32_t)((row * 4 + (chunk ^ ((row >> 1) & 3))) * 16);
}

// B fragment pack: slot s of a K x 128 weight [Wl;Wr] (FD rows each)
__device__ __forceinline__ uint32_t pack_w(int s, int FD,
                                           const float* __restrict__ Wl,
                                           const float* __restrict__ Wr) {
    int reg = s & 1, lane = (s >> 1) & 31, nb = (s >> 6) & 15, kb = s >> 10;
    int tig = lane & 3, gid = lane >> 2;
    int n = nb * 8 + gid;
    int k0 = kb * 16 + reg * 8 + tig * 2;
    float lo = (k0 < FD) ? Wl[k0 * 128 + n] : Wr[(k0 - FD) * 128 + n];
    float hi = (k0 + 1 < FD) ? Wl[(k0 + 1) * 128 + n] : Wr[(k0 + 1 - FD) * 128 + n];
    return packh2(lo, hi);
}

// ---------------------------------------------------------------------------
// prep: zero deg/cur, convert x/eattr to fp16, prepack weight fragments
__global__ void prep_kernel(const float* __restrict__ x,
                            const float* __restrict__ eattr,
                            const float* __restrict__ Wl0, const float* __restrict__ Wr0,
                            const float* __restrict__ Wl1, const float* __restrict__ Wr1,
                            const float* __restrict__ W1,
                            int* __restrict__ deg, int* __restrict__ cur,
                            uint32_t* __restrict__ xh, uint32_t* __restrict__ eattrh,
                            uint32_t* __restrict__ B0, uint32_t* __restrict__ B1,
                            uint32_t* __restrict__ BC, int Ef) {
    int i0 = blockIdx.x * blockDim.x + threadIdx.x;
    int stride = gridDim.x * blockDim.x;
    for (int j = i0; j < N_NODES; j += stride) { deg[j] = 0; cur[j] = 0; }
    for (int j = i0; j < N_NODES * 32; j += stride) {
        float2 v = ((const float2*)x)[j];
        xh[j] = packh2(v.x, v.y);
    }
    for (int j = i0; j < Ef * 16; j += stride) {
        float2 v = ((const float2*)eattr)[j];
        eattrh[j] = packh2(v.x, v.y);
    }
    for (int s = i0; s < 128 * 64; s += stride) B0[s] = pack_w(s, 64, Wl0, Wr0);
    for (int s = i0; s < 256 * 64; s += stride) B1[s] = pack_w(s, 128, Wl1, Wr1);
    for (int s = i0; s < 288 * 64; s += stride) BC[s] = pack_w(s, 288, W1, W1);
}

__global__ void count_deg_kernel(const int* __restrict__ dst, int E,
                                 int* __restrict__ deg) {
    int e = blockIdx.x * blockDim.x + threadIdx.x;
    if (e < E) atomicAdd(&deg[dst[e]], 1);
}

__global__ void scan1_kernel(const int* __restrict__ deg,
                             int* __restrict__ off, int* __restrict__ bsum) {
    __shared__ int sh[256];
    int tid = threadIdx.x;
    int i = blockIdx.x * 256 + tid;
    int v = (i < N_NODES) ? deg[i] : 0;
    sh[tid] = v;
    __syncthreads();
    for (int ofs = 1; ofs < 256; ofs <<= 1) {
        int t = (tid >= ofs) ? sh[tid - ofs] : 0;
        __syncthreads();
        sh[tid] += t;
        __syncthreads();
    }
    if (i < N_NODES) off[i] = sh[tid] - v;
    if (tid == 255) bsum[blockIdx.x] = sh[255];
}

__global__ void scan2_kernel(const int* __restrict__ bsum, int* __restrict__ off) {
    __shared__ int sh[256];
    int tid = threadIdx.x;
    int b = blockIdx.x;
    int acc = 0;
    for (int j = tid; j < b; j += 256) acc += bsum[j];
    sh[tid] = acc;
    __syncthreads();
    for (int ofs = 128; ofs; ofs >>= 1) {
        if (tid < ofs) sh[tid] += sh[tid + ofs];
        __syncthreads();
    }
    int base = sh[0];
    int i = b * 256 + tid;
    if (i < N_NODES) off[i] += base;
}

__global__ void fill_adj_kernel(const int* __restrict__ src,
                                const int* __restrict__ dst, int E,
                                const int* __restrict__ off,
                                int* __restrict__ cur, int* __restrict__ adj) {
    int e = blockIdx.x * blockDim.x + threadIdx.x;
    if (e >= E) return;
    int d = __ldg(&dst[e]);
    int pos = atomicAdd(&cur[d], 1);
    adj[off[d] + pos] = __ldg(&src[e]);
}

// gather-mean over fp32 x (64 cols): warp per node
__global__ void gather_mean_f32_kernel(const float* __restrict__ x,
                                       const int* __restrict__ off,
                                       const int* __restrict__ deg,
                                       const int* __restrict__ adj,
                                       uint32_t* __restrict__ aggh) {
    int warp = (blockIdx.x * blockDim.x + threadIdx.x) >> 5;
    int lane = threadIdx.x & 31;
    if (warp >= N_NODES) return;
    int o = __ldg(&off[warp]);
    int dg = __ldg(&deg[warp]);
    float ax = 0.f, ay = 0.f;
    int j = 0;
    for (; j + 1 < dg; j += 2) {
        int s0 = __ldg(&adj[o + j]);
        int s1 = __ldg(&adj[o + j + 1]);
        float2 v0 = *(const float2*)(x + (size_t)s0 * 64 + lane * 2);
        float2 v1 = *(const float2*)(x + (size_t)s1 * 64 + lane * 2);
        ax += v0.x; ay += v0.y;
        ax += v1.x; ay += v1.y;
    }
    if (j < dg) {
        int s0 = __ldg(&adj[o + j]);
        float2 v0 = *(const float2*)(x + (size_t)s0 * 64 + lane * 2);
        ax += v0.x; ay += v0.y;
    }
    float rc = 1.0f / fmaxf((float)dg, 1.0f);
    aggh[(size_t)warp * 32 + lane] = packh2(ax * rc, ay * rc);
}

// gather-mean over fp16 h0 (128 cols): warp per node
__global__ void gather_mean_h_kernel(const uint32_t* __restrict__ feath,
                                     const int* __restrict__ off,
                                     const int* __restrict__ deg,
                                     const int* __restrict__ adj,
                                     uint32_t* __restrict__ aggh) {
    int warp = (blockIdx.x * blockDim.x + threadIdx.x) >> 5;
    int lane = threadIdx.x & 31;
    if (warp >= N_NODES) return;
    int o = __ldg(&off[warp]);
    int dg = __ldg(&deg[warp]);
    float a0 = 0.f, a1 = 0.f, a2 = 0.f, a3 = 0.f;
    int j = 0;
    for (; j + 1 < dg; j += 2) {
        int s0 = __ldg(&adj[o + j]);
        int s1 = __ldg(&adj[o + j + 1]);
        uint32_t u0 = feath[(size_t)s0 * 64 + lane];
        uint32_t u1 = feath[(size_t)s0 * 64 + 32 + lane];
        uint32_t w0 = feath[(size_t)s1 * 64 + lane];
        uint32_t w1 = feath[(size_t)s1 * 64 + 32 + lane];
        float2 f;
        f = __half22float2(*(__half2*)&u0); a0 += f.x; a1 += f.y;
        f = __half22float2(*(__half2*)&u1); a2 += f.x; a3 += f.y;
        f = __half22float2(*(__half2*)&w0); a0 += f.x; a1 += f.y;
        f = __half22float2(*(__half2*)&w1); a2 += f.x; a3 += f.y;
    }
    if (j < dg) {
        int s0 = __ldg(&adj[o + j]);
        uint32_t u0 = feath[(size_t)s0 * 64 + lane];
        uint32_t u1 = feath[(size_t)s0 * 64 + 32 + lane];
        float2 f;
        f = __half22float2(*(__half2*)&u0); a0 += f.x; a1 += f.y;
        f = __half22float2(*(__half2*)&u1); a2 += f.x; a3 += f.y;
    }
    float rc = 1.0f / fmaxf((float)dg, 1.0f);
    aggh[(size_t)warp * 64 + lane]      = packh2(a0 * rc, a1 * rc);
    aggh[(size_t)warp * 64 + 32 + lane] = packh2(a2 * rc, a3 * rc);
}

// ---------------------------------------------------------------------------
// Fused SAGE layer via fp16 mma.sync + cp.async + ldmatrix.
// M-tile = 128 nodes, N = 128, 256 threads = 8 warps, 2 CTAs/SM.
// A panels: 4-deep cp.async ring, row-major + XOR swizzle; A frags via LDSM.
template <int K, bool RELU>
__launch_bounds__(256, 2)
__global__ void layer_mma_kernel(const uint32_t* __restrict__ aggh,
                                 const uint32_t* __restrict__ xh,
                                 const uint32_t* __restrict__ Bg,
                                 const float* __restrict__ bl,
                                 uint32_t* __restrict__ outh) {
    extern __shared__ uint32_t usm[];
    uint32_t* Bsm  = usm;                  // K*64 b32
    uint32_t* Abuf = Bsm + K * 64;         // 4 * 2048 b32 (4 x 8KB panels)
    float* bs = (float*)(Abuf + 8192);     // 128

    const int tid = threadIdx.x;
    const int FD = K / 2;
    const int FD2 = FD / 2;
    const uint32_t Abase_s = (uint32_t)__cvta_generic_to_shared(Abuf);

    for (int i = tid; i < K * 16; i += 256)
        ((uint4*)Bsm)[i] = ((const uint4*)Bg)[i];
    if (tid < 128) bs[tid] = bl[tid];
    __syncthreads();

    const int wid = tid >> 5, lane = tid & 31;
    const int wm = wid & 3, wn = wid >> 2;
    const int gid = lane >> 2, tig = lane & 3;
    const int m = lane >> 3;
    const int rowg = ((m & 1) << 3) | (lane & 7);
    const int chp = m >> 1;

    constexpr int P = K / 32;
    const int ntiles = (N_NODES + 127) >> 7;

    for (int tile = blockIdx.x; tile < ntiles; tile += gridDim.x) {
        const int n0 = tile << 7;

        auto issue_panel = [&](int p) {
            if (p < P) {
                int c0 = p * 32;
                const uint32_t* src;
                int cu;
                if (c0 < FD) { src = aggh; cu = c0 >> 1; }
                else         { src = xh;   cu = (c0 - FD) >> 1; }
                uint32_t dstb = Abase_s + (uint32_t)((p & 3) * 8192);
#pragma unroll
                for (int it = 0; it < 2; it++) {
                    int idx = tid + 256 * it;       // 0..511
                    int r = idx >> 2, ch = idx & 3;
                    int node = min(n0 + r, N_NODES - 1);
                    const uint32_t* g = src + (size_t)node * FD2 + cu + ch * 4;
                    CP_ASYNC16(dstb + a_off(r, ch), g);
                }
            }
            CP_COMMIT();
        };

        issue_panel(0);
        issue_panel(1);

        float4 d[2][8];
#pragma unroll
        for (int t = 0; t < 2; t++)
#pragma unroll
            for (int j = 0; j < 8; j++) d[t][j] = make_float4(0.f, 0.f, 0.f, 0.f);

        for (int p = 0; p < P; p++) {
            issue_panel(p + 2);
            CP_WAIT2();
            __syncthreads();
            uint32_t Ab = Abase_s + (uint32_t)((p & 3) * 8192);
#pragma unroll
            for (int kt = 0; kt < 2; kt++) {
                int chunk = kt * 2 + chp;
                uint4 av[2];
#pragma unroll
                for (int t = 0; t < 2; t++) {
                    int row = wm * 32 + t * 16 + rowg;
                    av[t] = ldsm_x4(Ab + a_off(row, chunk));
                }
                int kb = p * 2 + kt;
#pragma unroll
                for (int j = 0; j < 8; j++) {
                    uint2 bv = *(const uint2*)&Bsm[((kb * 16 + wn * 8 + j) * 32 + lane) * 2];
#pragma unroll
                    for (int t = 0; t < 2; t++) mma_f16(d[t][j], av[t], bv);
                }
            }
        }

        // epilogue: bias (+relu), write fp16
#pragma unroll
        for (int t = 0; t < 2; t++) {
            int nlo = n0 + wm * 32 + t * 16 + gid;
            int nhi = nlo + 8;
#pragma unroll
            for (int j = 0; j < 8; j++) {
                int col = wn * 64 + j * 8 + tig * 2;
                float ba = bs[col], bb = bs[col + 1];
                float2 lo = make_float2(d[t][j].x + ba, d[t][j].y + bb);
                float2 hi = make_float2(d[t][j].z + ba, d[t][j].w + bb);
                if (RELU) {
                    lo.x = fmaxf(lo.x, 0.f); lo.y = fmaxf(lo.y, 0.f);
                    hi.x = fmaxf(hi.x, 0.f); hi.y = fmaxf(hi.y, 0.f);
                }
                if (nlo < N_NODES) outh[(size_t)nlo * 64 + (col >> 1)] = packh2(lo.x, lo.y);
                if (nhi < N_NODES) outh[(size_t)nhi * 64 + (col >> 1)] = packh2(hi.x, hi.y);
            }
        }
        __syncthreads();
    }
}

// ---------------------------------------------------------------------------
// Classifier via fp16 mma.sync + cp.async + ldmatrix.
// M-tile = 128 edges, N = 128, K = 288, 256 threads, 2 CTAs/SM.
__launch_bounds__(256, 2)
__global__ void classify_mma_kernel(const uint32_t* __restrict__ h1h,
                                    const int* __restrict__ fsrc,
                                    const int* __restrict__ fdst,
                                    const uint32_t* __restrict__ eattrh,
                                    const uint32_t* __restrict__ Bg,
                                    const float* __restrict__ b1,
                                    const float* __restrict__ W2,
                                    const float* __restrict__ b2,
                                    float* __restrict__ outp, int Ef) {
    extern __shared__ uint32_t usm[];
    uint32_t* Bsm  = usm;                  // 288*64 = 18432 b32
    uint32_t* Abuf = Bsm + 18432;          // 4 * 2048 b32
    float* b1s  = (float*)(Abuf + 8192);   // 128
    float* w2s  = b1s + 128;               // 128
    float* red  = w2s + 128;               // 128
    int*   sidx = (int*)(red + 128);       // 128
    int*   didx = sidx + 128;              // 128

    const int tid = threadIdx.x;
    const uint32_t Abase_s = (uint32_t)__cvta_generic_to_shared(Abuf);

    for (int i = tid; i < 4608; i += 256)
        ((uint4*)Bsm)[i] = ((const uint4*)Bg)[i];
    if (tid < 128) { b1s[tid] = b1[tid]; w2s[tid] = W2[tid]; }
    __syncthreads();
    const float b2v = __ldg(&b2[0]);

    const int wid = tid >> 5, lane = tid & 31;
    const int wm = wid & 3, wn = wid >> 2;
    const int gid = lane >> 2, tig = lane & 3;
    const int m = lane >> 3;
    const int rowg = ((m & 1) << 3) | (lane & 7);
    const int chp = m >> 1;

    const int ntiles = (Ef + 127) >> 7;
    for (int tile = blockIdx.x; tile < ntiles; tile += gridDim.x) {
        const int e0 = tile << 7;
        if (tid < 128) {
            int e = min(e0 + tid, Ef - 1);
            sidx[tid] = __ldg(&fsrc[e]);
            didx[tid] = __ldg(&fdst[e]);
            red[tid] = 0.0f;
        }
        __syncthreads();

        auto issue_panel = [&](int p) {
            if (p < 9) {
                uint32_t dstb = Abase_s + (uint32_t)((p & 3) * 8192);
#pragma unroll
                for (int it = 0; it < 2; it++) {
                    int idx = tid + 256 * it;
                    int r = idx >> 2, ch = idx & 3;
                    const uint32_t* g;
                    if (p < 4)
                        g = h1h + (size_t)sidx[r] * 64 + p * 16 + ch * 4;
                    else if (p < 8)
                        g = h1h + (size_t)didx[r] * 64 + (p - 4) * 16 + ch * 4;
                    else {
                        int e = min(e0 + r, Ef - 1);
                        g = eattrh + (size_t)e * 16 + ch * 4;
                    }
                    CP_ASYNC16(dstb + a_off(r, ch), g);
                }
            }
            CP_COMMIT();
        };

        issue_panel(0);
        issue_panel(1);

        float4 d[2][8];
#pragma unroll
        for (int t = 0; t < 2; t++)
#pragma unroll
            for (int j = 0; j < 8; j++) d[t][j] = make_float4(0.f, 0.f, 0.f, 0.f);

        for (int p = 0; p < 9; p++) {
            issue_panel(p + 2);
            CP_WAIT2();
            __syncthreads();
            uint32_t Ab = Abase_s + (uint32_t)((p & 3) * 8192);
#pragma unroll
            for (int kt = 0; kt < 2; kt++) {
                int chunk = kt * 2 + chp;
                uint4 av[2];
#pragma unroll
                for (int t = 0; t < 2; t++) {
                    int row = wm * 32 + t * 16 + rowg;
                    av[t] = ldsm_x4(Ab + a_off(row, chunk));
                }
                int kb = p * 2 + kt;
#pragma unroll
                for (int j = 0; j < 8; j++) {
                    uint2 bv = *(const uint2*)&Bsm[((kb * 16 + wn * 8 + j) * 32 + lane) * 2];
#pragma unroll
                    for (int t = 0; t < 2; t++) mma_f16(d[t][j], av[t], bv);
                }
            }
        }

        // epilogue: relu + dot with W2, reduce over 128 hidden dims
        float s_[2][2];
#pragma unroll
        for (int t = 0; t < 2; t++) { s_[t][0] = 0.f; s_[t][1] = 0.f; }
#pragma unroll
        for (int t = 0; t < 2; t++) {
#pragma unroll
            for (int j = 0; j < 8; j++) {
                int col = wn * 64 + j * 8 + tig * 2;
                float ba = b1s[col], bb = b1s[col + 1];
                float wa = w2s[col], wb = w2s[col + 1];
                s_[t][0] += fmaxf(d[t][j].x + ba, 0.f) * wa + fmaxf(d[t][j].y + bb, 0.f) * wb;
                s_[t][1] += fmaxf(d[t][j].z + ba, 0.f) * wa + fmaxf(d[t][j].w + bb, 0.f) * wb;
            }
        }
#pragma unroll
        for (int t = 0; t < 2; t++) {
            s_[t][0] += __shfl_xor_sync(0xffffffffu, s_[t][0], 1);
            s_[t][0] += __shfl_xor_sync(0xffffffffu, s_[t][0], 2);
            s_[t][1] += __shfl_xor_sync(0xffffffffu, s_[t][1], 1);
            s_[t][1] += __shfl_xor_sync(0xffffffffu, s_[t][1], 2);
        }
        if (tig == 0) {
#pragma unroll
            for (int t = 0; t < 2; t++) {
                atomicAdd(&red[wm * 32 + t * 16 + gid], s_[t][0]);
                atomicAdd(&red[wm * 32 + t * 16 + gid + 8], s_[t][1]);
            }
        }
        __syncthreads();
        if (tid < 128) {
            int e = e0 + tid;
            if (e < Ef) outp[e] = red[tid] + b2v;
        }
        __syncthreads();
    }
}

// ---------------------------------------------------------------------------
extern "C" void kernel_launch(void* const* d_in, const int* in_sizes, int n_in,
                              void* d_out, int out_size) {
    const float* x     = (const float*)d_in[0];
    const int*   ei    = (const int*)d_in[1];
    const int*   fei   = (const int*)d_in[2];
    const float* eattr = (const float*)d_in[3];
    const float* Wl0   = (const float*)d_in[4];
    const float* bl0   = (const float*)d_in[5];
    const float* Wr0   = (const float*)d_in[6];
    const float* Wl1   = (const float*)d_in[7];
    const float* bl1   = (const float*)d_in[8];
    const float* Wr1   = (const float*)d_in[9];
    const float* W1    = (const float*)d_in[10];
    const float* b1    = (const float*)d_in[11];
    const float* W2    = (const float*)d_in[12];
    const float* b2    = (const float*)d_in[13];
    float* outp = (float*)d_out;

    int E  = in_sizes[1] / 2;
    int Ef = in_sizes[2] / 2;
    const int* src  = ei;
    const int* dst  = ei + E;
    const int* fsrc = fei;
    const int* fdst = fei + Ef;

    int *deg_p, *cur_p, *off_p, *bsum_p, *adj_p;
    uint32_t *xh_p, *h0h_p, *h1h_p, *aggh_p, *eattrh_p, *B0_p, *B1_p, *BC_p;
    cudaGetSymbolAddress((void**)&deg_p, g_deg);
    cudaGetSymbolAddress((void**)&cur_p, g_cur);
    cudaGetSymbolAddress((void**)&off_p, g_off);
    cudaGetSymbolAddress((void**)&bsum_p, g_bsum);
    cudaGetSymbolAddress((void**)&adj_p, g_adj);
    cudaGetSymbolAddress((void**)&xh_p, g_xh);
    cudaGetSymbolAddress((void**)&h0h_p, g_h0h);
    cudaGetSymbolAddress((void**)&h1h_p, g_h1h);
    cudaGetSymbolAddress((void**)&aggh_p, g_aggh);
    cudaGetSymbolAddress((void**)&eattrh_p, g_eattrh);
    cudaGetSymbolAddress((void**)&B0_p, g_B0);
    cudaGetSymbolAddress((void**)&B1_p, g_B1);
    cudaGetSymbolAddress((void**)&BC_p, g_BC);

    const int smemL0 = (128 * 64 + 8192 + 128) * 4;
    const int smemL1 = (256 * 64 + 8192 + 128) * 4;
    const int smemC  = (18432 + 8192 + 384) * 4 + 256 * 4;
    cudaFuncSetAttribute(layer_mma_kernel<128, true>,
                         cudaFuncAttributeMaxDynamicSharedMemorySize, smemL0);
    cudaFuncSetAttribute(layer_mma_kernel<256, false>,
                         cudaFuncAttributeMaxDynamicSharedMemorySize, smemL1);
    cudaFuncSetAttribute(classify_mma_kernel,
                         cudaFuncAttributeMaxDynamicSharedMemorySize, smemC);

    // 1: prep (zero deg/cur, fp16 conversions, weight prepack)
    prep_kernel<<<2048, 256>>>(x, eattr, Wl0, Wr0, Wl1, Wr1, W1,
                               deg_p, cur_p, xh_p, eattrh_p,
                               B0_p, B1_p, BC_p, Ef);
    // 2-5: CSR build
    count_deg_kernel<<<(E + 255) / 256, 256>>>(dst, E, deg_p);
    scan1_kernel<<<SCAN_NB, 256>>>(deg_p, off_p, bsum_p);
    scan2_kernel<<<SCAN_NB, 256>>>(bsum_p, off_p);
    fill_adj_kernel<<<(E + 255) / 256, 256>>>(src, dst, E, off_p, cur_p, adj_p);
    // 6: layer-0 mean aggregation
    gather_mean_f32_kernel<<<(N_NODES * 32 + 255) / 256, 256>>>(x, off_p, deg_p,
                                                                adj_p, aggh_p);
    // 7: layer 0 mma
    layer_mma_kernel<128, true><<<296, 256, smemL0>>>(aggh_p, xh_p, B0_p, bl0, h0h_p);
    // 8: layer-1 mean aggregation
    gather_mean_h_kernel<<<(N_NODES * 32 + 255) / 256, 256>>>(h0h_p, off_p, deg_p,
                                                              adj_p, aggh_p);
    // 9: layer 1 mma
    layer_mma_kernel<256, false><<<296, 256, smemL1>>>(aggh_p, h0h_p, B1_p, bl1, h1h_p);
    // 10: edge classifier
    classify_mma_kernel<<<296, 256, smemC>>>(h1h_p, fsrc, fdst, eattrh_p,
                                             BC_p, b1, W2, b2, outp, Ef);
}